// round 9
// baseline (speedup 1.0000x reference)
#include <cuda_runtime.h>
#include <cuda_bf16.h>
#include <math.h>
#include <stdint.h>

#define BATCH 2
#define SEQ   2048
#define DIM   2048
#define NH    16
#define HDIM  128
#define NE    4
#define IDIM  2048
#define NTOK  (BATCH*SEQ)   // 4096

// ---------------- scratch (static device globals) ----
__device__ float g_ln   [(size_t)NTOK*DIM];
__device__ float g_q    [(size_t)NTOK*DIM];   // also reused as MoE hmid (compacted)
__device__ float g_k    [(size_t)NTOK*DIM];
__device__ float g_v    [(size_t)NTOK*DIM];
__device__ float g_attn [(size_t)NTOK*DIM];
__device__ float g_comb [(size_t)NTOK*NE];
__device__ int   g_cnt  [NE];
__device__ int   g_idx  [NE*NTOK];

__device__ __forceinline__ uint32_t f2tf32(float x) {
    uint32_t u;
    asm("cvt.rna.tf32.f32 %0, %1;" : "=r"(u) : "f"(x));
    return u;
}
__device__ __forceinline__ float tf32r(float x) { return __uint_as_float(f2tf32(x)); }

__device__ __forceinline__ void mma_tf32(float d[4], uint32_t a0, uint32_t a1,
                                         uint32_t a2, uint32_t a3,
                                         uint32_t b0, uint32_t b1) {
    asm volatile(
        "mma.sync.aligned.m16n8k8.row.col.f32.tf32.tf32.f32 "
        "{%0,%1,%2,%3}, {%4,%5,%6,%7}, {%8,%9}, {%0,%1,%2,%3};"
        : "+f"(d[0]), "+f"(d[1]), "+f"(d[2]), "+f"(d[3])
        : "r"(a0), "r"(a1), "r"(a2), "r"(a3), "r"(b0), "r"(b1));
}

__device__ __forceinline__ void mma_bf16(float d[4], uint32_t a0, uint32_t a1,
                                         uint32_t a2, uint32_t a3,
                                         uint32_t b0, uint32_t b1) {
    asm volatile(
        "mma.sync.aligned.m16n8k16.row.col.f32.bf16.bf16.f32 "
        "{%0,%1,%2,%3}, {%4,%5,%6,%7}, {%8,%9}, {%0,%1,%2,%3};"
        : "+f"(d[0]), "+f"(d[1]), "+f"(d[2]), "+f"(d[3])
        : "r"(a0), "r"(a1), "r"(a2), "r"(a3), "r"(b0), "r"(b1));
}

__device__ __forceinline__ uint32_t pack_bf2(float lo, float hi) {
    __nv_bfloat162 t = __floats2bfloat162_rn(lo, hi);   // .x = lo (low half)
    return *(uint32_t*)&t;
}
__device__ __forceinline__ uint16_t bf16bits(float x) {
    __nv_bfloat16 t = __float2bfloat16_rn(x);
    return *(uint16_t*)&t;
}

// ---------------- LayerNorm ----------------
__global__ void ln_kernel(const float* __restrict__ x, const float* __restrict__ w,
                          const float* __restrict__ b, float* __restrict__ y) {
    int row = blockIdx.x;
    const float* xr = x + (size_t)row * DIM;
    float* yr = y + (size_t)row * DIM;
    __shared__ float red[256];
    int tid = threadIdx.x;
    float s = 0.f;
    for (int i = tid; i < DIM; i += 256) s += xr[i];
    red[tid] = s; __syncthreads();
    for (int o = 128; o > 0; o >>= 1) { if (tid < o) red[tid] += red[tid + o]; __syncthreads(); }
    float mu = red[0] * (1.f / DIM);
    __syncthreads();
    float v = 0.f;
    for (int i = tid; i < DIM; i += 256) { float d = xr[i] - mu; v += d * d; }
    red[tid] = v; __syncthreads();
    for (int o = 128; o > 0; o >>= 1) { if (tid < o) red[tid] += red[tid + o]; __syncthreads(); }
    float inv = rsqrtf(red[0] * (1.f / DIM) + 1e-5f);
    for (int i = tid; i < DIM; i += 256) yr[i] = (xr[i] - mu) * inv * w[i] + b[i];
}

// ---------------- TF32 GEMM, double-buffered smem, gather/scatter rows -----------------
__device__ __forceinline__ void epi(float v, int gm, int gn,
                                    const float* bias, int act,
                                    const float* resid, int ldr,
                                    const float* rowscale, int rss,
                                    float* C, int ldc, int accum) {
    if (bias) v += bias[gn];
    if (act) v = 0.5f * v * (1.f + erff(v * 0.70710678118654752f));
    if (resid) v += resid[(size_t)gm * ldr + gn];
    if (rowscale) v *= rowscale[(size_t)gm * rss];
    size_t o = (size_t)gm * ldc + gn;
    if (accum) C[o] += v; else C[o] = v;
}

__global__ void __launch_bounds__(256)
gemm_tf32(const float* __restrict__ A, int lda,
          const float* __restrict__ B, int ldb,
          const float* __restrict__ bias,
          float* __restrict__ C, int ldc,
          const float* __restrict__ resid, int ldr,
          const float* __restrict__ rowscale, int rss,
          int M, int N, int K, int act, int accum,
          const int* __restrict__ amap, const int* __restrict__ cmap,
          const int* __restrict__ mcount) {
    int M_eff = mcount ? *mcount : M;
    int row0 = blockIdx.y * 128, col0 = blockIdx.x * 128;
    if (row0 >= M_eff) return;

    __shared__ float As[2][128][20];
    __shared__ float Bs[2][16][136];
    int tid = threadIdx.x;
    int w = tid >> 5, lane = tid & 31;
    int wm = w >> 2, wn = w & 3;
    int m_w = wm * 64, n_w = wn * 32;
    int g = lane >> 2, q = lane & 3;

    float acc[4][4][4];
#pragma unroll
    for (int i = 0; i < 4; i++)
#pragma unroll
        for (int j = 0; j < 4; j++)
#pragma unroll
            for (int r = 0; r < 4; r++) acc[i][j][r] = 0.f;

    int a_row0 = tid >> 2,  a_c0 = (tid & 3) * 4;
    int a_row1 = (tid + 256) >> 2, a_c1 = ((tid + 256) & 3) * 4;
    int b_row0 = tid >> 5,  b_c0 = (tid & 31) * 4;
    int b_row1 = (tid + 256) >> 5, b_c1 = ((tid + 256) & 31) * 4;

    int gr0 = row0 + a_row0, gr1 = row0 + a_row1;
    int cl0 = gr0 < M_eff ? gr0 : M_eff - 1;
    int cl1 = gr1 < M_eff ? gr1 : M_eff - 1;
    int ar0 = amap ? amap[cl0] : cl0;
    int ar1 = amap ? amap[cl1] : cl1;

    const float* Ap0 = A + (size_t)ar0 * lda + a_c0;
    const float* Ap1 = A + (size_t)ar1 * lda + a_c1;
    const float* Bp0 = B + (size_t)b_row0 * ldb + col0 + b_c0;
    const float* Bp1 = B + (size_t)b_row1 * ldb + col0 + b_c1;

    float4 pa0 = *(const float4*)Ap0;
    float4 pa1 = *(const float4*)Ap1;
    float4 pb0 = *(const float4*)Bp0;
    float4 pb1 = *(const float4*)Bp1;

    // stage tile 0 into buffer 0
    As[0][a_row0][a_c0 + 0] = tf32r(pa0.x);
    As[0][a_row0][a_c0 + 1] = tf32r(pa0.y);
    As[0][a_row0][a_c0 + 2] = tf32r(pa0.z);
    As[0][a_row0][a_c0 + 3] = tf32r(pa0.w);
    As[0][a_row1][a_c1 + 0] = tf32r(pa1.x);
    As[0][a_row1][a_c1 + 1] = tf32r(pa1.y);
    As[0][a_row1][a_c1 + 2] = tf32r(pa1.z);
    As[0][a_row1][a_c1 + 3] = tf32r(pa1.w);
    Bs[0][b_row0][b_c0 + 0] = tf32r(pb0.x);
    Bs[0][b_row0][b_c0 + 1] = tf32r(pb0.y);
    Bs[0][b_row0][b_c0 + 2] = tf32r(pb0.z);
    Bs[0][b_row0][b_c0 + 3] = tf32r(pb0.w);
    Bs[0][b_row1][b_c1 + 0] = tf32r(pb1.x);
    Bs[0][b_row1][b_c1 + 1] = tf32r(pb1.y);
    Bs[0][b_row1][b_c1 + 2] = tf32r(pb1.z);
    Bs[0][b_row1][b_c1 + 3] = tf32r(pb1.w);
    __syncthreads();

    int nk = K / 16;
    for (int t = 0; t < nk; t++) {
        int bsel = t & 1;
        bool more = (t + 1 < nk);
        if (more) {
            int k0 = (t + 1) * 16;
            pa0 = *(const float4*)(Ap0 + k0);
            pa1 = *(const float4*)(Ap1 + k0);
            pb0 = *(const float4*)(Bp0 + (size_t)k0 * ldb);
            pb1 = *(const float4*)(Bp1 + (size_t)k0 * ldb);
        }

#pragma unroll
        for (int ks = 0; ks < 2; ks++) {
            int kb = ks * 8;
            uint32_t af[4][4], bf[4][2];
#pragma unroll
            for (int i = 0; i < 4; i++) {
                int r = m_w + i * 16 + g;
                af[i][0] = __float_as_uint(As[bsel][r][kb + q]);
                af[i][1] = __float_as_uint(As[bsel][r + 8][kb + q]);
                af[i][2] = __float_as_uint(As[bsel][r][kb + q + 4]);
                af[i][3] = __float_as_uint(As[bsel][r + 8][kb + q + 4]);
            }
#pragma unroll
            for (int j = 0; j < 4; j++) {
                int c = n_w + j * 8 + g;
                bf[j][0] = __float_as_uint(Bs[bsel][kb + q][c]);
                bf[j][1] = __float_as_uint(Bs[bsel][kb + q + 4][c]);
            }
#pragma unroll
            for (int i = 0; i < 4; i++)
#pragma unroll
                for (int j = 0; j < 4; j++)
                    mma_tf32(acc[i][j], af[i][0], af[i][1], af[i][2], af[i][3],
                             bf[j][0], bf[j][1]);
        }

        if (more) {
            int nsel = bsel ^ 1;
            As[nsel][a_row0][a_c0 + 0] = tf32r(pa0.x);
            As[nsel][a_row0][a_c0 + 1] = tf32r(pa0.y);
            As[nsel][a_row0][a_c0 + 2] = tf32r(pa0.z);
            As[nsel][a_row0][a_c0 + 3] = tf32r(pa0.w);
            As[nsel][a_row1][a_c1 + 0] = tf32r(pa1.x);
            As[nsel][a_row1][a_c1 + 1] = tf32r(pa1.y);
            As[nsel][a_row1][a_c1 + 2] = tf32r(pa1.z);
            As[nsel][a_row1][a_c1 + 3] = tf32r(pa1.w);
            Bs[nsel][b_row0][b_c0 + 0] = tf32r(pb0.x);
            Bs[nsel][b_row0][b_c0 + 1] = tf32r(pb0.y);
            Bs[nsel][b_row0][b_c0 + 2] = tf32r(pb0.z);
            Bs[nsel][b_row0][b_c0 + 3] = tf32r(pb0.w);
            Bs[nsel][b_row1][b_c1 + 0] = tf32r(pb1.x);
            Bs[nsel][b_row1][b_c1 + 1] = tf32r(pb1.y);
            Bs[nsel][b_row1][b_c1 + 2] = tf32r(pb1.z);
            Bs[nsel][b_row1][b_c1 + 3] = tf32r(pb1.w);
        }
        __syncthreads();
    }

#pragma unroll
    for (int i = 0; i < 4; i++) {
        int gm = row0 + m_w + i * 16 + g;
        if (gm >= M_eff) continue;
        int cr = cmap ? cmap[gm] : gm;
#pragma unroll
        for (int j = 0; j < 4; j++) {
            int cb = col0 + n_w + j * 8 + q * 2;
            epi(acc[i][j][0], cr, cb,     bias, act, resid, ldr, rowscale, rss, C, ldc, accum);
            epi(acc[i][j][1], cr, cb + 1, bias, act, resid, ldr, rowscale, rss, C, ldc, accum);
        }
        int gm2 = gm + 8;
        if (gm2 >= M_eff) continue;
        int cr2 = cmap ? cmap[gm2] : gm2;
#pragma unroll
        for (int j = 0; j < 4; j++) {
            int cb = col0 + n_w + j * 8 + q * 2;
            epi(acc[i][j][2], cr2, cb,     bias, act, resid, ldr, rowscale, rss, C, ldc, accum);
            epi(acc[i][j][3], cr2, cb + 1, bias, act, resid, ldr, rowscale, rss, C, ldc, accum);
        }
    }
}

// ---------------- RoPE ----------------------------------------------------------------
__global__ void rope_kernel(float* __restrict__ q, float* __restrict__ k) {
    int idx = blockIdx.x * blockDim.x + threadIdx.x;
    if (idx >= NTOK * NH * 64) return;
    int i = idx & 63;
    int rem = idx >> 6;
    int h = rem % NH;
    int t = rem / NH;
    int s = t % SEQ;
    float invf = (float)(1.0 / pow(10000.0, (double)i / 64.0));
    float ang = (float)s * invf;
    double angd = (double)ang;
    float c  = (float)cos(angd);
    float sn = (float)sin(angd);
    size_t base = (size_t)t * DIM + (size_t)h * HDIM;
    float q1 = q[base + i], q2 = q[base + 64 + i];
    q[base + i]      = q1 * c - q2 * sn;
    q[base + 64 + i] = q2 * c + q1 * sn;
    float k1 = k[base + i], k2 = k[base + 64 + i];
    k[base + i]      = k1 * c - k2 * sn;
    k[base + 64 + i] = k2 * c + k1 * sn;
}

// ---------------- Flash attention: running-max online softmax (R5 numerics), -----------
// Q-frags in registers, bit-exact rescale skip when the max is unchanged.
// 128 threads = 4 warps; warp w owns query rows [w*16, w*16+16). K-tiles of 32.
__global__ void __launch_bounds__(128)
fa_kernel(const float* __restrict__ q, const float* __restrict__ k,
          const float* __restrict__ v, float* __restrict__ attn) {
    __shared__ uint32_t Ks[32][68];    // [key][dim-pair]      8704 B
    __shared__ uint32_t Vt[128][20];   // [dim][key-pair]     10240 B
    __shared__ uint32_t Ps[4][16][20]; // per-warp [row][key-pair] 5120 B

    int bh = blockIdx.y;
    int b = bh / NH, h = bh % NH;
    int q0 = blockIdx.x * 64;
    int tid = threadIdx.x, w = tid >> 5, lane = tid & 31;
    int g = lane >> 2, qd = lane & 3;
    const float alpha = 0.08838834764831845f;   // 1/sqrt(128)

    const float* qb = q + ((size_t)b * SEQ) * DIM + h * HDIM;
    const float* kb_ = k + ((size_t)b * SEQ) * DIM + h * HDIM;
    const float* vb = v + ((size_t)b * SEQ) * DIM + h * HDIM;

    // Q fragments straight from gmem into registers (alpha pre-folded)
    uint32_t qf[8][4];
    {
        const float* qr0 = qb + (size_t)(q0 + w * 16 + g) * DIM;
        const float* qr1 = qr0 + 8 * DIM;
#pragma unroll
        for (int ks = 0; ks < 8; ks++) {
            int c0 = (ks * 8 + qd) * 2, c1 = (ks * 8 + qd + 4) * 2;
            float2 t00 = *(const float2*)(qr0 + c0);
            float2 t10 = *(const float2*)(qr1 + c0);
            float2 t01 = *(const float2*)(qr0 + c1);
            float2 t11 = *(const float2*)(qr1 + c1);
            qf[ks][0] = pack_bf2(t00.x * alpha, t00.y * alpha);
            qf[ks][1] = pack_bf2(t10.x * alpha, t10.y * alpha);
            qf[ks][2] = pack_bf2(t01.x * alpha, t01.y * alpha);
            qf[ks][3] = pack_bf2(t11.x * alpha, t11.y * alpha);
        }
    }

    float m0 = -1e30f, m1 = -1e30f, l0 = 0.f, l1 = 0.f;
    float out[16][4];
#pragma unroll
    for (int i = 0; i < 16; i++)
#pragma unroll
        for (int r = 0; r < 4; r++) out[i][r] = 0.f;

    int ktiles = q0 / 32 + 2;

    for (int kt = 0; kt < ktiles; kt++) {
        int k0 = kt * 32;
        __syncthreads();   // all warps done reading previous Ks/Vt
        for (int i = tid; i < 32 * 32; i += 128) {
            int r = i >> 5, c4 = i & 31;
            float4 tk = *(const float4*)(kb_ + (size_t)(k0 + r) * DIM + c4 * 4);
            Ks[r][c4 * 2]     = pack_bf2(tk.x, tk.y);
            Ks[r][c4 * 2 + 1] = pack_bf2(tk.z, tk.w);
            float4 tv = *(const float4*)(vb + (size_t)(k0 + r) * DIM + c4 * 4);
            uint16_t* vt = (uint16_t*)Vt;     // row stride = 40 uint16
            vt[(c4 * 4 + 0) * 40 + r] = bf16bits(tv.x);
            vt[(c4 * 4 + 1) * 40 + r] = bf16bits(tv.y);
            vt[(c4 * 4 + 2) * 40 + r] = bf16bits(tv.z);
            vt[(c4 * 4 + 3) * 40 + r] = bf16bits(tv.w);
        }
        __syncthreads();

        // scores: S(16x32) = Qw(16x128) @ K^T(128x32)
        float sc[4][4];
#pragma unroll
        for (int nt = 0; nt < 4; nt++)
#pragma unroll
            for (int r = 0; r < 4; r++) sc[nt][r] = 0.f;
#pragma unroll
        for (int ks = 0; ks < 8; ks++) {
            int kp = ks * 8;
#pragma unroll
            for (int nt = 0; nt < 4; nt++) {
                uint32_t b0 = Ks[nt * 8 + g][kp + qd];
                uint32_t b1 = Ks[nt * 8 + g][kp + qd + 4];
                mma_bf16(sc[nt], qf[ks][0], qf[ks][1], qf[ks][2], qf[ks][3], b0, b1);
            }
        }

        // causal mask on diagonal-crossing tiles
        if (k0 + 31 > q0) {
            int rq0 = q0 + w * 16 + g;
            int rq1 = rq0 + 8;
#pragma unroll
            for (int nt = 0; nt < 4; nt++) {
                int kc = k0 + nt * 8 + qd * 2;
                if (kc     > rq0) sc[nt][0] = -1e30f;
                if (kc + 1 > rq0) sc[nt][1] = -1e30f;
                if (kc     > rq1) sc[nt][2] = -1e30f;
                if (kc + 1 > rq1) sc[nt][3] = -1e30f;
            }
        }

        // running-max online softmax; rescale skipped (bit-exact) when max unchanged
        float tm0 = -1e30f, tm1 = -1e30f;
#pragma unroll
        for (int nt = 0; nt < 4; nt++) {
            tm0 = fmaxf(tm0, fmaxf(sc[nt][0], sc[nt][1]));
            tm1 = fmaxf(tm1, fmaxf(sc[nt][2], sc[nt][3]));
        }
        tm0 = fmaxf(tm0, __shfl_xor_sync(0xffffffffu, tm0, 1));
        tm0 = fmaxf(tm0, __shfl_xor_sync(0xffffffffu, tm0, 2));
        tm1 = fmaxf(tm1, __shfl_xor_sync(0xffffffffu, tm1, 1));
        tm1 = fmaxf(tm1, __shfl_xor_sync(0xffffffffu, tm1, 2));

        float mn0 = fmaxf(m0, tm0), mn1 = fmaxf(m1, tm1);
        bool chg = (mn0 != m0) || (mn1 != m1);
        if (__any_sync(0xffffffffu, chg)) {
            float corr0 = expf(m0 - mn0), corr1 = expf(m1 - mn1);  // == 1.0 if unchanged
            l0 *= corr0; l1 *= corr1;
#pragma unroll
            for (int nt = 0; nt < 16; nt++) {
                out[nt][0] *= corr0; out[nt][1] *= corr0;
                out[nt][2] *= corr1; out[nt][3] *= corr1;
            }
        }
        m0 = mn0; m1 = mn1;

        float s0 = 0.f, s1 = 0.f;
#pragma unroll
        for (int nt = 0; nt < 4; nt++) {
            float p0 = expf(sc[nt][0] - m0);
            float p1 = expf(sc[nt][1] - m0);
            float p2 = expf(sc[nt][2] - m1);
            float p3 = expf(sc[nt][3] - m1);
            s0 += p0 + p1; s1 += p2 + p3;
            Ps[w][g][nt * 4 + qd]     = pack_bf2(p0, p1);
            Ps[w][g + 8][nt * 4 + qd] = pack_bf2(p2, p3);
        }
        s0 += __shfl_xor_sync(0xffffffffu, s0, 1);
        s0 += __shfl_xor_sync(0xffffffffu, s0, 2);
        s1 += __shfl_xor_sync(0xffffffffu, s1, 1);
        s1 += __shfl_xor_sync(0xffffffffu, s1, 2);
        l0 += s0; l1 += s1;
        __syncwarp();

        // out(16x128) += P(16x32) @ V(32x128)
#pragma unroll
        for (int ks = 0; ks < 2; ks++) {
            int kp = ks * 8;
            uint32_t a0 = Ps[w][g][kp + qd];
            uint32_t a1 = Ps[w][g + 8][kp + qd];
            uint32_t a2 = Ps[w][g][kp + qd + 4];
            uint32_t a3 = Ps[w][g + 8][kp + qd + 4];
#pragma unroll
            for (int nt = 0; nt < 16; nt++) {
                uint32_t b0 = Vt[nt * 8 + g][kp + qd];
                uint32_t b1 = Vt[nt * 8 + g][kp + qd + 4];
                mma_bf16(out[nt], a0, a1, a2, a3, b0, b1);
            }
        }
        __syncwarp();
    }

    float inv0 = 1.f / l0, inv1 = 1.f / l1;
    int r0g = q0 + w * 16 + g;
    float* ob = attn + ((size_t)b * SEQ) * DIM + h * HDIM;
#pragma unroll
    for (int nt = 0; nt < 16; nt++) {
        int c = nt * 8 + qd * 2;
        *(float2*)(ob + (size_t)r0g * DIM + c) =
            make_float2(out[nt][0] * inv0, out[nt][1] * inv0);
        *(float2*)(ob + (size_t)(r0g + 8) * DIM + c) =
            make_float2(out[nt][2] * inv1, out[nt][3] * inv1);
    }
}

// ---------------- MoE gate -------------------------------------------------------------
__global__ void gate_kernel(const float* __restrict__ x, const float* __restrict__ wg,
                            float* __restrict__ comb) {
    int t = blockIdx.x;
    int tid = threadIdx.x;
    __shared__ float red[NE * 128];
    const float* xr = x + (size_t)t * DIM;
    float acc[NE] = {0.f, 0.f, 0.f, 0.f};
    for (int d = tid; d < DIM; d += 128) {
        float xv = xr[d];
#pragma unroll
        for (int e = 0; e < NE; e++) acc[e] += xv * wg[(size_t)d * NE + e];
    }
#pragma unroll
    for (int e = 0; e < NE; e++) red[e * 128 + tid] = acc[e];
    __syncthreads();
    for (int o = 64; o > 0; o >>= 1) {
        if (tid < o) {
#pragma unroll
            for (int e = 0; e < NE; e++) red[e * 128 + tid] += red[e * 128 + tid + o];
        }
        __syncthreads();
    }
    if (tid == 0) {
        float l[NE];
#pragma unroll
        for (int e = 0; e < NE; e++) l[e] = red[e * 128];
        float mx = fmaxf(fmaxf(l[0], l[1]), fmaxf(l[2], l[3]));
        float ex[NE], s = 0.f;
#pragma unroll
        for (int e = 0; e < NE; e++) { ex[e] = expf(l[e] - mx); s += ex[e]; }
        float p[NE];
#pragma unroll
        for (int e = 0; e < NE; e++) p[e] = ex[e] / s;
        int i0 = 0;
#pragma unroll
        for (int e = 1; e < NE; e++) if (p[e] > p[i0]) i0 = e;
        int i1 = (i0 == 0) ? 1 : 0;
#pragma unroll
        for (int e = 0; e < NE; e++) if (e != i0 && p[e] > p[i1]) i1 = e;
        float e1 = expf(p[i1] - p[i0]);
        float invs = 1.f / (1.f + e1);
        float c[NE] = {0.f, 0.f, 0.f, 0.f};
        c[i0] = invs;
        c[i1] = e1 * invs;
#pragma unroll
        for (int e = 0; e < NE; e++) comb[(size_t)t * NE + e] = c[e];
    }
}

// ---------------- Routing: build per-expert token lists --------------------------------
__global__ void zero_cnt_kernel(int* cnt) {
    if (threadIdx.x < NE) cnt[threadIdx.x] = 0;
}
__global__ void route_kernel(const float* __restrict__ comb, int* __restrict__ cnt,
                             int* __restrict__ idx) {
    int t = blockIdx.x * blockDim.x + threadIdx.x;
    if (t >= NTOK) return;
#pragma unroll
    for (int e = 0; e < NE; e++) {
        if (comb[(size_t)t * NE + e] > 0.f) {
            int pos = atomicAdd(&cnt[e], 1);
            idx[e * NTOK + pos] = t;
        }
    }
}

// ---------------- host orchestration ---------------------------------------------------
extern "C" void kernel_launch(void* const* d_in, const int* in_sizes, int n_in,
                              void* d_out, int out_size) {
    (void)in_sizes; (void)n_in; (void)out_size;
    const float* hs   = (const float*)d_in[0];
    const float* wq   = (const float*)d_in[1];
    const float* bq   = (const float*)d_in[2];
    const float* wk   = (const float*)d_in[3];
    const float* bk   = (const float*)d_in[4];
    const float* wv   = (const float*)d_in[5];
    const float* bv   = (const float*)d_in[6];
    const float* wo   = (const float*)d_in[7];
    const float* bo   = (const float*)d_in[8];
    const float* ln1w = (const float*)d_in[9];
    const float* ln1b = (const float*)d_in[10];
    const float* ln2w = (const float*)d_in[11];
    const float* ln2b = (const float*)d_in[12];
    const float* wg   = (const float*)d_in[13];
    const float* we1  = (const float*)d_in[14];
    const float* be1  = (const float*)d_in[15];
    const float* we2  = (const float*)d_in[16];
    const float* be2  = (const float*)d_in[17];
    float* out = (float*)d_out;

    float *p_ln, *p_q, *p_k, *p_v, *p_attn, *p_comb;
    int *p_cnt, *p_idx;
    cudaGetSymbolAddress((void**)&p_ln, g_ln);
    cudaGetSymbolAddress((void**)&p_q, g_q);
    cudaGetSymbolAddress((void**)&p_k, g_k);
    cudaGetSymbolAddress((void**)&p_v, g_v);
    cudaGetSymbolAddress((void**)&p_attn, g_attn);
    cudaGetSymbolAddress((void**)&p_comb, g_comb);
    cudaGetSymbolAddress((void**)&p_cnt, g_cnt);
    cudaGetSymbolAddress((void**)&p_idx, g_idx);

    // 1. LN1
    ln_kernel<<<NTOK, 256>>>(hs, ln1w, ln1b, p_ln);

    // 2. QKV projections (dense)
    dim3 gBig(DIM / 128, NTOK / 128);
    gemm_tf32<<<gBig, 256>>>(p_ln, DIM, wq, DIM, bq, p_q, DIM,
                             nullptr, 0, nullptr, 0, NTOK, DIM, DIM, 0, 0,
                             nullptr, nullptr, nullptr);
    gemm_tf32<<<gBig, 256>>>(p_ln, DIM, wk, DIM, bk, p_k, DIM,
                             nullptr, 0, nullptr, 0, NTOK, DIM, DIM, 0, 0,
                             nullptr, nullptr, nullptr);
    gemm_tf32<<<gBig, 256>>>(p_ln, DIM, wv, DIM, bv, p_v, DIM,
                             nullptr, 0, nullptr, 0, NTOK, DIM, DIM, 0, 0,
                             nullptr, nullptr, nullptr);

    // 3. RoPE
    int nrope = NTOK * NH * 64;
    rope_kernel<<<(nrope + 255) / 256, 256>>>(p_q, p_k);

    // 4. Flash attention
    dim3 gFA(SEQ / 64, BATCH * NH);
    fa_kernel<<<gFA, 128>>>(p_q, p_k, p_v, p_attn);

    // 5. O-proj + bias + residual -> out (= h)
    gemm_tf32<<<gBig, 256>>>(p_attn, DIM, wo, DIM, bo, out, DIM,
                             hs, DIM, nullptr, 0, NTOK, DIM, DIM, 0, 0,
                             nullptr, nullptr, nullptr);

    // 6. LN2
    ln_kernel<<<NTOK, 256>>>(out, ln2w, ln2b, p_ln);

    // 7. Gate + routing
    gate_kernel<<<NTOK, 128>>>(p_ln, wg, p_comb);
    zero_cnt_kernel<<<1, 32>>>(p_cnt);
    route_kernel<<<NTOK / 256, 256>>>(p_comb, p_cnt, p_idx);

    // 8. Sparse experts
    for (int e = 0; e < NE; e++) {
        const float* w1 = we1 + (size_t)e * DIM * IDIM;
        const float* b1 = be1 + (size_t)e * IDIM;
        const float* w2 = we2 + (size_t)e * IDIM * DIM;
        const float* b2 = be2 + (size_t)e * DIM;
        const int* idx_e = p_idx + e * NTOK;
        const int* cnt_e = p_cnt + e;
        gemm_tf32<<<gBig, 256>>>(p_ln, DIM, w1, IDIM, b1, p_q, IDIM,
                                 nullptr, 0, nullptr, 0, NTOK, IDIM, DIM, 1, 0,
                                 idx_e, nullptr, cnt_e);
        gemm_tf32<<<gBig, 256>>>(p_q, IDIM, w2, DIM, b2, out, DIM,
                                 nullptr, 0, p_comb + e, NE, NTOK, DIM, IDIM, 0, 1,
                                 nullptr, idx_e, cnt_e);
    }
}

// round 10
// speedup vs baseline: 1.1013x; 1.1013x over previous
#include <cuda_runtime.h>
#include <cuda_bf16.h>
#include <math.h>
#include <stdint.h>

#define BATCH 2
#define SEQ   2048
#define DIM   2048
#define NH    16
#define HDIM  128
#define NE    4
#define IDIM  2048
#define NTOK  (BATCH*SEQ)   // 4096

// ---------------- scratch (static device globals) ----
__device__ float g_ln   [(size_t)NTOK*DIM];
__device__ float g_q    [(size_t)NTOK*DIM];   // also reused as MoE hmid (compacted)
__device__ float g_k    [(size_t)NTOK*DIM];
__device__ float g_v    [(size_t)NTOK*DIM];
__device__ float g_attn [(size_t)NTOK*DIM];
__device__ float g_comb [(size_t)NTOK*NE];
__device__ int   g_cnt  [NE];
__device__ int   g_idx  [NE*NTOK];

__device__ __forceinline__ uint32_t f2tf32(float x) {
    uint32_t u;
    asm("cvt.rna.tf32.f32 %0, %1;" : "=r"(u) : "f"(x));
    return u;
}
__device__ __forceinline__ float tf32r(float x) { return __uint_as_float(f2tf32(x)); }

__device__ __forceinline__ void mma_tf32(float d[4], uint32_t a0, uint32_t a1,
                                         uint32_t a2, uint32_t a3,
                                         uint32_t b0, uint32_t b1) {
    asm volatile(
        "mma.sync.aligned.m16n8k8.row.col.f32.tf32.tf32.f32 "
        "{%0,%1,%2,%3}, {%4,%5,%6,%7}, {%8,%9}, {%0,%1,%2,%3};"
        : "+f"(d[0]), "+f"(d[1]), "+f"(d[2]), "+f"(d[3])
        : "r"(a0), "r"(a1), "r"(a2), "r"(a3), "r"(b0), "r"(b1));
}

__device__ __forceinline__ void mma_bf16(float d[4], uint32_t a0, uint32_t a1,
                                         uint32_t a2, uint32_t a3,
                                         uint32_t b0, uint32_t b1) {
    asm volatile(
        "mma.sync.aligned.m16n8k16.row.col.f32.bf16.bf16.f32 "
        "{%0,%1,%2,%3}, {%4,%5,%6,%7}, {%8,%9}, {%0,%1,%2,%3};"
        : "+f"(d[0]), "+f"(d[1]), "+f"(d[2]), "+f"(d[3])
        : "r"(a0), "r"(a1), "r"(a2), "r"(a3), "r"(b0), "r"(b1));
}

__device__ __forceinline__ uint32_t pack_bf2(float lo, float hi) {
    __nv_bfloat162 t = __floats2bfloat162_rn(lo, hi);   // .x = lo (low half)
    return *(uint32_t*)&t;
}
__device__ __forceinline__ uint16_t bf16bits(float x) {
    __nv_bfloat16 t = __float2bfloat16_rn(x);
    return *(uint16_t*)&t;
}

// ---------------- LayerNorm ----------------
__global__ void ln_kernel(const float* __restrict__ x, const float* __restrict__ w,
                          const float* __restrict__ b, float* __restrict__ y) {
    int row = blockIdx.x;
    const float* xr = x + (size_t)row * DIM;
    float* yr = y + (size_t)row * DIM;
    __shared__ float red[256];
    int tid = threadIdx.x;
    float s = 0.f;
    for (int i = tid; i < DIM; i += 256) s += xr[i];
    red[tid] = s; __syncthreads();
    for (int o = 128; o > 0; o >>= 1) { if (tid < o) red[tid] += red[tid + o]; __syncthreads(); }
    float mu = red[0] * (1.f / DIM);
    __syncthreads();
    float v = 0.f;
    for (int i = tid; i < DIM; i += 256) { float d = xr[i] - mu; v += d * d; }
    red[tid] = v; __syncthreads();
    for (int o = 128; o > 0; o >>= 1) { if (tid < o) red[tid] += red[tid + o]; __syncthreads(); }
    float inv = rsqrtf(red[0] * (1.f / DIM) + 1e-5f);
    for (int i = tid; i < DIM; i += 256) yr[i] = (xr[i] - mu) * inv * w[i] + b[i];
}

// ---------------- TF32 GEMM: 128 threads, 4 warps, 64x64 warp tiles --------------------
// Block tile 128x128, K-tile 16. Square warp tiles halve LDS bytes per MMA.
__device__ __forceinline__ void epi(float v, int gm, int gn,
                                    const float* bias, int act,
                                    const float* resid, int ldr,
                                    const float* rowscale, int rss,
                                    float* C, int ldc, int accum) {
    if (bias) v += bias[gn];
    if (act) v = 0.5f * v * (1.f + erff(v * 0.70710678118654752f));
    if (resid) v += resid[(size_t)gm * ldr + gn];
    if (rowscale) v *= rowscale[(size_t)gm * rss];
    size_t o = (size_t)gm * ldc + gn;
    if (accum) C[o] += v; else C[o] = v;
}

__global__ void __launch_bounds__(128)
gemm_tf32(const float* __restrict__ A, int lda,
          const float* __restrict__ B, int ldb,
          const float* __restrict__ bias,
          float* __restrict__ C, int ldc,
          const float* __restrict__ resid, int ldr,
          const float* __restrict__ rowscale, int rss,
          int M, int N, int K, int act, int accum,
          const int* __restrict__ amap, const int* __restrict__ cmap,
          const int* __restrict__ mcount) {
    int M_eff = mcount ? *mcount : M;
    int row0 = blockIdx.y * 128, col0 = blockIdx.x * 128;
    if (row0 >= M_eff) return;

    __shared__ float As[128][20];
    __shared__ float Bs[16][136];
    int tid = threadIdx.x;
    int w = tid >> 5, lane = tid & 31;
    int wm = w >> 1, wn = w & 1;           // 2x2 warp grid
    int m_w = wm * 64, n_w = wn * 64;
    int g = lane >> 2, q = lane & 3;

    float acc[4][8][4];
#pragma unroll
    for (int i = 0; i < 4; i++)
#pragma unroll
        for (int j = 0; j < 8; j++)
#pragma unroll
            for (int r = 0; r < 4; r++) acc[i][j][r] = 0.f;

    // staging maps: 4 float4 chunks each for A (128x16) and B (16x128)
    int a_row[4], a_c[4], b_row[4], b_c[4];
    const float *Ap[4], *Bp[4];
#pragma unroll
    for (int i = 0; i < 4; i++) {
        int idx = tid + i * 128;
        a_row[i] = idx >> 2;  a_c[i] = (idx & 3) * 4;
        b_row[i] = idx >> 5;  b_c[i] = (idx & 31) * 4;
        int gr = row0 + a_row[i];
        int cl = gr < M_eff ? gr : M_eff - 1;
        int ar = amap ? amap[cl] : cl;
        Ap[i] = A + (size_t)ar * lda + a_c[i];
        Bp[i] = B + (size_t)b_row[i] * ldb + col0 + b_c[i];
    }

    float4 pa[4], pb[4];
#pragma unroll
    for (int i = 0; i < 4; i++) { pa[i] = *(const float4*)Ap[i]; pb[i] = *(const float4*)Bp[i]; }

    int nk = K / 16;
    for (int t = 0; t < nk; t++) {
#pragma unroll
        for (int i = 0; i < 4; i++) {
            As[a_row[i]][a_c[i] + 0] = tf32r(pa[i].x);
            As[a_row[i]][a_c[i] + 1] = tf32r(pa[i].y);
            As[a_row[i]][a_c[i] + 2] = tf32r(pa[i].z);
            As[a_row[i]][a_c[i] + 3] = tf32r(pa[i].w);
            Bs[b_row[i]][b_c[i] + 0] = tf32r(pb[i].x);
            Bs[b_row[i]][b_c[i] + 1] = tf32r(pb[i].y);
            Bs[b_row[i]][b_c[i] + 2] = tf32r(pb[i].z);
            Bs[b_row[i]][b_c[i] + 3] = tf32r(pb[i].w);
        }
        __syncthreads();

        if (t + 1 < nk) {
            int k0 = (t + 1) * 16;
#pragma unroll
            for (int i = 0; i < 4; i++) {
                pa[i] = *(const float4*)(Ap[i] + k0);
                pb[i] = *(const float4*)(Bp[i] + (size_t)k0 * ldb);
            }
        }

#pragma unroll
        for (int ks = 0; ks < 2; ks++) {
            int kb = ks * 8;
            uint32_t af[4][4], bf[8][2];
#pragma unroll
            for (int i = 0; i < 4; i++) {
                int r = m_w + i * 16 + g;
                af[i][0] = __float_as_uint(As[r][kb + q]);
                af[i][1] = __float_as_uint(As[r + 8][kb + q]);
                af[i][2] = __float_as_uint(As[r][kb + q + 4]);
                af[i][3] = __float_as_uint(As[r + 8][kb + q + 4]);
            }
#pragma unroll
            for (int j = 0; j < 8; j++) {
                int c = n_w + j * 8 + g;
                bf[j][0] = __float_as_uint(Bs[kb + q][c]);
                bf[j][1] = __float_as_uint(Bs[kb + q + 4][c]);
            }
#pragma unroll
            for (int i = 0; i < 4; i++)
#pragma unroll
                for (int j = 0; j < 8; j++)
                    mma_tf32(acc[i][j], af[i][0], af[i][1], af[i][2], af[i][3],
                             bf[j][0], bf[j][1]);
        }
        __syncthreads();
    }

#pragma unroll
    for (int i = 0; i < 4; i++) {
        int gm = row0 + m_w + i * 16 + g;
        if (gm < M_eff) {
            int cr = cmap ? cmap[gm] : gm;
#pragma unroll
            for (int j = 0; j < 8; j++) {
                int cb = col0 + n_w + j * 8 + q * 2;
                epi(acc[i][j][0], cr, cb,     bias, act, resid, ldr, rowscale, rss, C, ldc, accum);
                epi(acc[i][j][1], cr, cb + 1, bias, act, resid, ldr, rowscale, rss, C, ldc, accum);
            }
        }
        int gm2 = gm + 8;
        if (gm2 < M_eff) {
            int cr2 = cmap ? cmap[gm2] : gm2;
#pragma unroll
            for (int j = 0; j < 8; j++) {
                int cb = col0 + n_w + j * 8 + q * 2;
                epi(acc[i][j][2], cr2, cb,     bias, act, resid, ldr, rowscale, rss, C, ldc, accum);
                epi(acc[i][j][3], cr2, cb + 1, bias, act, resid, ldr, rowscale, rss, C, ldc, accum);
            }
        }
    }
}

// ---------------- RoPE ----------------------------------------------------------------
__global__ void rope_kernel(float* __restrict__ q, float* __restrict__ k) {
    int idx = blockIdx.x * blockDim.x + threadIdx.x;
    if (idx >= NTOK * NH * 64) return;
    int i = idx & 63;
    int rem = idx >> 6;
    int h = rem % NH;
    int t = rem / NH;
    int s = t % SEQ;
    float invf = (float)(1.0 / pow(10000.0, (double)i / 64.0));
    float ang = (float)s * invf;
    double angd = (double)ang;
    float c  = (float)cos(angd);
    float sn = (float)sin(angd);
    size_t base = (size_t)t * DIM + (size_t)h * HDIM;
    float q1 = q[base + i], q2 = q[base + 64 + i];
    q[base + i]      = q1 * c - q2 * sn;
    q[base + 64 + i] = q2 * c + q1 * sn;
    float k1 = k[base + i], k2 = k[base + 64 + i];
    k[base + i]      = k1 * c - k2 * sn;
    k[base + 64 + i] = k2 * c + k1 * sn;
}

// ---------------- Flash attention (R8, proven): running-max softmax, Q-regs, -----------
// bit-exact rescale skip. 128 threads = 4 warps.
__global__ void __launch_bounds__(128)
fa_kernel(const float* __restrict__ q, const float* __restrict__ k,
          const float* __restrict__ v, float* __restrict__ attn) {
    __shared__ uint32_t Ks[32][68];
    __shared__ uint32_t Vt[128][20];
    __shared__ uint32_t Ps[4][16][20];

    int bh = blockIdx.y;
    int b = bh / NH, h = bh % NH;
    int q0 = blockIdx.x * 64;
    int tid = threadIdx.x, w = tid >> 5, lane = tid & 31;
    int g = lane >> 2, qd = lane & 3;
    const float alpha = 0.08838834764831845f;

    const float* qb = q + ((size_t)b * SEQ) * DIM + h * HDIM;
    const float* kb_ = k + ((size_t)b * SEQ) * DIM + h * HDIM;
    const float* vb = v + ((size_t)b * SEQ) * DIM + h * HDIM;

    uint32_t qf[8][4];
    {
        const float* qr0 = qb + (size_t)(q0 + w * 16 + g) * DIM;
        const float* qr1 = qr0 + 8 * DIM;
#pragma unroll
        for (int ks = 0; ks < 8; ks++) {
            int c0 = (ks * 8 + qd) * 2, c1 = (ks * 8 + qd + 4) * 2;
            float2 t00 = *(const float2*)(qr0 + c0);
            float2 t10 = *(const float2*)(qr1 + c0);
            float2 t01 = *(const float2*)(qr0 + c1);
            float2 t11 = *(const float2*)(qr1 + c1);
            qf[ks][0] = pack_bf2(t00.x * alpha, t00.y * alpha);
            qf[ks][1] = pack_bf2(t10.x * alpha, t10.y * alpha);
            qf[ks][2] = pack_bf2(t01.x * alpha, t01.y * alpha);
            qf[ks][3] = pack_bf2(t11.x * alpha, t11.y * alpha);
        }
    }

    float m0 = -1e30f, m1 = -1e30f, l0 = 0.f, l1 = 0.f;
    float out[16][4];
#pragma unroll
    for (int i = 0; i < 16; i++)
#pragma unroll
        for (int r = 0; r < 4; r++) out[i][r] = 0.f;

    int ktiles = q0 / 32 + 2;

    for (int kt = 0; kt < ktiles; kt++) {
        int k0 = kt * 32;
        __syncthreads();
        for (int i = tid; i < 32 * 32; i += 128) {
            int r = i >> 5, c4 = i & 31;
            float4 tk = *(const float4*)(kb_ + (size_t)(k0 + r) * DIM + c4 * 4);
            Ks[r][c4 * 2]     = pack_bf2(tk.x, tk.y);
            Ks[r][c4 * 2 + 1] = pack_bf2(tk.z, tk.w);
            float4 tv = *(const float4*)(vb + (size_t)(k0 + r) * DIM + c4 * 4);
            uint16_t* vt = (uint16_t*)Vt;
            vt[(c4 * 4 + 0) * 40 + r] = bf16bits(tv.x);
            vt[(c4 * 4 + 1) * 40 + r] = bf16bits(tv.y);
            vt[(c4 * 4 + 2) * 40 + r] = bf16bits(tv.z);
            vt[(c4 * 4 + 3) * 40 + r] = bf16bits(tv.w);
        }
        __syncthreads();

        float sc[4][4];
#pragma unroll
        for (int nt = 0; nt < 4; nt++)
#pragma unroll
            for (int r = 0; r < 4; r++) sc[nt][r] = 0.f;
#pragma unroll
        for (int ks = 0; ks < 8; ks++) {
            int kp = ks * 8;
#pragma unroll
            for (int nt = 0; nt < 4; nt++) {
                uint32_t b0 = Ks[nt * 8 + g][kp + qd];
                uint32_t b1 = Ks[nt * 8 + g][kp + qd + 4];
                mma_bf16(sc[nt], qf[ks][0], qf[ks][1], qf[ks][2], qf[ks][3], b0, b1);
            }
        }

        if (k0 + 31 > q0) {
            int rq0 = q0 + w * 16 + g;
            int rq1 = rq0 + 8;
#pragma unroll
            for (int nt = 0; nt < 4; nt++) {
                int kc = k0 + nt * 8 + qd * 2;
                if (kc     > rq0) sc[nt][0] = -1e30f;
                if (kc + 1 > rq0) sc[nt][1] = -1e30f;
                if (kc     > rq1) sc[nt][2] = -1e30f;
                if (kc + 1 > rq1) sc[nt][3] = -1e30f;
            }
        }

        float tm0 = -1e30f, tm1 = -1e30f;
#pragma unroll
        for (int nt = 0; nt < 4; nt++) {
            tm0 = fmaxf(tm0, fmaxf(sc[nt][0], sc[nt][1]));
            tm1 = fmaxf(tm1, fmaxf(sc[nt][2], sc[nt][3]));
        }
        tm0 = fmaxf(tm0, __shfl_xor_sync(0xffffffffu, tm0, 1));
        tm0 = fmaxf(tm0, __shfl_xor_sync(0xffffffffu, tm0, 2));
        tm1 = fmaxf(tm1, __shfl_xor_sync(0xffffffffu, tm1, 1));
        tm1 = fmaxf(tm1, __shfl_xor_sync(0xffffffffu, tm1, 2));

        float mn0 = fmaxf(m0, tm0), mn1 = fmaxf(m1, tm1);
        bool chg = (mn0 != m0) || (mn1 != m1);
        if (__any_sync(0xffffffffu, chg)) {
            float corr0 = expf(m0 - mn0), corr1 = expf(m1 - mn1);
            l0 *= corr0; l1 *= corr1;
#pragma unroll
            for (int nt = 0; nt < 16; nt++) {
                out[nt][0] *= corr0; out[nt][1] *= corr0;
                out[nt][2] *= corr1; out[nt][3] *= corr1;
            }
        }
        m0 = mn0; m1 = mn1;

        float s0 = 0.f, s1 = 0.f;
#pragma unroll
        for (int nt = 0; nt < 4; nt++) {
            float p0 = expf(sc[nt][0] - m0);
            float p1 = expf(sc[nt][1] - m0);
            float p2 = expf(sc[nt][2] - m1);
            float p3 = expf(sc[nt][3] - m1);
            s0 += p0 + p1; s1 += p2 + p3;
            Ps[w][g][nt * 4 + qd]     = pack_bf2(p0, p1);
            Ps[w][g + 8][nt * 4 + qd] = pack_bf2(p2, p3);
        }
        s0 += __shfl_xor_sync(0xffffffffu, s0, 1);
        s0 += __shfl_xor_sync(0xffffffffu, s0, 2);
        s1 += __shfl_xor_sync(0xffffffffu, s1, 1);
        s1 += __shfl_xor_sync(0xffffffffu, s1, 2);
        l0 += s0; l1 += s1;
        __syncwarp();

#pragma unroll
        for (int ks = 0; ks < 2; ks++) {
            int kp = ks * 8;
            uint32_t a0 = Ps[w][g][kp + qd];
            uint32_t a1 = Ps[w][g + 8][kp + qd];
            uint32_t a2 = Ps[w][g][kp + qd + 4];
            uint32_t a3 = Ps[w][g + 8][kp + qd + 4];
#pragma unroll
            for (int nt = 0; nt < 16; nt++) {
                uint32_t b0 = Vt[nt * 8 + g][kp + qd];
                uint32_t b1 = Vt[nt * 8 + g][kp + qd + 4];
                mma_bf16(out[nt], a0, a1, a2, a3, b0, b1);
            }
        }
        __syncwarp();
    }

    float inv0 = 1.f / l0, inv1 = 1.f / l1;
    int r0g = q0 + w * 16 + g;
    float* ob = attn + ((size_t)b * SEQ) * DIM + h * HDIM;
#pragma unroll
    for (int nt = 0; nt < 16; nt++) {
        int c = nt * 8 + qd * 2;
        *(float2*)(ob + (size_t)r0g * DIM + c) =
            make_float2(out[nt][0] * inv0, out[nt][1] * inv0);
        *(float2*)(ob + (size_t)(r0g + 8) * DIM + c) =
            make_float2(out[nt][2] * inv1, out[nt][3] * inv1);
    }
}

// ---------------- MoE gate -------------------------------------------------------------
__global__ void gate_kernel(const float* __restrict__ x, const float* __restrict__ wg,
                            float* __restrict__ comb) {
    int t = blockIdx.x;
    int tid = threadIdx.x;
    __shared__ float red[NE * 128];
    const float* xr = x + (size_t)t * DIM;
    float acc[NE] = {0.f, 0.f, 0.f, 0.f};
    for (int d = tid; d < DIM; d += 128) {
        float xv = xr[d];
#pragma unroll
        for (int e = 0; e < NE; e++) acc[e] += xv * wg[(size_t)d * NE + e];
    }
#pragma unroll
    for (int e = 0; e < NE; e++) red[e * 128 + tid] = acc[e];
    __syncthreads();
    for (int o = 64; o > 0; o >>= 1) {
        if (tid < o) {
#pragma unroll
            for (int e = 0; e < NE; e++) red[e * 128 + tid] += red[e * 128 + tid + o];
        }
        __syncthreads();
    }
    if (tid == 0) {
        float l[NE];
#pragma unroll
        for (int e = 0; e < NE; e++) l[e] = red[e * 128];
        float mx = fmaxf(fmaxf(l[0], l[1]), fmaxf(l[2], l[3]));
        float ex[NE], s = 0.f;
#pragma unroll
        for (int e = 0; e < NE; e++) { ex[e] = expf(l[e] - mx); s += ex[e]; }
        float p[NE];
#pragma unroll
        for (int e = 0; e < NE; e++) p[e] = ex[e] / s;
        int i0 = 0;
#pragma unroll
        for (int e = 1; e < NE; e++) if (p[e] > p[i0]) i0 = e;
        int i1 = (i0 == 0) ? 1 : 0;
#pragma unroll
        for (int e = 0; e < NE; e++) if (e != i0 && p[e] > p[i1]) i1 = e;
        float e1 = expf(p[i1] - p[i0]);
        float invs = 1.f / (1.f + e1);
        float c[NE] = {0.f, 0.f, 0.f, 0.f};
        c[i0] = invs;
        c[i1] = e1 * invs;
#pragma unroll
        for (int e = 0; e < NE; e++) comb[(size_t)t * NE + e] = c[e];
    }
}

// ---------------- Routing: build per-expert token lists --------------------------------
__global__ void zero_cnt_kernel(int* cnt) {
    if (threadIdx.x < NE) cnt[threadIdx.x] = 0;
}
__global__ void route_kernel(const float* __restrict__ comb, int* __restrict__ cnt,
                             int* __restrict__ idx) {
    int t = blockIdx.x * blockDim.x + threadIdx.x;
    if (t >= NTOK) return;
#pragma unroll
    for (int e = 0; e < NE; e++) {
        if (comb[(size_t)t * NE + e] > 0.f) {
            int pos = atomicAdd(&cnt[e], 1);
            idx[e * NTOK + pos] = t;
        }
    }
}

// ---------------- host orchestration ---------------------------------------------------
extern "C" void kernel_launch(void* const* d_in, const int* in_sizes, int n_in,
                              void* d_out, int out_size) {
    (void)in_sizes; (void)n_in; (void)out_size;
    const float* hs   = (const float*)d_in[0];
    const float* wq   = (const float*)d_in[1];
    const float* bq   = (const float*)d_in[2];
    const float* wk   = (const float*)d_in[3];
    const float* bk   = (const float*)d_in[4];
    const float* wv   = (const float*)d_in[5];
    const float* bv   = (const float*)d_in[6];
    const float* wo   = (const float*)d_in[7];
    const float* bo   = (const float*)d_in[8];
    const float* ln1w = (const float*)d_in[9];
    const float* ln1b = (const float*)d_in[10];
    const float* ln2w = (const float*)d_in[11];
    const float* ln2b = (const float*)d_in[12];
    const float* wg   = (const float*)d_in[13];
    const float* we1  = (const float*)d_in[14];
    const float* be1  = (const float*)d_in[15];
    const float* we2  = (const float*)d_in[16];
    const float* be2  = (const float*)d_in[17];
    float* out = (float*)d_out;

    float *p_ln, *p_q, *p_k, *p_v, *p_attn, *p_comb;
    int *p_cnt, *p_idx;
    cudaGetSymbolAddress((void**)&p_ln, g_ln);
    cudaGetSymbolAddress((void**)&p_q, g_q);
    cudaGetSymbolAddress((void**)&p_k, g_k);
    cudaGetSymbolAddress((void**)&p_v, g_v);
    cudaGetSymbolAddress((void**)&p_attn, g_attn);
    cudaGetSymbolAddress((void**)&p_comb, g_comb);
    cudaGetSymbolAddress((void**)&p_cnt, g_cnt);
    cudaGetSymbolAddress((void**)&p_idx, g_idx);

    // 1. LN1
    ln_kernel<<<NTOK, 256>>>(hs, ln1w, ln1b, p_ln);

    // 2. QKV projections (dense)
    dim3 gBig(DIM / 128, NTOK / 128);
    gemm_tf32<<<gBig, 128>>>(p_ln, DIM, wq, DIM, bq, p_q, DIM,
                             nullptr, 0, nullptr, 0, NTOK, DIM, DIM, 0, 0,
                             nullptr, nullptr, nullptr);
    gemm_tf32<<<gBig, 128>>>(p_ln, DIM, wk, DIM, bk, p_k, DIM,
                             nullptr, 0, nullptr, 0, NTOK, DIM, DIM, 0, 0,
                             nullptr, nullptr, nullptr);
    gemm_tf32<<<gBig, 128>>>(p_ln, DIM, wv, DIM, bv, p_v, DIM,
                             nullptr, 0, nullptr, 0, NTOK, DIM, DIM, 0, 0,
                             nullptr, nullptr, nullptr);

    // 3. RoPE
    int nrope = NTOK * NH * 64;
    rope_kernel<<<(nrope + 255) / 256, 256>>>(p_q, p_k);

    // 4. Flash attention
    dim3 gFA(SEQ / 64, BATCH * NH);
    fa_kernel<<<gFA, 128>>>(p_q, p_k, p_v, p_attn);

    // 5. O-proj + bias + residual -> out (= h)
    gemm_tf32<<<gBig, 128>>>(p_attn, DIM, wo, DIM, bo, out, DIM,
                             hs, DIM, nullptr, 0, NTOK, DIM, DIM, 0, 0,
                             nullptr, nullptr, nullptr);

    // 6. LN2
    ln_kernel<<<NTOK, 256>>>(out, ln2w, ln2b, p_ln);

    // 7. Gate + routing
    gate_kernel<<<NTOK, 128>>>(p_ln, wg, p_comb);
    zero_cnt_kernel<<<1, 32>>>(p_cnt);
    route_kernel<<<NTOK / 256, 256>>>(p_comb, p_cnt, p_idx);

    // 8. Sparse experts
    for (int e = 0; e < NE; e++) {
        const float* w1 = we1 + (size_t)e * DIM * IDIM;
        const float* b1 = be1 + (size_t)e * IDIM;
        const float* w2 = we2 + (size_t)e * IDIM * DIM;
        const float* b2 = be2 + (size_t)e * DIM;
        const int* idx_e = p_idx + e * NTOK;
        const int* cnt_e = p_cnt + e;
        gemm_tf32<<<gBig, 128>>>(p_ln, DIM, w1, IDIM, b1, p_q, IDIM,
                                 nullptr, 0, nullptr, 0, NTOK, IDIM, DIM, 1, 0,
                                 idx_e, nullptr, cnt_e);
        gemm_tf32<<<gBig, 128>>>(p_q, IDIM, w2, DIM, b2, out, DIM,
                                 nullptr, 0, p_comb + e, NE, NTOK, DIM, IDIM, 0, 1,
                                 nullptr, idx_e, cnt_e);
    }
}

// round 11
// speedup vs baseline: 1.3425x; 1.2190x over previous
#include <cuda_runtime.h>
#include <cuda_bf16.h>
#include <cuda_fp16.h>
#include <math.h>
#include <stdint.h>

#define BATCH 2
#define SEQ   2048
#define DIM   2048
#define NH    16
#define HDIM  128
#define NE    4
#define IDIM  2048
#define NTOK  (BATCH*SEQ)   // 4096

// ---------------- scratch (static device globals) ----
__device__ float g_ln   [(size_t)NTOK*DIM];
__device__ float g_q    [(size_t)NTOK*DIM];   // also reused as MoE hmid (compacted)
__device__ float g_k    [(size_t)NTOK*DIM];
__device__ float g_v    [(size_t)NTOK*DIM];
__device__ float g_attn [(size_t)NTOK*DIM];
__device__ float g_comb [(size_t)NTOK*NE];
__device__ int   g_cnt  [NE];
__device__ int   g_idx  [NE*NTOK];
__device__ __half g_wbf [(size_t)12*DIM*DIM];   // 12 transposed half weight mats [N][K]

__device__ __forceinline__ void mma_f16(float d[4], uint32_t a0, uint32_t a1,
                                        uint32_t a2, uint32_t a3,
                                        uint32_t b0, uint32_t b1) {
    asm volatile(
        "mma.sync.aligned.m16n8k16.row.col.f32.f16.f16.f32 "
        "{%0,%1,%2,%3}, {%4,%5,%6,%7}, {%8,%9}, {%0,%1,%2,%3};"
        : "+f"(d[0]), "+f"(d[1]), "+f"(d[2]), "+f"(d[3])
        : "r"(a0), "r"(a1), "r"(a2), "r"(a3), "r"(b0), "r"(b1));
}

__device__ __forceinline__ void mma_bf16(float d[4], uint32_t a0, uint32_t a1,
                                         uint32_t a2, uint32_t a3,
                                         uint32_t b0, uint32_t b1) {
    asm volatile(
        "mma.sync.aligned.m16n8k16.row.col.f32.bf16.bf16.f32 "
        "{%0,%1,%2,%3}, {%4,%5,%6,%7}, {%8,%9}, {%0,%1,%2,%3};"
        : "+f"(d[0]), "+f"(d[1]), "+f"(d[2]), "+f"(d[3])
        : "r"(a0), "r"(a1), "r"(a2), "r"(a3), "r"(b0), "r"(b1));
}

__device__ __forceinline__ uint32_t pack_bf2(float lo, float hi) {
    __nv_bfloat162 t = __floats2bfloat162_rn(lo, hi);
    return *(uint32_t*)&t;
}
__device__ __forceinline__ uint32_t pack_h2(float lo, float hi) {
    __half2 t = __floats2half2_rn(lo, hi);
    return *(uint32_t*)&t;
}
__device__ __forceinline__ uint16_t bf16bits(float x) {
    __nv_bfloat16 t = __float2bfloat16_rn(x);
    return *(uint16_t*)&t;
}

// ---------------- Weight prep: transpose+convert 12 matrices to half [N][K] ------------
__global__ void wprep_kernel(const float* __restrict__ wq, const float* __restrict__ wk,
                             const float* __restrict__ wv, const float* __restrict__ wo,
                             const float* __restrict__ we1, const float* __restrict__ we2,
                             __half* __restrict__ wbf) {
    int z = blockIdx.z;
    const float* src;
    if (z == 0) src = wq;
    else if (z == 1) src = wk;
    else if (z == 2) src = wv;
    else if (z == 3) src = wo;
    else if (z < 8) src = we1 + (size_t)(z - 4) * DIM * IDIM;
    else src = we2 + (size_t)(z - 8) * IDIM * DIM;
    __half* dst = wbf + (size_t)z * DIM * DIM;
    __shared__ float tile[32][33];
    int k0 = blockIdx.y * 32, n0 = blockIdx.x * 32;
    int tx = threadIdx.x, ty = threadIdx.y;   // 32 x 8
#pragma unroll
    for (int r = ty; r < 32; r += 8)
        tile[r][tx] = src[(size_t)(k0 + r) * DIM + n0 + tx];
    __syncthreads();
#pragma unroll
    for (int r = ty; r < 32; r += 8)
        dst[(size_t)(n0 + r) * DIM + k0 + tx] = __float2half_rn(tile[tx][r]);
}

// ---------------- LayerNorm ----------------
__global__ void ln_kernel(const float* __restrict__ x, const float* __restrict__ w,
                          const float* __restrict__ b, float* __restrict__ y) {
    int row = blockIdx.x;
    const float* xr = x + (size_t)row * DIM;
    float* yr = y + (size_t)row * DIM;
    __shared__ float red[256];
    int tid = threadIdx.x;
    float s = 0.f;
    for (int i = tid; i < DIM; i += 256) s += xr[i];
    red[tid] = s; __syncthreads();
    for (int o = 128; o > 0; o >>= 1) { if (tid < o) red[tid] += red[tid + o]; __syncthreads(); }
    float mu = red[0] * (1.f / DIM);
    __syncthreads();
    float v = 0.f;
    for (int i = tid; i < DIM; i += 256) { float d = xr[i] - mu; v += d * d; }
    red[tid] = v; __syncthreads();
    for (int o = 128; o > 0; o >>= 1) { if (tid < o) red[tid] += red[tid + o]; __syncthreads(); }
    float inv = rsqrtf(red[0] * (1.f / DIM) + 1e-5f);
    for (int i = tid; i < DIM; i += 256) yr[i] = (xr[i] - mu) * inv * w[i] + b[i];
}

// ---------------- FP16 GEMM: 128 thr, 4 warps (2x2), 64x64 warp tiles, ktile 32 --------
// A fp32 [M][K] (optional row gather), B half pre-transposed [N][K]. C fp32.
__device__ __forceinline__ void epi(float v, int gm, int gn,
                                    const float* bias, int act,
                                    const float* resid, int ldr,
                                    const float* rowscale, int rss,
                                    float* C, int ldc, int accum) {
    if (bias) v += bias[gn];
    if (act) v = 0.5f * v * (1.f + erff(v * 0.70710678118654752f));
    if (resid) v += resid[(size_t)gm * ldr + gn];
    if (rowscale) v *= rowscale[(size_t)gm * rss];
    size_t o = (size_t)gm * ldc + gn;
    if (accum) C[o] += v; else C[o] = v;
}

__global__ void __launch_bounds__(128)
gemm_f16(const float* __restrict__ A, int lda,
         const __half* __restrict__ Bt, int ldb,           // Bt[N][K], ldb = K
         const float* __restrict__ bias,
         float* __restrict__ C, int ldc,
         const float* __restrict__ resid, int ldr,
         const float* __restrict__ rowscale, int rss,
         int M, int N, int K, int act, int accum,
         const int* __restrict__ amap, const int* __restrict__ cmap,
         const int* __restrict__ mcount) {
    int M_eff = mcount ? *mcount : M;
    int row0 = blockIdx.y * 128, col0 = blockIdx.x * 128;
    if (row0 >= M_eff) return;

    __shared__ uint32_t As[128][20];   // [m][kpair], 16 pairs + pad
    __shared__ uint32_t Bs[128][20];   // [n][kpair]
    int tid = threadIdx.x;
    int w = tid >> 5, lane = tid & 31;
    int wm = w >> 1, wn = w & 1;
    int m_w = wm * 64, n_w = wn * 64;
    int g = lane >> 2, q = lane & 3;

    float acc[4][8][4];
#pragma unroll
    for (int i = 0; i < 4; i++)
#pragma unroll
        for (int j = 0; j < 8; j++)
#pragma unroll
            for (int r = 0; r < 4; r++) acc[i][j][r] = 0.f;

    // A staging: 8 float4/thread. row m = mbase+16j, chunk ac covers floats ac*4..+3.
    int mbase = tid >> 3, ac = tid & 7;
    const float* Ap[8];
#pragma unroll
    for (int j = 0; j < 8; j++) {
        int gm = row0 + mbase + 16 * j;
        int cl = gm < M_eff ? gm : M_eff - 1;
        int ar = amap ? amap[cl] : cl;
        Ap[j] = A + (size_t)ar * lda + ac * 4;
    }
    // B staging: 4 uint4/thread. row n = nbase+32j, chunk bc covers halfs bc*8..+7.
    int nbase = tid >> 2, bc = tid & 3;
    const __half* Bp[4];
#pragma unroll
    for (int j = 0; j < 4; j++)
        Bp[j] = Bt + (size_t)(col0 + nbase + 32 * j) * ldb + bc * 8;

    float4 pa[8];
    uint4 pb[4];
#pragma unroll
    for (int j = 0; j < 8; j++) pa[j] = *(const float4*)Ap[j];
#pragma unroll
    for (int j = 0; j < 4; j++) pb[j] = *(const uint4*)Bp[j];

    int nk = K / 32;
    for (int t = 0; t < nk; t++) {
#pragma unroll
        for (int j = 0; j < 8; j++) {
            int m = mbase + 16 * j;
            As[m][ac * 2]     = pack_h2(pa[j].x, pa[j].y);
            As[m][ac * 2 + 1] = pack_h2(pa[j].z, pa[j].w);
        }
#pragma unroll
        for (int j = 0; j < 4; j++)
            *(uint4*)&Bs[nbase + 32 * j][bc * 4] = pb[j];
        __syncthreads();

        if (t + 1 < nk) {
            int k0 = (t + 1) * 32;
#pragma unroll
            for (int j = 0; j < 8; j++) pa[j] = *(const float4*)(Ap[j] + k0);
#pragma unroll
            for (int j = 0; j < 4; j++) pb[j] = *(const uint4*)(Bp[j] + k0);
        }

#pragma unroll
        for (int ks = 0; ks < 2; ks++) {
            int kp = ks * 8;
            uint32_t af[4][4], bf[8][2];
#pragma unroll
            for (int i = 0; i < 4; i++) {
                int r = m_w + i * 16 + g;
                af[i][0] = As[r][kp + q];
                af[i][1] = As[r + 8][kp + q];
                af[i][2] = As[r][kp + q + 4];
                af[i][3] = As[r + 8][kp + q + 4];
            }
#pragma unroll
            for (int j = 0; j < 8; j++) {
                int c = n_w + j * 8 + g;
                bf[j][0] = Bs[c][kp + q];
                bf[j][1] = Bs[c][kp + q + 4];
            }
#pragma unroll
            for (int i = 0; i < 4; i++)
#pragma unroll
                for (int j = 0; j < 8; j++)
                    mma_f16(acc[i][j], af[i][0], af[i][1], af[i][2], af[i][3],
                            bf[j][0], bf[j][1]);
        }
        __syncthreads();
    }

#pragma unroll
    for (int i = 0; i < 4; i++) {
        int gm = row0 + m_w + i * 16 + g;
        if (gm < M_eff) {
            int cr = cmap ? cmap[gm] : gm;
#pragma unroll
            for (int j = 0; j < 8; j++) {
                int cb = col0 + n_w + j * 8 + q * 2;
                epi(acc[i][j][0], cr, cb,     bias, act, resid, ldr, rowscale, rss, C, ldc, accum);
                epi(acc[i][j][1], cr, cb + 1, bias, act, resid, ldr, rowscale, rss, C, ldc, accum);
            }
        }
        int gm2 = gm + 8;
        if (gm2 < M_eff) {
            int cr2 = cmap ? cmap[gm2] : gm2;
#pragma unroll
            for (int j = 0; j < 8; j++) {
                int cb = col0 + n_w + j * 8 + q * 2;
                epi(acc[i][j][2], cr2, cb,     bias, act, resid, ldr, rowscale, rss, C, ldc, accum);
                epi(acc[i][j][3], cr2, cb + 1, bias, act, resid, ldr, rowscale, rss, C, ldc, accum);
            }
        }
    }
}

// ---------------- RoPE ----------------------------------------------------------------
__global__ void rope_kernel(float* __restrict__ q, float* __restrict__ k) {
    int idx = blockIdx.x * blockDim.x + threadIdx.x;
    if (idx >= NTOK * NH * 64) return;
    int i = idx & 63;
    int rem = idx >> 6;
    int h = rem % NH;
    int t = rem / NH;
    int s = t % SEQ;
    float invf = (float)(1.0 / pow(10000.0, (double)i / 64.0));
    float ang = (float)s * invf;
    double angd = (double)ang;
    float c  = (float)cos(angd);
    float sn = (float)sin(angd);
    size_t base = (size_t)t * DIM + (size_t)h * HDIM;
    float q1 = q[base + i], q2 = q[base + 64 + i];
    q[base + i]      = q1 * c - q2 * sn;
    q[base + 64 + i] = q2 * c + q1 * sn;
    float k1 = k[base + i], k2 = k[base + 64 + i];
    k[base + i]      = k1 * c - k2 * sn;
    k[base + 64 + i] = k2 * c + k1 * sn;
}

// ---------------- Flash attention (R8/R9, proven) --------------------------------------
__global__ void __launch_bounds__(128)
fa_kernel(const float* __restrict__ q, const float* __restrict__ k,
          const float* __restrict__ v, float* __restrict__ attn) {
    __shared__ uint32_t Ks[32][68];
    __shared__ uint32_t Vt[128][20];
    __shared__ uint32_t Ps[4][16][20];

    int bh = blockIdx.y;
    int b = bh / NH, h = bh % NH;
    int q0 = blockIdx.x * 64;
    int tid = threadIdx.x, w = tid >> 5, lane = tid & 31;
    int g = lane >> 2, qd = lane & 3;
    const float alpha = 0.08838834764831845f;

    const float* qb = q + ((size_t)b * SEQ) * DIM + h * HDIM;
    const float* kb_ = k + ((size_t)b * SEQ) * DIM + h * HDIM;
    const float* vb = v + ((size_t)b * SEQ) * DIM + h * HDIM;

    uint32_t qf[8][4];
    {
        const float* qr0 = qb + (size_t)(q0 + w * 16 + g) * DIM;
        const float* qr1 = qr0 + 8 * DIM;
#pragma unroll
        for (int ks = 0; ks < 8; ks++) {
            int c0 = (ks * 8 + qd) * 2, c1 = (ks * 8 + qd + 4) * 2;
            float2 t00 = *(const float2*)(qr0 + c0);
            float2 t10 = *(const float2*)(qr1 + c0);
            float2 t01 = *(const float2*)(qr0 + c1);
            float2 t11 = *(const float2*)(qr1 + c1);
            qf[ks][0] = pack_bf2(t00.x * alpha, t00.y * alpha);
            qf[ks][1] = pack_bf2(t10.x * alpha, t10.y * alpha);
            qf[ks][2] = pack_bf2(t01.x * alpha, t01.y * alpha);
            qf[ks][3] = pack_bf2(t11.x * alpha, t11.y * alpha);
        }
    }

    float m0 = -1e30f, m1 = -1e30f, l0 = 0.f, l1 = 0.f;
    float out[16][4];
#pragma unroll
    for (int i = 0; i < 16; i++)
#pragma unroll
        for (int r = 0; r < 4; r++) out[i][r] = 0.f;

    int ktiles = q0 / 32 + 2;

    for (int kt = 0; kt < ktiles; kt++) {
        int k0 = kt * 32;
        __syncthreads();
        for (int i = tid; i < 32 * 32; i += 128) {
            int r = i >> 5, c4 = i & 31;
            float4 tk = *(const float4*)(kb_ + (size_t)(k0 + r) * DIM + c4 * 4);
            Ks[r][c4 * 2]     = pack_bf2(tk.x, tk.y);
            Ks[r][c4 * 2 + 1] = pack_bf2(tk.z, tk.w);
            float4 tv = *(const float4*)(vb + (size_t)(k0 + r) * DIM + c4 * 4);
            uint16_t* vt = (uint16_t*)Vt;
            vt[(c4 * 4 + 0) * 40 + r] = bf16bits(tv.x);
            vt[(c4 * 4 + 1) * 40 + r] = bf16bits(tv.y);
            vt[(c4 * 4 + 2) * 40 + r] = bf16bits(tv.z);
            vt[(c4 * 4 + 3) * 40 + r] = bf16bits(tv.w);
        }
        __syncthreads();

        float sc[4][4];
#pragma unroll
        for (int nt = 0; nt < 4; nt++)
#pragma unroll
            for (int r = 0; r < 4; r++) sc[nt][r] = 0.f;
#pragma unroll
        for (int ks = 0; ks < 8; ks++) {
            int kp = ks * 8;
#pragma unroll
            for (int nt = 0; nt < 4; nt++) {
                uint32_t b0 = Ks[nt * 8 + g][kp + qd];
                uint32_t b1 = Ks[nt * 8 + g][kp + qd + 4];
                mma_bf16(sc[nt], qf[ks][0], qf[ks][1], qf[ks][2], qf[ks][3], b0, b1);
            }
        }

        if (k0 + 31 > q0) {
            int rq0 = q0 + w * 16 + g;
            int rq1 = rq0 + 8;
#pragma unroll
            for (int nt = 0; nt < 4; nt++) {
                int kc = k0 + nt * 8 + qd * 2;
                if (kc     > rq0) sc[nt][0] = -1e30f;
                if (kc + 1 > rq0) sc[nt][1] = -1e30f;
                if (kc     > rq1) sc[nt][2] = -1e30f;
                if (kc + 1 > rq1) sc[nt][3] = -1e30f;
            }
        }

        float tm0 = -1e30f, tm1 = -1e30f;
#pragma unroll
        for (int nt = 0; nt < 4; nt++) {
            tm0 = fmaxf(tm0, fmaxf(sc[nt][0], sc[nt][1]));
            tm1 = fmaxf(tm1, fmaxf(sc[nt][2], sc[nt][3]));
        }
        tm0 = fmaxf(tm0, __shfl_xor_sync(0xffffffffu, tm0, 1));
        tm0 = fmaxf(tm0, __shfl_xor_sync(0xffffffffu, tm0, 2));
        tm1 = fmaxf(tm1, __shfl_xor_sync(0xffffffffu, tm1, 1));
        tm1 = fmaxf(tm1, __shfl_xor_sync(0xffffffffu, tm1, 2));

        float mn0 = fmaxf(m0, tm0), mn1 = fmaxf(m1, tm1);
        bool chg = (mn0 != m0) || (mn1 != m1);
        if (__any_sync(0xffffffffu, chg)) {
            float corr0 = expf(m0 - mn0), corr1 = expf(m1 - mn1);
            l0 *= corr0; l1 *= corr1;
#pragma unroll
            for (int nt = 0; nt < 16; nt++) {
                out[nt][0] *= corr0; out[nt][1] *= corr0;
                out[nt][2] *= corr1; out[nt][3] *= corr1;
            }
        }
        m0 = mn0; m1 = mn1;

        float s0 = 0.f, s1 = 0.f;
#pragma unroll
        for (int nt = 0; nt < 4; nt++) {
            float p0 = expf(sc[nt][0] - m0);
            float p1 = expf(sc[nt][1] - m0);
            float p2 = expf(sc[nt][2] - m1);
            float p3 = expf(sc[nt][3] - m1);
            s0 += p0 + p1; s1 += p2 + p3;
            Ps[w][g][nt * 4 + qd]     = pack_bf2(p0, p1);
            Ps[w][g + 8][nt * 4 + qd] = pack_bf2(p2, p3);
        }
        s0 += __shfl_xor_sync(0xffffffffu, s0, 1);
        s0 += __shfl_xor_sync(0xffffffffu, s0, 2);
        s1 += __shfl_xor_sync(0xffffffffu, s1, 1);
        s1 += __shfl_xor_sync(0xffffffffu, s1, 2);
        l0 += s0; l1 += s1;
        __syncwarp();

#pragma unroll
        for (int ks = 0; ks < 2; ks++) {
            int kp = ks * 8;
            uint32_t a0 = Ps[w][g][kp + qd];
            uint32_t a1 = Ps[w][g + 8][kp + qd];
            uint32_t a2 = Ps[w][g][kp + qd + 4];
            uint32_t a3 = Ps[w][g + 8][kp + qd + 4];
#pragma unroll
            for (int nt = 0; nt < 16; nt++) {
                uint32_t b0 = Vt[nt * 8 + g][kp + qd];
                uint32_t b1 = Vt[nt * 8 + g][kp + qd + 4];
                mma_bf16(out[nt], a0, a1, a2, a3, b0, b1);
            }
        }
        __syncwarp();
    }

    float inv0 = 1.f / l0, inv1 = 1.f / l1;
    int r0g = q0 + w * 16 + g;
    float* ob = attn + ((size_t)b * SEQ) * DIM + h * HDIM;
#pragma unroll
    for (int nt = 0; nt < 16; nt++) {
        int c = nt * 8 + qd * 2;
        *(float2*)(ob + (size_t)r0g * DIM + c) =
            make_float2(out[nt][0] * inv0, out[nt][1] * inv0);
        *(float2*)(ob + (size_t)(r0g + 8) * DIM + c) =
            make_float2(out[nt][2] * inv1, out[nt][3] * inv1);
    }
}

// ---------------- MoE gate -------------------------------------------------------------
__global__ void gate_kernel(const float* __restrict__ x, const float* __restrict__ wg,
                            float* __restrict__ comb) {
    int t = blockIdx.x;
    int tid = threadIdx.x;
    __shared__ float red[NE * 128];
    const float* xr = x + (size_t)t * DIM;
    float acc[NE] = {0.f, 0.f, 0.f, 0.f};
    for (int d = tid; d < DIM; d += 128) {
        float xv = xr[d];
#pragma unroll
        for (int e = 0; e < NE; e++) acc[e] += xv * wg[(size_t)d * NE + e];
    }
#pragma unroll
    for (int e = 0; e < NE; e++) red[e * 128 + tid] = acc[e];
    __syncthreads();
    for (int o = 64; o > 0; o >>= 1) {
        if (tid < o) {
#pragma unroll
            for (int e = 0; e < NE; e++) red[e * 128 + tid] += red[e * 128 + tid + o];
        }
        __syncthreads();
    }
    if (tid == 0) {
        float l[NE];
#pragma unroll
        for (int e = 0; e < NE; e++) l[e] = red[e * 128];
        float mx = fmaxf(fmaxf(l[0], l[1]), fmaxf(l[2], l[3]));
        float ex[NE], s = 0.f;
#pragma unroll
        for (int e = 0; e < NE; e++) { ex[e] = expf(l[e] - mx); s += ex[e]; }
        float p[NE];
#pragma unroll
        for (int e = 0; e < NE; e++) p[e] = ex[e] / s;
        int i0 = 0;
#pragma unroll
        for (int e = 1; e < NE; e++) if (p[e] > p[i0]) i0 = e;
        int i1 = (i0 == 0) ? 1 : 0;
#pragma unroll
        for (int e = 0; e < NE; e++) if (e != i0 && p[e] > p[i1]) i1 = e;
        float e1 = expf(p[i1] - p[i0]);
        float invs = 1.f / (1.f + e1);
        float c[NE] = {0.f, 0.f, 0.f, 0.f};
        c[i0] = invs;
        c[i1] = e1 * invs;
#pragma unroll
        for (int e = 0; e < NE; e++) comb[(size_t)t * NE + e] = c[e];
    }
}

// ---------------- Routing --------------------------------------------------------------
__global__ void zero_cnt_kernel(int* cnt) {
    if (threadIdx.x < NE) cnt[threadIdx.x] = 0;
}
__global__ void route_kernel(const float* __restrict__ comb, int* __restrict__ cnt,
                             int* __restrict__ idx) {
    int t = blockIdx.x * blockDim.x + threadIdx.x;
    if (t >= NTOK) return;
#pragma unroll
    for (int e = 0; e < NE; e++) {
        if (comb[(size_t)t * NE + e] > 0.f) {
            int pos = atomicAdd(&cnt[e], 1);
            idx[e * NTOK + pos] = t;
        }
    }
}

// ---------------- host orchestration ---------------------------------------------------
extern "C" void kernel_launch(void* const* d_in, const int* in_sizes, int n_in,
                              void* d_out, int out_size) {
    (void)in_sizes; (void)n_in; (void)out_size;
    const float* hs   = (const float*)d_in[0];
    const float* wq   = (const float*)d_in[1];
    const float* bq   = (const float*)d_in[2];
    const float* wk   = (const float*)d_in[3];
    const float* bk   = (const float*)d_in[4];
    const float* wv   = (const float*)d_in[5];
    const float* bv   = (const float*)d_in[6];
    const float* wo   = (const float*)d_in[7];
    const float* bo   = (const float*)d_in[8];
    const float* ln1w = (const float*)d_in[9];
    const float* ln1b = (const float*)d_in[10];
    const float* ln2w = (const float*)d_in[11];
    const float* ln2b = (const float*)d_in[12];
    const float* wg   = (const float*)d_in[13];
    const float* we1  = (const float*)d_in[14];
    const float* be1  = (const float*)d_in[15];
    const float* we2  = (const float*)d_in[16];
    const float* be2  = (const float*)d_in[17];
    float* out = (float*)d_out;

    float *p_ln, *p_q, *p_k, *p_v, *p_attn, *p_comb;
    int *p_cnt, *p_idx;
    __half* p_wbf;
    cudaGetSymbolAddress((void**)&p_ln, g_ln);
    cudaGetSymbolAddress((void**)&p_q, g_q);
    cudaGetSymbolAddress((void**)&p_k, g_k);
    cudaGetSymbolAddress((void**)&p_v, g_v);
    cudaGetSymbolAddress((void**)&p_attn, g_attn);
    cudaGetSymbolAddress((void**)&p_comb, g_comb);
    cudaGetSymbolAddress((void**)&p_cnt, g_cnt);
    cudaGetSymbolAddress((void**)&p_idx, g_idx);
    cudaGetSymbolAddress((void**)&p_wbf, g_wbf);

    // 0. Weight prep: transpose + fp16 convert all 12 weight matrices
    dim3 gW(DIM / 32, DIM / 32, 12);
    wprep_kernel<<<gW, dim3(32, 8)>>>(wq, wk, wv, wo, we1, we2, p_wbf);

    // 1. LN1
    ln_kernel<<<NTOK, 256>>>(hs, ln1w, ln1b, p_ln);

    // 2. QKV projections (fp16 tensor cores, pre-transposed weights)
    dim3 gBig(DIM / 128, NTOK / 128);
    size_t WSZ = (size_t)DIM * DIM;
    gemm_f16<<<gBig, 128>>>(p_ln, DIM, p_wbf + 0 * WSZ, DIM, bq, p_q, DIM,
                            nullptr, 0, nullptr, 0, NTOK, DIM, DIM, 0, 0,
                            nullptr, nullptr, nullptr);
    gemm_f16<<<gBig, 128>>>(p_ln, DIM, p_wbf + 1 * WSZ, DIM, bk, p_k, DIM,
                            nullptr, 0, nullptr, 0, NTOK, DIM, DIM, 0, 0,
                            nullptr, nullptr, nullptr);
    gemm_f16<<<gBig, 128>>>(p_ln, DIM, p_wbf + 2 * WSZ, DIM, bv, p_v, DIM,
                            nullptr, 0, nullptr, 0, NTOK, DIM, DIM, 0, 0,
                            nullptr, nullptr, nullptr);

    // 3. RoPE
    int nrope = NTOK * NH * 64;
    rope_kernel<<<(nrope + 255) / 256, 256>>>(p_q, p_k);

    // 4. Flash attention
    dim3 gFA(SEQ / 64, BATCH * NH);
    fa_kernel<<<gFA, 128>>>(p_q, p_k, p_v, p_attn);

    // 5. O-proj + bias + residual -> out (= h)
    gemm_f16<<<gBig, 128>>>(p_attn, DIM, p_wbf + 3 * WSZ, DIM, bo, out, DIM,
                            hs, DIM, nullptr, 0, NTOK, DIM, DIM, 0, 0,
                            nullptr, nullptr, nullptr);

    // 6. LN2
    ln_kernel<<<NTOK, 256>>>(out, ln2w, ln2b, p_ln);

    // 7. Gate + routing
    gate_kernel<<<NTOK, 128>>>(p_ln, wg, p_comb);
    zero_cnt_kernel<<<1, 32>>>(p_cnt);
    route_kernel<<<NTOK / 256, 256>>>(p_comb, p_cnt, p_idx);

    // 8. Sparse experts (fp16 weights, gather/scatter rows)
    for (int e = 0; e < NE; e++) {
        const float* b1 = be1 + (size_t)e * IDIM;
        const float* b2 = be2 + (size_t)e * DIM;
        const int* idx_e = p_idx + e * NTOK;
        const int* cnt_e = p_cnt + e;
        gemm_f16<<<gBig, 128>>>(p_ln, DIM, p_wbf + (4 + e) * WSZ, DIM, b1, p_q, IDIM,
                                nullptr, 0, nullptr, 0, NTOK, IDIM, DIM, 1, 0,
                                idx_e, nullptr, cnt_e);
        gemm_f16<<<gBig, 128>>>(p_q, IDIM, p_wbf + (8 + e) * WSZ, IDIM, b2, out, DIM,
                                nullptr, 0, p_comb + e, NE, NTOK, DIM, IDIM, 0, 1,
                                nullptr, idx_e, cnt_e);
    }
}

// round 12
// speedup vs baseline: 1.3516x; 1.0067x over previous
#include <cuda_runtime.h>
#include <cuda_bf16.h>
#include <cuda_fp16.h>
#include <math.h>
#include <stdint.h>

#define BATCH 2
#define SEQ   2048
#define DIM   2048
#define NH    16
#define HDIM  128
#define NE    4
#define IDIM  2048
#define NTOK  (BATCH*SEQ)   // 4096

// ---------------- scratch (static device globals) ----
__device__ float g_ln   [(size_t)NTOK*DIM];
__device__ float g_q    [(size_t)NTOK*DIM];   // also reused as MoE hmid (compacted)
__device__ float g_k    [(size_t)NTOK*DIM];
__device__ float g_v    [(size_t)NTOK*DIM];
__device__ float g_attn [(size_t)NTOK*DIM];
__device__ float g_comb [(size_t)NTOK*NE];
__device__ int   g_cnt  [NE];
__device__ int   g_idx  [NE*NTOK];
__device__ __half g_wbf [(size_t)12*DIM*DIM];   // 12 transposed half weight mats [N][K]

__device__ __forceinline__ void mma_f16(float d[4], uint32_t a0, uint32_t a1,
                                        uint32_t a2, uint32_t a3,
                                        uint32_t b0, uint32_t b1) {
    asm volatile(
        "mma.sync.aligned.m16n8k16.row.col.f32.f16.f16.f32 "
        "{%0,%1,%2,%3}, {%4,%5,%6,%7}, {%8,%9}, {%0,%1,%2,%3};"
        : "+f"(d[0]), "+f"(d[1]), "+f"(d[2]), "+f"(d[3])
        : "r"(a0), "r"(a1), "r"(a2), "r"(a3), "r"(b0), "r"(b1));
}

__device__ __forceinline__ void mma_bf16(float d[4], uint32_t a0, uint32_t a1,
                                         uint32_t a2, uint32_t a3,
                                         uint32_t b0, uint32_t b1) {
    asm volatile(
        "mma.sync.aligned.m16n8k16.row.col.f32.bf16.bf16.f32 "
        "{%0,%1,%2,%3}, {%4,%5,%6,%7}, {%8,%9}, {%0,%1,%2,%3};"
        : "+f"(d[0]), "+f"(d[1]), "+f"(d[2]), "+f"(d[3])
        : "r"(a0), "r"(a1), "r"(a2), "r"(a3), "r"(b0), "r"(b1));
}

__device__ __forceinline__ uint32_t pack_bf2(float lo, float hi) {
    __nv_bfloat162 t = __floats2bfloat162_rn(lo, hi);
    return *(uint32_t*)&t;
}
__device__ __forceinline__ uint32_t pack_h2(float lo, float hi) {
    __half2 t = __floats2half2_rn(lo, hi);
    return *(uint32_t*)&t;
}
__device__ __forceinline__ uint16_t bf16bits(float x) {
    __nv_bfloat16 t = __float2bfloat16_rn(x);
    return *(uint16_t*)&t;
}

// ---------------- Weight prep: transpose+convert 12 matrices to half [N][K] ------------
__global__ void wprep_kernel(const float* __restrict__ wq, const float* __restrict__ wk,
                             const float* __restrict__ wv, const float* __restrict__ wo,
                             const float* __restrict__ we1, const float* __restrict__ we2,
                             __half* __restrict__ wbf) {
    int z = blockIdx.z;
    const float* src;
    if (z == 0) src = wq;
    else if (z == 1) src = wk;
    else if (z == 2) src = wv;
    else if (z == 3) src = wo;
    else if (z < 8) src = we1 + (size_t)(z - 4) * DIM * IDIM;
    else src = we2 + (size_t)(z - 8) * IDIM * DIM;
    __half* dst = wbf + (size_t)z * DIM * DIM;
    __shared__ float tile[32][33];
    int k0 = blockIdx.y * 32, n0 = blockIdx.x * 32;
    int tx = threadIdx.x, ty = threadIdx.y;   // 32 x 8
#pragma unroll
    for (int r = ty; r < 32; r += 8)
        tile[r][tx] = src[(size_t)(k0 + r) * DIM + n0 + tx];
    __syncthreads();
#pragma unroll
    for (int r = ty; r < 32; r += 8)
        dst[(size_t)(n0 + r) * DIM + k0 + tx] = __float2half_rn(tile[tx][r]);
}

// ---------------- LayerNorm ----------------
__global__ void ln_kernel(const float* __restrict__ x, const float* __restrict__ w,
                          const float* __restrict__ b, float* __restrict__ y) {
    int row = blockIdx.x;
    const float* xr = x + (size_t)row * DIM;
    float* yr = y + (size_t)row * DIM;
    __shared__ float red[256];
    int tid = threadIdx.x;
    float s = 0.f;
    for (int i = tid; i < DIM; i += 256) s += xr[i];
    red[tid] = s; __syncthreads();
    for (int o = 128; o > 0; o >>= 1) { if (tid < o) red[tid] += red[tid + o]; __syncthreads(); }
    float mu = red[0] * (1.f / DIM);
    __syncthreads();
    float v = 0.f;
    for (int i = tid; i < DIM; i += 256) { float d = xr[i] - mu; v += d * d; }
    red[tid] = v; __syncthreads();
    for (int o = 128; o > 0; o >>= 1) { if (tid < o) red[tid] += red[tid + o]; __syncthreads(); }
    float inv = rsqrtf(red[0] * (1.f / DIM) + 1e-5f);
    for (int i = tid; i < DIM; i += 256) yr[i] = (xr[i] - mu) * inv * w[i] + b[i];
}

// ---------------- FP16 GEMM: 128 thr, 4 warps (2x2), 64x64 warp tiles, ktile 32 --------
__device__ __forceinline__ void epi(float v, int gm, int gn,
                                    const float* bias, int act,
                                    const float* resid, int ldr,
                                    const float* rowscale, int rss,
                                    float* C, int ldc, int accum) {
    if (bias) v += bias[gn];
    if (act) v = 0.5f * v * (1.f + erff(v * 0.70710678118654752f));
    if (resid) v += resid[(size_t)gm * ldr + gn];
    if (rowscale) v *= rowscale[(size_t)gm * rss];
    size_t o = (size_t)gm * ldc + gn;
    if (accum) C[o] += v; else C[o] = v;
}

__global__ void __launch_bounds__(128)
gemm_f16(const float* __restrict__ A, int lda,
         const __half* __restrict__ Bt, int ldb,           // Bt[N][K], ldb = K
         const float* __restrict__ bias,
         float* __restrict__ C, int ldc,
         const float* __restrict__ resid, int ldr,
         const float* __restrict__ rowscale, int rss,
         int M, int N, int K, int act, int accum,
         const int* __restrict__ amap, const int* __restrict__ cmap,
         const int* __restrict__ mcount) {
    int M_eff = mcount ? *mcount : M;
    int row0 = blockIdx.y * 128, col0 = blockIdx.x * 128;
    if (row0 >= M_eff) return;

    __shared__ uint32_t As[128][20];
    __shared__ uint32_t Bs[128][20];
    int tid = threadIdx.x;
    int w = tid >> 5, lane = tid & 31;
    int wm = w >> 1, wn = w & 1;
    int m_w = wm * 64, n_w = wn * 64;
    int g = lane >> 2, q = lane & 3;

    float acc[4][8][4];
#pragma unroll
    for (int i = 0; i < 4; i++)
#pragma unroll
        for (int j = 0; j < 8; j++)
#pragma unroll
            for (int r = 0; r < 4; r++) acc[i][j][r] = 0.f;

    int mbase = tid >> 3, ac = tid & 7;
    const float* Ap[8];
#pragma unroll
    for (int j = 0; j < 8; j++) {
        int gm = row0 + mbase + 16 * j;
        int cl = gm < M_eff ? gm : M_eff - 1;
        int ar = amap ? amap[cl] : cl;
        Ap[j] = A + (size_t)ar * lda + ac * 4;
    }
    int nbase = tid >> 2, bc = tid & 3;
    const __half* Bp[4];
#pragma unroll
    for (int j = 0; j < 4; j++)
        Bp[j] = Bt + (size_t)(col0 + nbase + 32 * j) * ldb + bc * 8;

    float4 pa[8];
    uint4 pb[4];
#pragma unroll
    for (int j = 0; j < 8; j++) pa[j] = *(const float4*)Ap[j];
#pragma unroll
    for (int j = 0; j < 4; j++) pb[j] = *(const uint4*)Bp[j];

    int nk = K / 32;
    for (int t = 0; t < nk; t++) {
#pragma unroll
        for (int j = 0; j < 8; j++) {
            int m = mbase + 16 * j;
            As[m][ac * 2]     = pack_h2(pa[j].x, pa[j].y);
            As[m][ac * 2 + 1] = pack_h2(pa[j].z, pa[j].w);
        }
#pragma unroll
        for (int j = 0; j < 4; j++)
            *(uint4*)&Bs[nbase + 32 * j][bc * 4] = pb[j];
        __syncthreads();

        if (t + 1 < nk) {
            int k0 = (t + 1) * 32;
#pragma unroll
            for (int j = 0; j < 8; j++) pa[j] = *(const float4*)(Ap[j] + k0);
#pragma unroll
            for (int j = 0; j < 4; j++) pb[j] = *(const uint4*)(Bp[j] + k0);
        }

#pragma unroll
        for (int ks = 0; ks < 2; ks++) {
            int kp = ks * 8;
            uint32_t af[4][4], bf[8][2];
#pragma unroll
            for (int i = 0; i < 4; i++) {
                int r = m_w + i * 16 + g;
                af[i][0] = As[r][kp + q];
                af[i][1] = As[r + 8][kp + q];
                af[i][2] = As[r][kp + q + 4];
                af[i][3] = As[r + 8][kp + q + 4];
            }
#pragma unroll
            for (int j = 0; j < 8; j++) {
                int c = n_w + j * 8 + g;
                bf[j][0] = Bs[c][kp + q];
                bf[j][1] = Bs[c][kp + q + 4];
            }
#pragma unroll
            for (int i = 0; i < 4; i++)
#pragma unroll
                for (int j = 0; j < 8; j++)
                    mma_f16(acc[i][j], af[i][0], af[i][1], af[i][2], af[i][3],
                            bf[j][0], bf[j][1]);
        }
        __syncthreads();
    }

#pragma unroll
    for (int i = 0; i < 4; i++) {
        int gm = row0 + m_w + i * 16 + g;
        if (gm < M_eff) {
            int cr = cmap ? cmap[gm] : gm;
#pragma unroll
            for (int j = 0; j < 8; j++) {
                int cb = col0 + n_w + j * 8 + q * 2;
                epi(acc[i][j][0], cr, cb,     bias, act, resid, ldr, rowscale, rss, C, ldc, accum);
                epi(acc[i][j][1], cr, cb + 1, bias, act, resid, ldr, rowscale, rss, C, ldc, accum);
            }
        }
        int gm2 = gm + 8;
        if (gm2 < M_eff) {
            int cr2 = cmap ? cmap[gm2] : gm2;
#pragma unroll
            for (int j = 0; j < 8; j++) {
                int cb = col0 + n_w + j * 8 + q * 2;
                epi(acc[i][j][2], cr2, cb,     bias, act, resid, ldr, rowscale, rss, C, ldc, accum);
                epi(acc[i][j][3], cr2, cb + 1, bias, act, resid, ldr, rowscale, rss, C, ldc, accum);
            }
        }
    }
}

// ---------------- RoPE ----------------------------------------------------------------
__global__ void rope_kernel(float* __restrict__ q, float* __restrict__ k) {
    int idx = blockIdx.x * blockDim.x + threadIdx.x;
    if (idx >= NTOK * NH * 64) return;
    int i = idx & 63;
    int rem = idx >> 6;
    int h = rem % NH;
    int t = rem / NH;
    int s = t % SEQ;
    float invf = (float)(1.0 / pow(10000.0, (double)i / 64.0));
    float ang = (float)s * invf;
    double angd = (double)ang;
    float c  = (float)cos(angd);
    float sn = (float)sin(angd);
    size_t base = (size_t)t * DIM + (size_t)h * HDIM;
    float q1 = q[base + i], q2 = q[base + 64 + i];
    q[base + i]      = q1 * c - q2 * sn;
    q[base + 64 + i] = q2 * c + q1 * sn;
    float k1 = k[base + i], k2 = k[base + 64 + i];
    k[base + i]      = k1 * c - k2 * sn;
    k[base + 64 + i] = k2 * c + k1 * sn;
}

// ---------------- Flash attention: Q-tile 128, 8 warps (256 thr), __expf softmax -------
// Warp w owns query rows [w*16, w*16+16) of a 128-row Q block. K-tiles of 32.
__global__ void __launch_bounds__(256)
fa_kernel(const float* __restrict__ q, const float* __restrict__ k,
          const float* __restrict__ v, float* __restrict__ attn) {
    __shared__ uint32_t Ks[32][68];    //  8704 B
    __shared__ uint32_t Vt[128][20];   // 10240 B
    __shared__ uint32_t Ps[8][16][20]; // 10240 B

    int bh = blockIdx.y;
    int b = bh / NH, h = bh % NH;
    int q0 = blockIdx.x * 128;
    int tid = threadIdx.x, w = tid >> 5, lane = tid & 31;   // w in 0..7
    int g = lane >> 2, qd = lane & 3;
    const float alpha = 0.08838834764831845f;

    const float* qb = q + ((size_t)b * SEQ) * DIM + h * HDIM;
    const float* kb_ = k + ((size_t)b * SEQ) * DIM + h * HDIM;
    const float* vb = v + ((size_t)b * SEQ) * DIM + h * HDIM;

    // Q fragments from gmem into registers (alpha pre-folded)
    uint32_t qf[8][4];
    {
        const float* qr0 = qb + (size_t)(q0 + w * 16 + g) * DIM;
        const float* qr1 = qr0 + 8 * DIM;
#pragma unroll
        for (int ks = 0; ks < 8; ks++) {
            int c0 = (ks * 8 + qd) * 2, c1 = (ks * 8 + qd + 4) * 2;
            float2 t00 = *(const float2*)(qr0 + c0);
            float2 t10 = *(const float2*)(qr1 + c0);
            float2 t01 = *(const float2*)(qr0 + c1);
            float2 t11 = *(const float2*)(qr1 + c1);
            qf[ks][0] = pack_bf2(t00.x * alpha, t00.y * alpha);
            qf[ks][1] = pack_bf2(t10.x * alpha, t10.y * alpha);
            qf[ks][2] = pack_bf2(t01.x * alpha, t01.y * alpha);
            qf[ks][3] = pack_bf2(t11.x * alpha, t11.y * alpha);
        }
    }

    float m0 = -1e30f, m1 = -1e30f, l0 = 0.f, l1 = 0.f;
    float out[16][4];
#pragma unroll
    for (int i = 0; i < 16; i++)
#pragma unroll
        for (int r = 0; r < 4; r++) out[i][r] = 0.f;

    int ktiles = q0 / 32 + 4;   // keys up to q0+127

    for (int kt = 0; kt < ktiles; kt++) {
        int k0 = kt * 32;
        __syncthreads();
        for (int i = tid; i < 32 * 32; i += 256) {
            int r = i >> 5, c4 = i & 31;
            float4 tk = *(const float4*)(kb_ + (size_t)(k0 + r) * DIM + c4 * 4);
            Ks[r][c4 * 2]     = pack_bf2(tk.x, tk.y);
            Ks[r][c4 * 2 + 1] = pack_bf2(tk.z, tk.w);
            float4 tv = *(const float4*)(vb + (size_t)(k0 + r) * DIM + c4 * 4);
            uint16_t* vt = (uint16_t*)Vt;
            vt[(c4 * 4 + 0) * 40 + r] = bf16bits(tv.x);
            vt[(c4 * 4 + 1) * 40 + r] = bf16bits(tv.y);
            vt[(c4 * 4 + 2) * 40 + r] = bf16bits(tv.z);
            vt[(c4 * 4 + 3) * 40 + r] = bf16bits(tv.w);
        }
        __syncthreads();

        float sc[4][4];
#pragma unroll
        for (int nt = 0; nt < 4; nt++)
#pragma unroll
            for (int r = 0; r < 4; r++) sc[nt][r] = 0.f;
#pragma unroll
        for (int ks = 0; ks < 8; ks++) {
            int kp = ks * 8;
#pragma unroll
            for (int nt = 0; nt < 4; nt++) {
                uint32_t b0 = Ks[nt * 8 + g][kp + qd];
                uint32_t b1 = Ks[nt * 8 + g][kp + qd + 4];
                mma_bf16(sc[nt], qf[ks][0], qf[ks][1], qf[ks][2], qf[ks][3], b0, b1);
            }
        }

        // causal mask (tiles that can cross any row's diagonal in this block)
        if (k0 + 31 > q0) {
            int rq0 = q0 + w * 16 + g;
            int rq1 = rq0 + 8;
#pragma unroll
            for (int nt = 0; nt < 4; nt++) {
                int kc = k0 + nt * 8 + qd * 2;
                if (kc     > rq0) sc[nt][0] = -1e30f;
                if (kc + 1 > rq0) sc[nt][1] = -1e30f;
                if (kc     > rq1) sc[nt][2] = -1e30f;
                if (kc + 1 > rq1) sc[nt][3] = -1e30f;
            }
        }

        float tm0 = -1e30f, tm1 = -1e30f;
#pragma unroll
        for (int nt = 0; nt < 4; nt++) {
            tm0 = fmaxf(tm0, fmaxf(sc[nt][0], sc[nt][1]));
            tm1 = fmaxf(tm1, fmaxf(sc[nt][2], sc[nt][3]));
        }
        tm0 = fmaxf(tm0, __shfl_xor_sync(0xffffffffu, tm0, 1));
        tm0 = fmaxf(tm0, __shfl_xor_sync(0xffffffffu, tm0, 2));
        tm1 = fmaxf(tm1, __shfl_xor_sync(0xffffffffu, tm1, 1));
        tm1 = fmaxf(tm1, __shfl_xor_sync(0xffffffffu, tm1, 2));

        float mn0 = fmaxf(m0, tm0), mn1 = fmaxf(m1, tm1);
        bool chg = (mn0 != m0) || (mn1 != m1);
        if (__any_sync(0xffffffffu, chg)) {
            float corr0 = __expf(m0 - mn0), corr1 = __expf(m1 - mn1);
            l0 *= corr0; l1 *= corr1;
#pragma unroll
            for (int nt = 0; nt < 16; nt++) {
                out[nt][0] *= corr0; out[nt][1] *= corr0;
                out[nt][2] *= corr1; out[nt][3] *= corr1;
            }
        }
        m0 = mn0; m1 = mn1;

        float s0 = 0.f, s1 = 0.f;
#pragma unroll
        for (int nt = 0; nt < 4; nt++) {
            float p0 = __expf(sc[nt][0] - m0);
            float p1 = __expf(sc[nt][1] - m0);
            float p2 = __expf(sc[nt][2] - m1);
            float p3 = __expf(sc[nt][3] - m1);
            s0 += p0 + p1; s1 += p2 + p3;
            Ps[w][g][nt * 4 + qd]     = pack_bf2(p0, p1);
            Ps[w][g + 8][nt * 4 + qd] = pack_bf2(p2, p3);
        }
        s0 += __shfl_xor_sync(0xffffffffu, s0, 1);
        s0 += __shfl_xor_sync(0xffffffffu, s0, 2);
        s1 += __shfl_xor_sync(0xffffffffu, s1, 1);
        s1 += __shfl_xor_sync(0xffffffffu, s1, 2);
        l0 += s0; l1 += s1;
        __syncwarp();

#pragma unroll
        for (int ks = 0; ks < 2; ks++) {
            int kp = ks * 8;
            uint32_t a0 = Ps[w][g][kp + qd];
            uint32_t a1 = Ps[w][g + 8][kp + qd];
            uint32_t a2 = Ps[w][g][kp + qd + 4];
            uint32_t a3 = Ps[w][g + 8][kp + qd + 4];
#pragma unroll
            for (int nt = 0; nt < 16; nt++) {
                uint32_t b0 = Vt[nt * 8 + g][kp + qd];
                uint32_t b1 = Vt[nt * 8 + g][kp + qd + 4];
                mma_bf16(out[nt], a0, a1, a2, a3, b0, b1);
            }
        }
        __syncwarp();
    }

    float inv0 = 1.f / l0, inv1 = 1.f / l1;
    int r0g = q0 + w * 16 + g;
    float* ob = attn + ((size_t)b * SEQ) * DIM + h * HDIM;
#pragma unroll
    for (int nt = 0; nt < 16; nt++) {
        int c = nt * 8 + qd * 2;
        *(float2*)(ob + (size_t)r0g * DIM + c) =
            make_float2(out[nt][0] * inv0, out[nt][1] * inv0);
        *(float2*)(ob + (size_t)(r0g + 8) * DIM + c) =
            make_float2(out[nt][2] * inv1, out[nt][3] * inv1);
    }
}

// ---------------- MoE gate -------------------------------------------------------------
__global__ void gate_kernel(const float* __restrict__ x, const float* __restrict__ wg,
                            float* __restrict__ comb) {
    int t = blockIdx.x;
    int tid = threadIdx.x;
    __shared__ float red[NE * 128];
    const float* xr = x + (size_t)t * DIM;
    float acc[NE] = {0.f, 0.f, 0.f, 0.f};
    for (int d = tid; d < DIM; d += 128) {
        float xv = xr[d];
#pragma unroll
        for (int e = 0; e < NE; e++) acc[e] += xv * wg[(size_t)d * NE + e];
    }
#pragma unroll
    for (int e = 0; e < NE; e++) red[e * 128 + tid] = acc[e];
    __syncthreads();
    for (int o = 64; o > 0; o >>= 1) {
        if (tid < o) {
#pragma unroll
            for (int e = 0; e < NE; e++) red[e * 128 + tid] += red[e * 128 + tid + o];
        }
        __syncthreads();
    }
    if (tid == 0) {
        float l[NE];
#pragma unroll
        for (int e = 0; e < NE; e++) l[e] = red[e * 128];
        float mx = fmaxf(fmaxf(l[0], l[1]), fmaxf(l[2], l[3]));
        float ex[NE], s = 0.f;
#pragma unroll
        for (int e = 0; e < NE; e++) { ex[e] = expf(l[e] - mx); s += ex[e]; }
        float p[NE];
#pragma unroll
        for (int e = 0; e < NE; e++) p[e] = ex[e] / s;
        int i0 = 0;
#pragma unroll
        for (int e = 1; e < NE; e++) if (p[e] > p[i0]) i0 = e;
        int i1 = (i0 == 0) ? 1 : 0;
#pragma unroll
        for (int e = 0; e < NE; e++) if (e != i0 && p[e] > p[i1]) i1 = e;
        float e1 = expf(p[i1] - p[i0]);
        float invs = 1.f / (1.f + e1);
        float c[NE] = {0.f, 0.f, 0.f, 0.f};
        c[i0] = invs;
        c[i1] = e1 * invs;
#pragma unroll
        for (int e = 0; e < NE; e++) comb[(size_t)t * NE + e] = c[e];
    }
}

// ---------------- Routing --------------------------------------------------------------
__global__ void zero_cnt_kernel(int* cnt) {
    if (threadIdx.x < NE) cnt[threadIdx.x] = 0;
}
__global__ void route_kernel(const float* __restrict__ comb, int* __restrict__ cnt,
                             int* __restrict__ idx) {
    int t = blockIdx.x * blockDim.x + threadIdx.x;
    if (t >= NTOK) return;
#pragma unroll
    for (int e = 0; e < NE; e++) {
        if (comb[(size_t)t * NE + e] > 0.f) {
            int pos = atomicAdd(&cnt[e], 1);
            idx[e * NTOK + pos] = t;
        }
    }
}

// ---------------- host orchestration ---------------------------------------------------
extern "C" void kernel_launch(void* const* d_in, const int* in_sizes, int n_in,
                              void* d_out, int out_size) {
    (void)in_sizes; (void)n_in; (void)out_size;
    const float* hs   = (const float*)d_in[0];
    const float* wq   = (const float*)d_in[1];
    const float* bq   = (const float*)d_in[2];
    const float* wk   = (const float*)d_in[3];
    const float* bk   = (const float*)d_in[4];
    const float* wv   = (const float*)d_in[5];
    const float* bv   = (const float*)d_in[6];
    const float* wo   = (const float*)d_in[7];
    const float* bo   = (const float*)d_in[8];
    const float* ln1w = (const float*)d_in[9];
    const float* ln1b = (const float*)d_in[10];
    const float* ln2w = (const float*)d_in[11];
    const float* ln2b = (const float*)d_in[12];
    const float* wg   = (const float*)d_in[13];
    const float* we1  = (const float*)d_in[14];
    const float* be1  = (const float*)d_in[15];
    const float* we2  = (const float*)d_in[16];
    const float* be2  = (const float*)d_in[17];
    float* out = (float*)d_out;

    float *p_ln, *p_q, *p_k, *p_v, *p_attn, *p_comb;
    int *p_cnt, *p_idx;
    __half* p_wbf;
    cudaGetSymbolAddress((void**)&p_ln, g_ln);
    cudaGetSymbolAddress((void**)&p_q, g_q);
    cudaGetSymbolAddress((void**)&p_k, g_k);
    cudaGetSymbolAddress((void**)&p_v, g_v);
    cudaGetSymbolAddress((void**)&p_attn, g_attn);
    cudaGetSymbolAddress((void**)&p_comb, g_comb);
    cudaGetSymbolAddress((void**)&p_cnt, g_cnt);
    cudaGetSymbolAddress((void**)&p_idx, g_idx);
    cudaGetSymbolAddress((void**)&p_wbf, g_wbf);

    // 0. Weight prep
    dim3 gW(DIM / 32, DIM / 32, 12);
    wprep_kernel<<<gW, dim3(32, 8)>>>(wq, wk, wv, wo, we1, we2, p_wbf);

    // 1. LN1
    ln_kernel<<<NTOK, 256>>>(hs, ln1w, ln1b, p_ln);

    // 2. QKV projections
    dim3 gBig(DIM / 128, NTOK / 128);
    size_t WSZ = (size_t)DIM * DIM;
    gemm_f16<<<gBig, 128>>>(p_ln, DIM, p_wbf + 0 * WSZ, DIM, bq, p_q, DIM,
                            nullptr, 0, nullptr, 0, NTOK, DIM, DIM, 0, 0,
                            nullptr, nullptr, nullptr);
    gemm_f16<<<gBig, 128>>>(p_ln, DIM, p_wbf + 1 * WSZ, DIM, bk, p_k, DIM,
                            nullptr, 0, nullptr, 0, NTOK, DIM, DIM, 0, 0,
                            nullptr, nullptr, nullptr);
    gemm_f16<<<gBig, 128>>>(p_ln, DIM, p_wbf + 2 * WSZ, DIM, bv, p_v, DIM,
                            nullptr, 0, nullptr, 0, NTOK, DIM, DIM, 0, 0,
                            nullptr, nullptr, nullptr);

    // 3. RoPE
    int nrope = NTOK * NH * 64;
    rope_kernel<<<(nrope + 255) / 256, 256>>>(p_q, p_k);

    // 4. Flash attention (Q-tile 128, 8 warps)
    dim3 gFA(SEQ / 128, BATCH * NH);
    fa_kernel<<<gFA, 256>>>(p_q, p_k, p_v, p_attn);

    // 5. O-proj + bias + residual -> out (= h)
    gemm_f16<<<gBig, 128>>>(p_attn, DIM, p_wbf + 3 * WSZ, DIM, bo, out, DIM,
                            hs, DIM, nullptr, 0, NTOK, DIM, DIM, 0, 0,
                            nullptr, nullptr, nullptr);

    // 6. LN2
    ln_kernel<<<NTOK, 256>>>(out, ln2w, ln2b, p_ln);

    // 7. Gate + routing
    gate_kernel<<<NTOK, 128>>>(p_ln, wg, p_comb);
    zero_cnt_kernel<<<1, 32>>>(p_cnt);
    route_kernel<<<NTOK / 256, 256>>>(p_comb, p_cnt, p_idx);

    // 8. Sparse experts
    for (int e = 0; e < NE; e++) {
        const float* b1 = be1 + (size_t)e * IDIM;
        const float* b2 = be2 + (size_t)e * DIM;
        const int* idx_e = p_idx + e * NTOK;
        const int* cnt_e = p_cnt + e;
        gemm_f16<<<gBig, 128>>>(p_ln, DIM, p_wbf + (4 + e) * WSZ, DIM, b1, p_q, IDIM,
                                nullptr, 0, nullptr, 0, NTOK, IDIM, DIM, 1, 0,
                                idx_e, nullptr, cnt_e);
        gemm_f16<<<gBig, 128>>>(p_q, IDIM, p_wbf + (8 + e) * WSZ, IDIM, b2, out, DIM,
                                nullptr, 0, p_comb + e, NE, NTOK, DIM, IDIM, 0, 1,
                                nullptr, idx_e, cnt_e);
    }
}

// round 13
// speedup vs baseline: 1.9375x; 1.4335x over previous
#include <cuda_runtime.h>
#include <cuda_bf16.h>
#include <cuda_fp16.h>
#include <math.h>
#include <stdint.h>

#define BATCH 2
#define SEQ   2048
#define DIM   2048
#define NH    16
#define HDIM  128
#define NE    4
#define IDIM  2048
#define NTOK  (BATCH*SEQ)   // 4096

// ---------------- scratch (static device globals) ----
__device__ float g_ln   [(size_t)NTOK*DIM];
__device__ float g_q    [(size_t)NTOK*DIM];   // also reused as MoE hmid (compacted)
__device__ float g_k    [(size_t)NTOK*DIM];
__device__ float g_v    [(size_t)NTOK*DIM];
__device__ float g_attn [(size_t)NTOK*DIM];
__device__ float g_comb [(size_t)NTOK*NE];
__device__ int   g_cnt  [NE];
__device__ int   g_idx  [NE*NTOK];
__device__ __half g_wbf [(size_t)12*DIM*DIM];   // 12 transposed half weight mats [N][K]
__device__ float2 g_rope[(size_t)SEQ*64];       // (cos, sin) per (position, freq)

__device__ __forceinline__ void mma_f16(float d[4], uint32_t a0, uint32_t a1,
                                        uint32_t a2, uint32_t a3,
                                        uint32_t b0, uint32_t b1) {
    asm volatile(
        "mma.sync.aligned.m16n8k16.row.col.f32.f16.f16.f32 "
        "{%0,%1,%2,%3}, {%4,%5,%6,%7}, {%8,%9}, {%0,%1,%2,%3};"
        : "+f"(d[0]), "+f"(d[1]), "+f"(d[2]), "+f"(d[3])
        : "r"(a0), "r"(a1), "r"(a2), "r"(a3), "r"(b0), "r"(b1));
}

__device__ __forceinline__ void mma_bf16(float d[4], uint32_t a0, uint32_t a1,
                                         uint32_t a2, uint32_t a3,
                                         uint32_t b0, uint32_t b1) {
    asm volatile(
        "mma.sync.aligned.m16n8k16.row.col.f32.bf16.bf16.f32 "
        "{%0,%1,%2,%3}, {%4,%5,%6,%7}, {%8,%9}, {%0,%1,%2,%3};"
        : "+f"(d[0]), "+f"(d[1]), "+f"(d[2]), "+f"(d[3])
        : "r"(a0), "r"(a1), "r"(a2), "r"(a3), "r"(b0), "r"(b1));
}

__device__ __forceinline__ uint32_t pack_bf2(float lo, float hi) {
    __nv_bfloat162 t = __floats2bfloat162_rn(lo, hi);
    return *(uint32_t*)&t;
}
__device__ __forceinline__ uint32_t pack_h2(float lo, float hi) {
    __half2 t = __floats2half2_rn(lo, hi);
    return *(uint32_t*)&t;
}
__device__ __forceinline__ uint16_t bf16bits(float x) {
    __nv_bfloat16 t = __float2bfloat16_rn(x);
    return *(uint16_t*)&t;
}

// ---------------- Weight prep: transpose+convert 12 matrices to half [N][K] ------------
__global__ void wprep_kernel(const float* __restrict__ wq, const float* __restrict__ wk,
                             const float* __restrict__ wv, const float* __restrict__ wo,
                             const float* __restrict__ we1, const float* __restrict__ we2,
                             __half* __restrict__ wbf) {
    int z = blockIdx.z;
    const float* src;
    if (z == 0) src = wq;
    else if (z == 1) src = wk;
    else if (z == 2) src = wv;
    else if (z == 3) src = wo;
    else if (z < 8) src = we1 + (size_t)(z - 4) * DIM * IDIM;
    else src = we2 + (size_t)(z - 8) * IDIM * DIM;
    __half* dst = wbf + (size_t)z * DIM * DIM;
    __shared__ float tile[32][33];
    int k0 = blockIdx.y * 32, n0 = blockIdx.x * 32;
    int tx = threadIdx.x, ty = threadIdx.y;   // 32 x 8
#pragma unroll
    for (int r = ty; r < 32; r += 8)
        tile[r][tx] = src[(size_t)(k0 + r) * DIM + n0 + tx];
    __syncthreads();
#pragma unroll
    for (int r = ty; r < 32; r += 8)
        dst[(size_t)(n0 + r) * DIM + k0 + tx] = __float2half_rn(tile[tx][r]);
}

// ---------------- RoPE table: same double-trig math, computed once per (s, i) ----------
__global__ void rope_table_kernel(float2* __restrict__ tab) {
    int idx = blockIdx.x * blockDim.x + threadIdx.x;   // SEQ*64
    if (idx >= SEQ * 64) return;
    int i = idx & 63;
    int s = idx >> 6;
    float invf = (float)(1.0 / pow(10000.0, (double)i / 64.0));
    float ang = (float)s * invf;
    double angd = (double)ang;
    tab[idx] = make_float2((float)cos(angd), (float)sin(angd));
}

// ---------------- RoPE apply: pure fp32 table lookup -----------------------------------
__global__ void rope_kernel(float* __restrict__ q, float* __restrict__ k,
                            const float2* __restrict__ tab) {
    int idx = blockIdx.x * blockDim.x + threadIdx.x;   // over NTOK*NH*64
    if (idx >= NTOK * NH * 64) return;
    int i = idx & 63;
    int rem = idx >> 6;
    int h = rem % NH;
    int t = rem / NH;
    int s = t % SEQ;
    float2 cs = tab[s * 64 + i];
    float c = cs.x, sn = cs.y;
    size_t base = (size_t)t * DIM + (size_t)h * HDIM;
    float q1 = q[base + i], q2 = q[base + 64 + i];
    q[base + i]      = q1 * c - q2 * sn;
    q[base + 64 + i] = q2 * c + q1 * sn;
    float k1 = k[base + i], k2 = k[base + 64 + i];
    k[base + i]      = k1 * c - k2 * sn;
    k[base + 64 + i] = k2 * c + k1 * sn;
}

// ---------------- LayerNorm ----------------
__global__ void ln_kernel(const float* __restrict__ x, const float* __restrict__ w,
                          const float* __restrict__ b, float* __restrict__ y) {
    int row = blockIdx.x;
    const float* xr = x + (size_t)row * DIM;
    float* yr = y + (size_t)row * DIM;
    __shared__ float red[256];
    int tid = threadIdx.x;
    float s = 0.f;
    for (int i = tid; i < DIM; i += 256) s += xr[i];
    red[tid] = s; __syncthreads();
    for (int o = 128; o > 0; o >>= 1) { if (tid < o) red[tid] += red[tid + o]; __syncthreads(); }
    float mu = red[0] * (1.f / DIM);
    __syncthreads();
    float v = 0.f;
    for (int i = tid; i < DIM; i += 256) { float d = xr[i] - mu; v += d * d; }
    red[tid] = v; __syncthreads();
    for (int o = 128; o > 0; o >>= 1) { if (tid < o) red[tid] += red[tid + o]; __syncthreads(); }
    float inv = rsqrtf(red[0] * (1.f / DIM) + 1e-5f);
    for (int i = tid; i < DIM; i += 256) yr[i] = (xr[i] - mu) * inv * w[i] + b[i];
}

// ---------------- FP16 GEMM: 128 thr, 4 warps (2x2), 64x64 warp tiles, ktile 32 --------
__device__ __forceinline__ void epi(float v, int gm, int gn,
                                    const float* bias, int act,
                                    const float* resid, int ldr,
                                    const float* rowscale, int rss,
                                    float* C, int ldc, int accum) {
    if (bias) v += bias[gn];
    if (act) v = 0.5f * v * (1.f + erff(v * 0.70710678118654752f));
    if (resid) v += resid[(size_t)gm * ldr + gn];
    if (rowscale) v *= rowscale[(size_t)gm * rss];
    size_t o = (size_t)gm * ldc + gn;
    if (accum) C[o] += v; else C[o] = v;
}

__global__ void __launch_bounds__(128)
gemm_f16(const float* __restrict__ A, int lda,
         const __half* __restrict__ Bt, int ldb,           // Bt[N][K], ldb = K
         const float* __restrict__ bias,
         float* __restrict__ C, int ldc,
         const float* __restrict__ resid, int ldr,
         const float* __restrict__ rowscale, int rss,
         int M, int N, int K, int act, int accum,
         const int* __restrict__ amap, const int* __restrict__ cmap,
         const int* __restrict__ mcount) {
    int M_eff = mcount ? *mcount : M;
    int row0 = blockIdx.y * 128, col0 = blockIdx.x * 128;
    if (row0 >= M_eff) return;

    __shared__ uint32_t As[128][20];
    __shared__ uint32_t Bs[128][20];
    int tid = threadIdx.x;
    int w = tid >> 5, lane = tid & 31;
    int wm = w >> 1, wn = w & 1;
    int m_w = wm * 64, n_w = wn * 64;
    int g = lane >> 2, q = lane & 3;

    float acc[4][8][4];
#pragma unroll
    for (int i = 0; i < 4; i++)
#pragma unroll
        for (int j = 0; j < 8; j++)
#pragma unroll
            for (int r = 0; r < 4; r++) acc[i][j][r] = 0.f;

    int mbase = tid >> 3, ac = tid & 7;
    const float* Ap[8];
#pragma unroll
    for (int j = 0; j < 8; j++) {
        int gm = row0 + mbase + 16 * j;
        int cl = gm < M_eff ? gm : M_eff - 1;
        int ar = amap ? amap[cl] : cl;
        Ap[j] = A + (size_t)ar * lda + ac * 4;
    }
    int nbase = tid >> 2, bc = tid & 3;
    const __half* Bp[4];
#pragma unroll
    for (int j = 0; j < 4; j++)
        Bp[j] = Bt + (size_t)(col0 + nbase + 32 * j) * ldb + bc * 8;

    float4 pa[8];
    uint4 pb[4];
#pragma unroll
    for (int j = 0; j < 8; j++) pa[j] = *(const float4*)Ap[j];
#pragma unroll
    for (int j = 0; j < 4; j++) pb[j] = *(const uint4*)Bp[j];

    int nk = K / 32;
    for (int t = 0; t < nk; t++) {
#pragma unroll
        for (int j = 0; j < 8; j++) {
            int m = mbase + 16 * j;
            As[m][ac * 2]     = pack_h2(pa[j].x, pa[j].y);
            As[m][ac * 2 + 1] = pack_h2(pa[j].z, pa[j].w);
        }
#pragma unroll
        for (int j = 0; j < 4; j++)
            *(uint4*)&Bs[nbase + 32 * j][bc * 4] = pb[j];
        __syncthreads();

        if (t + 1 < nk) {
            int k0 = (t + 1) * 32;
#pragma unroll
            for (int j = 0; j < 8; j++) pa[j] = *(const float4*)(Ap[j] + k0);
#pragma unroll
            for (int j = 0; j < 4; j++) pb[j] = *(const uint4*)(Bp[j] + k0);
        }

#pragma unroll
        for (int ks = 0; ks < 2; ks++) {
            int kp = ks * 8;
            uint32_t af[4][4], bf[8][2];
#pragma unroll
            for (int i = 0; i < 4; i++) {
                int r = m_w + i * 16 + g;
                af[i][0] = As[r][kp + q];
                af[i][1] = As[r + 8][kp + q];
                af[i][2] = As[r][kp + q + 4];
                af[i][3] = As[r + 8][kp + q + 4];
            }
#pragma unroll
            for (int j = 0; j < 8; j++) {
                int c = n_w + j * 8 + g;
                bf[j][0] = Bs[c][kp + q];
                bf[j][1] = Bs[c][kp + q + 4];
            }
#pragma unroll
            for (int i = 0; i < 4; i++)
#pragma unroll
                for (int j = 0; j < 8; j++)
                    mma_f16(acc[i][j], af[i][0], af[i][1], af[i][2], af[i][3],
                            bf[j][0], bf[j][1]);
        }
        __syncthreads();
    }

#pragma unroll
    for (int i = 0; i < 4; i++) {
        int gm = row0 + m_w + i * 16 + g;
        if (gm < M_eff) {
            int cr = cmap ? cmap[gm] : gm;
#pragma unroll
            for (int j = 0; j < 8; j++) {
                int cb = col0 + n_w + j * 8 + q * 2;
                epi(acc[i][j][0], cr, cb,     bias, act, resid, ldr, rowscale, rss, C, ldc, accum);
                epi(acc[i][j][1], cr, cb + 1, bias, act, resid, ldr, rowscale, rss, C, ldc, accum);
            }
        }
        int gm2 = gm + 8;
        if (gm2 < M_eff) {
            int cr2 = cmap ? cmap[gm2] : gm2;
#pragma unroll
            for (int j = 0; j < 8; j++) {
                int cb = col0 + n_w + j * 8 + q * 2;
                epi(acc[i][j][2], cr2, cb,     bias, act, resid, ldr, rowscale, rss, C, ldc, accum);
                epi(acc[i][j][3], cr2, cb + 1, bias, act, resid, ldr, rowscale, rss, C, ldc, accum);
            }
        }
    }
}

// ---------------- Flash attention (R11, proven): Q-tile 128, 8 warps, __expf -----------
__global__ void __launch_bounds__(256)
fa_kernel(const float* __restrict__ q, const float* __restrict__ k,
          const float* __restrict__ v, float* __restrict__ attn) {
    __shared__ uint32_t Ks[32][68];
    __shared__ uint32_t Vt[128][20];
    __shared__ uint32_t Ps[8][16][20];

    int bh = blockIdx.y;
    int b = bh / NH, h = bh % NH;
    int q0 = blockIdx.x * 128;
    int tid = threadIdx.x, w = tid >> 5, lane = tid & 31;
    int g = lane >> 2, qd = lane & 3;
    const float alpha = 0.08838834764831845f;

    const float* qb = q + ((size_t)b * SEQ) * DIM + h * HDIM;
    const float* kb_ = k + ((size_t)b * SEQ) * DIM + h * HDIM;
    const float* vb = v + ((size_t)b * SEQ) * DIM + h * HDIM;

    uint32_t qf[8][4];
    {
        const float* qr0 = qb + (size_t)(q0 + w * 16 + g) * DIM;
        const float* qr1 = qr0 + 8 * DIM;
#pragma unroll
        for (int ks = 0; ks < 8; ks++) {
            int c0 = (ks * 8 + qd) * 2, c1 = (ks * 8 + qd + 4) * 2;
            float2 t00 = *(const float2*)(qr0 + c0);
            float2 t10 = *(const float2*)(qr1 + c0);
            float2 t01 = *(const float2*)(qr0 + c1);
            float2 t11 = *(const float2*)(qr1 + c1);
            qf[ks][0] = pack_bf2(t00.x * alpha, t00.y * alpha);
            qf[ks][1] = pack_bf2(t10.x * alpha, t10.y * alpha);
            qf[ks][2] = pack_bf2(t01.x * alpha, t01.y * alpha);
            qf[ks][3] = pack_bf2(t11.x * alpha, t11.y * alpha);
        }
    }

    float m0 = -1e30f, m1 = -1e30f, l0 = 0.f, l1 = 0.f;
    float out[16][4];
#pragma unroll
    for (int i = 0; i < 16; i++)
#pragma unroll
        for (int r = 0; r < 4; r++) out[i][r] = 0.f;

    int ktiles = q0 / 32 + 4;

    for (int kt = 0; kt < ktiles; kt++) {
        int k0 = kt * 32;
        __syncthreads();
        for (int i = tid; i < 32 * 32; i += 256) {
            int r = i >> 5, c4 = i & 31;
            float4 tk = *(const float4*)(kb_ + (size_t)(k0 + r) * DIM + c4 * 4);
            Ks[r][c4 * 2]     = pack_bf2(tk.x, tk.y);
            Ks[r][c4 * 2 + 1] = pack_bf2(tk.z, tk.w);
            float4 tv = *(const float4*)(vb + (size_t)(k0 + r) * DIM + c4 * 4);
            uint16_t* vt = (uint16_t*)Vt;
            vt[(c4 * 4 + 0) * 40 + r] = bf16bits(tv.x);
            vt[(c4 * 4 + 1) * 40 + r] = bf16bits(tv.y);
            vt[(c4 * 4 + 2) * 40 + r] = bf16bits(tv.z);
            vt[(c4 * 4 + 3) * 40 + r] = bf16bits(tv.w);
        }
        __syncthreads();

        float sc[4][4];
#pragma unroll
        for (int nt = 0; nt < 4; nt++)
#pragma unroll
            for (int r = 0; r < 4; r++) sc[nt][r] = 0.f;
#pragma unroll
        for (int ks = 0; ks < 8; ks++) {
            int kp = ks * 8;
#pragma unroll
            for (int nt = 0; nt < 4; nt++) {
                uint32_t b0 = Ks[nt * 8 + g][kp + qd];
                uint32_t b1 = Ks[nt * 8 + g][kp + qd + 4];
                mma_bf16(sc[nt], qf[ks][0], qf[ks][1], qf[ks][2], qf[ks][3], b0, b1);
            }
        }

        if (k0 + 31 > q0) {
            int rq0 = q0 + w * 16 + g;
            int rq1 = rq0 + 8;
#pragma unroll
            for (int nt = 0; nt < 4; nt++) {
                int kc = k0 + nt * 8 + qd * 2;
                if (kc     > rq0) sc[nt][0] = -1e30f;
                if (kc + 1 > rq0) sc[nt][1] = -1e30f;
                if (kc     > rq1) sc[nt][2] = -1e30f;
                if (kc + 1 > rq1) sc[nt][3] = -1e30f;
            }
        }

        float tm0 = -1e30f, tm1 = -1e30f;
#pragma unroll
        for (int nt = 0; nt < 4; nt++) {
            tm0 = fmaxf(tm0, fmaxf(sc[nt][0], sc[nt][1]));
            tm1 = fmaxf(tm1, fmaxf(sc[nt][2], sc[nt][3]));
        }
        tm0 = fmaxf(tm0, __shfl_xor_sync(0xffffffffu, tm0, 1));
        tm0 = fmaxf(tm0, __shfl_xor_sync(0xffffffffu, tm0, 2));
        tm1 = fmaxf(tm1, __shfl_xor_sync(0xffffffffu, tm1, 1));
        tm1 = fmaxf(tm1, __shfl_xor_sync(0xffffffffu, tm1, 2));

        float mn0 = fmaxf(m0, tm0), mn1 = fmaxf(m1, tm1);
        bool chg = (mn0 != m0) || (mn1 != m1);
        if (__any_sync(0xffffffffu, chg)) {
            float corr0 = __expf(m0 - mn0), corr1 = __expf(m1 - mn1);
            l0 *= corr0; l1 *= corr1;
#pragma unroll
            for (int nt = 0; nt < 16; nt++) {
                out[nt][0] *= corr0; out[nt][1] *= corr0;
                out[nt][2] *= corr1; out[nt][3] *= corr1;
            }
        }
        m0 = mn0; m1 = mn1;

        float s0 = 0.f, s1 = 0.f;
#pragma unroll
        for (int nt = 0; nt < 4; nt++) {
            float p0 = __expf(sc[nt][0] - m0);
            float p1 = __expf(sc[nt][1] - m0);
            float p2 = __expf(sc[nt][2] - m1);
            float p3 = __expf(sc[nt][3] - m1);
            s0 += p0 + p1; s1 += p2 + p3;
            Ps[w][g][nt * 4 + qd]     = pack_bf2(p0, p1);
            Ps[w][g + 8][nt * 4 + qd] = pack_bf2(p2, p3);
        }
        s0 += __shfl_xor_sync(0xffffffffu, s0, 1);
        s0 += __shfl_xor_sync(0xffffffffu, s0, 2);
        s1 += __shfl_xor_sync(0xffffffffu, s1, 1);
        s1 += __shfl_xor_sync(0xffffffffu, s1, 2);
        l0 += s0; l1 += s1;
        __syncwarp();

#pragma unroll
        for (int ks = 0; ks < 2; ks++) {
            int kp = ks * 8;
            uint32_t a0 = Ps[w][g][kp + qd];
            uint32_t a1 = Ps[w][g + 8][kp + qd];
            uint32_t a2 = Ps[w][g][kp + qd + 4];
            uint32_t a3 = Ps[w][g + 8][kp + qd + 4];
#pragma unroll
            for (int nt = 0; nt < 16; nt++) {
                uint32_t b0 = Vt[nt * 8 + g][kp + qd];
                uint32_t b1 = Vt[nt * 8 + g][kp + qd + 4];
                mma_bf16(out[nt], a0, a1, a2, a3, b0, b1);
            }
        }
        __syncwarp();
    }

    float inv0 = 1.f / l0, inv1 = 1.f / l1;
    int r0g = q0 + w * 16 + g;
    float* ob = attn + ((size_t)b * SEQ) * DIM + h * HDIM;
#pragma unroll
    for (int nt = 0; nt < 16; nt++) {
        int c = nt * 8 + qd * 2;
        *(float2*)(ob + (size_t)r0g * DIM + c) =
            make_float2(out[nt][0] * inv0, out[nt][1] * inv0);
        *(float2*)(ob + (size_t)(r0g + 8) * DIM + c) =
            make_float2(out[nt][2] * inv1, out[nt][3] * inv1);
    }
}

// ---------------- MoE gate -------------------------------------------------------------
__global__ void gate_kernel(const float* __restrict__ x, const float* __restrict__ wg,
                            float* __restrict__ comb) {
    int t = blockIdx.x;
    int tid = threadIdx.x;
    __shared__ float red[NE * 128];
    const float* xr = x + (size_t)t * DIM;
    float acc[NE] = {0.f, 0.f, 0.f, 0.f};
    for (int d = tid; d < DIM; d += 128) {
        float xv = xr[d];
#pragma unroll
        for (int e = 0; e < NE; e++) acc[e] += xv * wg[(size_t)d * NE + e];
    }
#pragma unroll
    for (int e = 0; e < NE; e++) red[e * 128 + tid] = acc[e];
    __syncthreads();
    for (int o = 64; o > 0; o >>= 1) {
        if (tid < o) {
#pragma unroll
            for (int e = 0; e < NE; e++) red[e * 128 + tid] += red[e * 128 + tid + o];
        }
        __syncthreads();
    }
    if (tid == 0) {
        float l[NE];
#pragma unroll
        for (int e = 0; e < NE; e++) l[e] = red[e * 128];
        float mx = fmaxf(fmaxf(l[0], l[1]), fmaxf(l[2], l[3]));
        float ex[NE], s = 0.f;
#pragma unroll
        for (int e = 0; e < NE; e++) { ex[e] = expf(l[e] - mx); s += ex[e]; }
        float p[NE];
#pragma unroll
        for (int e = 0; e < NE; e++) p[e] = ex[e] / s;
        int i0 = 0;
#pragma unroll
        for (int e = 1; e < NE; e++) if (p[e] > p[i0]) i0 = e;
        int i1 = (i0 == 0) ? 1 : 0;
#pragma unroll
        for (int e = 0; e < NE; e++) if (e != i0 && p[e] > p[i1]) i1 = e;
        float e1 = expf(p[i1] - p[i0]);
        float invs = 1.f / (1.f + e1);
        float c[NE] = {0.f, 0.f, 0.f, 0.f};
        c[i0] = invs;
        c[i1] = e1 * invs;
#pragma unroll
        for (int e = 0; e < NE; e++) comb[(size_t)t * NE + e] = c[e];
    }
}

// ---------------- Routing --------------------------------------------------------------
__global__ void zero_cnt_kernel(int* cnt) {
    if (threadIdx.x < NE) cnt[threadIdx.x] = 0;
}
__global__ void route_kernel(const float* __restrict__ comb, int* __restrict__ cnt,
                             int* __restrict__ idx) {
    int t = blockIdx.x * blockDim.x + threadIdx.x;
    if (t >= NTOK) return;
#pragma unroll
    for (int e = 0; e < NE; e++) {
        if (comb[(size_t)t * NE + e] > 0.f) {
            int pos = atomicAdd(&cnt[e], 1);
            idx[e * NTOK + pos] = t;
        }
    }
}

// ---------------- host orchestration ---------------------------------------------------
extern "C" void kernel_launch(void* const* d_in, const int* in_sizes, int n_in,
                              void* d_out, int out_size) {
    (void)in_sizes; (void)n_in; (void)out_size;
    const float* hs   = (const float*)d_in[0];
    const float* wq   = (const float*)d_in[1];
    const float* bq   = (const float*)d_in[2];
    const float* wk   = (const float*)d_in[3];
    const float* bk   = (const float*)d_in[4];
    const float* wv   = (const float*)d_in[5];
    const float* bv   = (const float*)d_in[6];
    const float* wo   = (const float*)d_in[7];
    const float* bo   = (const float*)d_in[8];
    const float* ln1w = (const float*)d_in[9];
    const float* ln1b = (const float*)d_in[10];
    const float* ln2w = (const float*)d_in[11];
    const float* ln2b = (const float*)d_in[12];
    const float* wg   = (const float*)d_in[13];
    const float* we1  = (const float*)d_in[14];
    const float* be1  = (const float*)d_in[15];
    const float* we2  = (const float*)d_in[16];
    const float* be2  = (const float*)d_in[17];
    float* out = (float*)d_out;

    float *p_ln, *p_q, *p_k, *p_v, *p_attn, *p_comb;
    int *p_cnt, *p_idx;
    __half* p_wbf;
    float2* p_rope;
    cudaGetSymbolAddress((void**)&p_ln, g_ln);
    cudaGetSymbolAddress((void**)&p_q, g_q);
    cudaGetSymbolAddress((void**)&p_k, g_k);
    cudaGetSymbolAddress((void**)&p_v, g_v);
    cudaGetSymbolAddress((void**)&p_attn, g_attn);
    cudaGetSymbolAddress((void**)&p_comb, g_comb);
    cudaGetSymbolAddress((void**)&p_cnt, g_cnt);
    cudaGetSymbolAddress((void**)&p_idx, g_idx);
    cudaGetSymbolAddress((void**)&p_wbf, g_wbf);
    cudaGetSymbolAddress((void**)&p_rope, g_rope);

    // 0. Weight prep + RoPE table (independent of activations)
    dim3 gW(DIM / 32, DIM / 32, 12);
    wprep_kernel<<<gW, dim3(32, 8)>>>(wq, wk, wv, wo, we1, we2, p_wbf);
    rope_table_kernel<<<(SEQ * 64) / 256, 256>>>(p_rope);

    // 1. LN1
    ln_kernel<<<NTOK, 256>>>(hs, ln1w, ln1b, p_ln);

    // 2. QKV projections
    dim3 gBig(DIM / 128, NTOK / 128);
    size_t WSZ = (size_t)DIM * DIM;
    gemm_f16<<<gBig, 128>>>(p_ln, DIM, p_wbf + 0 * WSZ, DIM, bq, p_q, DIM,
                            nullptr, 0, nullptr, 0, NTOK, DIM, DIM, 0, 0,
                            nullptr, nullptr, nullptr);
    gemm_f16<<<gBig, 128>>>(p_ln, DIM, p_wbf + 1 * WSZ, DIM, bk, p_k, DIM,
                            nullptr, 0, nullptr, 0, NTOK, DIM, DIM, 0, 0,
                            nullptr, nullptr, nullptr);
    gemm_f16<<<gBig, 128>>>(p_ln, DIM, p_wbf + 2 * WSZ, DIM, bv, p_v, DIM,
                            nullptr, 0, nullptr, 0, NTOK, DIM, DIM, 0, 0,
                            nullptr, nullptr, nullptr);

    // 3. RoPE (table lookup)
    int nrope = NTOK * NH * 64;
    rope_kernel<<<(nrope + 255) / 256, 256>>>(p_q, p_k, p_rope);

    // 4. Flash attention
    dim3 gFA(SEQ / 128, BATCH * NH);
    fa_kernel<<<gFA, 256>>>(p_q, p_k, p_v, p_attn);

    // 5. O-proj + bias + residual -> out (= h)
    gemm_f16<<<gBig, 128>>>(p_attn, DIM, p_wbf + 3 * WSZ, DIM, bo, out, DIM,
                            hs, DIM, nullptr, 0, NTOK, DIM, DIM, 0, 0,
                            nullptr, nullptr, nullptr);

    // 6. LN2
    ln_kernel<<<NTOK, 256>>>(out, ln2w, ln2b, p_ln);

    // 7. Gate + routing
    gate_kernel<<<NTOK, 128>>>(p_ln, wg, p_comb);
    zero_cnt_kernel<<<1, 32>>>(p_cnt);
    route_kernel<<<NTOK / 256, 256>>>(p_comb, p_cnt, p_idx);

    // 8. Sparse experts
    for (int e = 0; e < NE; e++) {
        const float* b1 = be1 + (size_t)e * IDIM;
        const float* b2 = be2 + (size_t)e * DIM;
        const int* idx_e = p_idx + e * NTOK;
        const int* cnt_e = p_cnt + e;
        gemm_f16<<<gBig, 128>>>(p_ln, DIM, p_wbf + (4 + e) * WSZ, DIM, b1, p_q, IDIM,
                                nullptr, 0, nullptr, 0, NTOK, IDIM, DIM, 1, 0,
                                idx_e, nullptr, cnt_e);
        gemm_f16<<<gBig, 128>>>(p_q, IDIM, p_wbf + (8 + e) * WSZ, IDIM, b2, out, DIM,
                                nullptr, 0, p_comb + e, NE, NTOK, DIM, IDIM, 0, 1,
                                nullptr, idx_e, cnt_e);
    }
}

// round 14
// speedup vs baseline: 1.9511x; 1.0070x over previous
#include <cuda_runtime.h>
#include <cuda_bf16.h>
#include <cuda_fp16.h>
#include <math.h>
#include <stdint.h>

#define BATCH 2
#define SEQ   2048
#define DIM   2048
#define NH    16
#define HDIM  128
#define NE    4
#define IDIM  2048
#define NTOK  (BATCH*SEQ)   // 4096

// ---------------- scratch (static device globals) ----
__device__ float  g_ln   [(size_t)NTOK*DIM];
__device__ __half g_lnh  [(size_t)NTOK*DIM];    // half copy of LN output (GEMM A)
__device__ float  g_q    [(size_t)NTOK*DIM];
__device__ float  g_k    [(size_t)NTOK*DIM];
__device__ float  g_v    [(size_t)NTOK*DIM];
__device__ __half g_attnh[(size_t)NTOK*DIM];    // attention output (half, O-proj A)
__device__ __half g_hmidh[(size_t)NTOK*IDIM];   // expert hidden (half, GEMM2 A)
__device__ float  g_comb [(size_t)NTOK*NE];
__device__ int    g_cnt  [NE];
__device__ int    g_idx  [NE*NTOK];
__device__ __half g_wbf  [(size_t)12*DIM*DIM];  // 12 transposed half weight mats [N][K]
__device__ float2 g_rope [(size_t)SEQ*64];      // (cos, sin) per (position, freq)

__device__ __forceinline__ void mma_f16(float d[4], uint32_t a0, uint32_t a1,
                                        uint32_t a2, uint32_t a3,
                                        uint32_t b0, uint32_t b1) {
    asm volatile(
        "mma.sync.aligned.m16n8k16.row.col.f32.f16.f16.f32 "
        "{%0,%1,%2,%3}, {%4,%5,%6,%7}, {%8,%9}, {%0,%1,%2,%3};"
        : "+f"(d[0]), "+f"(d[1]), "+f"(d[2]), "+f"(d[3])
        : "r"(a0), "r"(a1), "r"(a2), "r"(a3), "r"(b0), "r"(b1));
}

__device__ __forceinline__ void mma_bf16(float d[4], uint32_t a0, uint32_t a1,
                                         uint32_t a2, uint32_t a3,
                                         uint32_t b0, uint32_t b1) {
    asm volatile(
        "mma.sync.aligned.m16n8k16.row.col.f32.bf16.bf16.f32 "
        "{%0,%1,%2,%3}, {%4,%5,%6,%7}, {%8,%9}, {%0,%1,%2,%3};"
        : "+f"(d[0]), "+f"(d[1]), "+f"(d[2]), "+f"(d[3])
        : "r"(a0), "r"(a1), "r"(a2), "r"(a3), "r"(b0), "r"(b1));
}

__device__ __forceinline__ uint32_t pack_bf2(float lo, float hi) {
    __nv_bfloat162 t = __floats2bfloat162_rn(lo, hi);
    return *(uint32_t*)&t;
}
__device__ __forceinline__ uint32_t pack_h2(float lo, float hi) {
    __half2 t = __floats2half2_rn(lo, hi);
    return *(uint32_t*)&t;
}
__device__ __forceinline__ uint16_t bf16bits(float x) {
    __nv_bfloat16 t = __float2bfloat16_rn(x);
    return *(uint16_t*)&t;
}
__device__ __forceinline__ void cp_async16(uint32_t saddr, const void* g) {
    asm volatile("cp.async.cg.shared.global [%0], [%1], 16;" :: "r"(saddr), "l"(g) : "memory");
}

// ---------------- Weight prep: transpose+convert 12 matrices to half [N][K] ------------
__global__ void wprep_kernel(const float* __restrict__ wq, const float* __restrict__ wk,
                             const float* __restrict__ wv, const float* __restrict__ wo,
                             const float* __restrict__ we1, const float* __restrict__ we2,
                             __half* __restrict__ wbf) {
    int z = blockIdx.z;
    const float* src;
    if (z == 0) src = wq;
    else if (z == 1) src = wk;
    else if (z == 2) src = wv;
    else if (z == 3) src = wo;
    else if (z < 8) src = we1 + (size_t)(z - 4) * DIM * IDIM;
    else src = we2 + (size_t)(z - 8) * IDIM * DIM;
    __half* dst = wbf + (size_t)z * DIM * DIM;
    __shared__ float tile[32][33];
    int k0 = blockIdx.y * 32, n0 = blockIdx.x * 32;
    int tx = threadIdx.x, ty = threadIdx.y;   // 32 x 8
#pragma unroll
    for (int r = ty; r < 32; r += 8)
        tile[r][tx] = src[(size_t)(k0 + r) * DIM + n0 + tx];
    __syncthreads();
#pragma unroll
    for (int r = ty; r < 32; r += 8)
        dst[(size_t)(n0 + r) * DIM + k0 + tx] = __float2half_rn(tile[tx][r]);
}

// ---------------- RoPE table (one-shot double trig) ------------------------------------
__global__ void rope_table_kernel(float2* __restrict__ tab) {
    int idx = blockIdx.x * blockDim.x + threadIdx.x;   // SEQ*64
    if (idx >= SEQ * 64) return;
    int i = idx & 63;
    int s = idx >> 6;
    float invf = (float)(1.0 / pow(10000.0, (double)i / 64.0));
    float ang = (float)s * invf;
    double angd = (double)ang;
    tab[idx] = make_float2((float)cos(angd), (float)sin(angd));
}

// ---------------- RoPE apply: pure fp32 table lookup -----------------------------------
__global__ void rope_kernel(float* __restrict__ q, float* __restrict__ k,
                            const float2* __restrict__ tab) {
    int idx = blockIdx.x * blockDim.x + threadIdx.x;   // over NTOK*NH*64
    if (idx >= NTOK * NH * 64) return;
    int i = idx & 63;
    int rem = idx >> 6;
    int h = rem % NH;
    int t = rem / NH;
    int s = t % SEQ;
    float2 cs = tab[s * 64 + i];
    float c = cs.x, sn = cs.y;
    size_t base = (size_t)t * DIM + (size_t)h * HDIM;
    float q1 = q[base + i], q2 = q[base + 64 + i];
    q[base + i]      = q1 * c - q2 * sn;
    q[base + 64 + i] = q2 * c + q1 * sn;
    float k1 = k[base + i], k2 = k[base + 64 + i];
    k[base + i]      = k1 * c - k2 * sn;
    k[base + 64 + i] = k2 * c + k1 * sn;
}

// ---------------- LayerNorm: fp32 out + half copy --------------------------------------
__global__ void ln_kernel(const float* __restrict__ x, const float* __restrict__ w,
                          const float* __restrict__ b, float* __restrict__ y,
                          __half* __restrict__ yh) {
    int row = blockIdx.x;
    const float* xr = x + (size_t)row * DIM;
    float* yr = y + (size_t)row * DIM;
    __half* yhr = yh + (size_t)row * DIM;
    __shared__ float red[256];
    int tid = threadIdx.x;
    float s = 0.f;
    for (int i = tid; i < DIM; i += 256) s += xr[i];
    red[tid] = s; __syncthreads();
    for (int o = 128; o > 0; o >>= 1) { if (tid < o) red[tid] += red[tid + o]; __syncthreads(); }
    float mu = red[0] * (1.f / DIM);
    __syncthreads();
    float v = 0.f;
    for (int i = tid; i < DIM; i += 256) { float d = xr[i] - mu; v += d * d; }
    red[tid] = v; __syncthreads();
    for (int o = 128; o > 0; o >>= 1) { if (tid < o) red[tid] += red[tid + o]; __syncthreads(); }
    float inv = rsqrtf(red[0] * (1.f / DIM) + 1e-5f);
    for (int i = tid; i < DIM; i += 256) {
        float val = (xr[i] - mu) * inv * w[i] + b[i];
        yr[i] = val;
        yhr[i] = __float2half_rn(val);
    }
}

// ---------------- FP16 GEMM, cp.async 2-stage pipeline ---------------------------------
// A half [M][K] (optional row gather), B half pre-transposed [N][K].
// Outputs: fp32 C (optional, +=/=) and/or half Ch.
__device__ __forceinline__ void epi(float v, int gm, int gn,
                                    const float* bias, int act,
                                    const float* resid, int ldr,
                                    const float* rowscale, int rss,
                                    float* C, __half* Ch, int ldc, int accum) {
    if (bias) v += bias[gn];
    if (act) v = 0.5f * v * (1.f + erff(v * 0.70710678118654752f));
    if (resid) v += resid[(size_t)gm * ldr + gn];
    if (rowscale) v *= rowscale[(size_t)gm * rss];
    size_t o = (size_t)gm * ldc + gn;
    if (C) { if (accum) C[o] += v; else C[o] = v; }
    if (Ch) Ch[o] = __float2half_rn(v);
}

__global__ void __launch_bounds__(128)
gemm_f16(const __half* __restrict__ A, int lda,
         const __half* __restrict__ Bt, int ldb,
         const float* __restrict__ bias,
         float* __restrict__ C, __half* __restrict__ Ch, int ldc,
         const float* __restrict__ resid, int ldr,
         const float* __restrict__ rowscale, int rss,
         int M, int N, int K, int act, int accum,
         const int* __restrict__ amap, const int* __restrict__ cmap,
         const int* __restrict__ mcount) {
    int M_eff = mcount ? *mcount : M;
    int row0 = blockIdx.y * 128, col0 = blockIdx.x * 128;
    if (row0 >= M_eff) return;

    __shared__ uint32_t As[2][128][20];   // [stage][m][kpair] (16 pairs + 4 pad)
    __shared__ uint32_t Bs[2][128][20];
    const uint32_t SB = 128 * 20 * 4;     // stage bytes
    int tid = threadIdx.x;
    int w = tid >> 5, lane = tid & 31;
    int wm = w >> 1, wn = w & 1;
    int m_w = wm * 64, n_w = wn * 64;
    int g = lane >> 2, q = lane & 3;

    float acc[4][8][4];
#pragma unroll
    for (int i = 0; i < 4; i++)
#pragma unroll
        for (int j = 0; j < 8; j++)
#pragma unroll
            for (int r = 0; r < 4; r++) acc[i][j][r] = 0.f;

    // staging: 4 x 16B cp.async each for A and B per thread per tile
    const __half *Apt[4], *Bpt[4];
    uint32_t offS[4];
#pragma unroll
    for (int j = 0; j < 4; j++) {
        int cidx = tid + j * 128;       // 0..511
        int row = cidx >> 2, ch = cidx & 3;
        int gm = row0 + row;
        int cl = gm < M_eff ? gm : M_eff - 1;
        int ar = amap ? amap[cl] : cl;
        Apt[j] = A + (size_t)ar * lda + ch * 8;
        Bpt[j] = Bt + (size_t)(col0 + row) * ldb + ch * 8;
        offS[j] = (uint32_t)(row * 20 + ch * 4) * 4;
    }
    uint32_t baseA = (uint32_t)__cvta_generic_to_shared(&As[0][0][0]);
    uint32_t baseB = (uint32_t)__cvta_generic_to_shared(&Bs[0][0][0]);

    int nk = K / 32;

#define GEMM_ISSUE(T_) do {                                            \
        int tt = (T_);                                                 \
        if (tt < nk) {                                                 \
            int st_ = tt & 1;                                          \
            int k0_ = tt * 32;                                         \
            uint32_t ab = baseA + st_ * SB, bb = baseB + st_ * SB;     \
            _Pragma("unroll")                                          \
            for (int j = 0; j < 4; j++) {                              \
                cp_async16(ab + offS[j], Apt[j] + k0_);                \
                cp_async16(bb + offS[j], Bpt[j] + k0_);                \
            }                                                          \
        }                                                              \
        asm volatile("cp.async.commit_group;" ::: "memory");           \
    } while (0)

    GEMM_ISSUE(0);
    for (int t = 0; t < nk; t++) {
        __syncthreads();                 // all threads done computing tile t-1
        GEMM_ISSUE(t + 1);               // prefetch next tile (overlaps compute of t)
        asm volatile("cp.async.wait_group 1;" ::: "memory");  // tile t data arrived
        __syncthreads();
        int st = t & 1;

#pragma unroll
        for (int ks = 0; ks < 2; ks++) {
            int kp = ks * 8;
            uint32_t af[4][4], bf[8][2];
#pragma unroll
            for (int i = 0; i < 4; i++) {
                int r = m_w + i * 16 + g;
                af[i][0] = As[st][r][kp + q];
                af[i][1] = As[st][r + 8][kp + q];
                af[i][2] = As[st][r][kp + q + 4];
                af[i][3] = As[st][r + 8][kp + q + 4];
            }
#pragma unroll
            for (int j = 0; j < 8; j++) {
                int c = n_w + j * 8 + g;
                bf[j][0] = Bs[st][c][kp + q];
                bf[j][1] = Bs[st][c][kp + q + 4];
            }
#pragma unroll
            for (int i = 0; i < 4; i++)
#pragma unroll
                for (int j = 0; j < 8; j++)
                    mma_f16(acc[i][j], af[i][0], af[i][1], af[i][2], af[i][3],
                            bf[j][0], bf[j][1]);
        }
    }
#undef GEMM_ISSUE

#pragma unroll
    for (int i = 0; i < 4; i++) {
        int gm = row0 + m_w + i * 16 + g;
        if (gm < M_eff) {
            int cr = cmap ? cmap[gm] : gm;
#pragma unroll
            for (int j = 0; j < 8; j++) {
                int cb = col0 + n_w + j * 8 + q * 2;
                epi(acc[i][j][0], cr, cb,     bias, act, resid, ldr, rowscale, rss, C, Ch, ldc, accum);
                epi(acc[i][j][1], cr, cb + 1, bias, act, resid, ldr, rowscale, rss, C, Ch, ldc, accum);
            }
        }
        int gm2 = gm + 8;
        if (gm2 < M_eff) {
            int cr2 = cmap ? cmap[gm2] : gm2;
#pragma unroll
            for (int j = 0; j < 8; j++) {
                int cb = col0 + n_w + j * 8 + q * 2;
                epi(acc[i][j][2], cr2, cb,     bias, act, resid, ldr, rowscale, rss, C, Ch, ldc, accum);
                epi(acc[i][j][3], cr2, cb + 1, bias, act, resid, ldr, rowscale, rss, C, Ch, ldc, accum);
            }
        }
    }
}

// ---------------- Flash attention (R12 numerics, half output) --------------------------
__global__ void __launch_bounds__(256)
fa_kernel(const float* __restrict__ q, const float* __restrict__ k,
          const float* __restrict__ v, __half* __restrict__ attnh) {
    __shared__ uint32_t Ks[32][68];
    __shared__ uint32_t Vt[128][20];
    __shared__ uint32_t Ps[8][16][20];

    int bh = blockIdx.y;
    int b = bh / NH, h = bh % NH;
    int q0 = blockIdx.x * 128;
    int tid = threadIdx.x, w = tid >> 5, lane = tid & 31;
    int g = lane >> 2, qd = lane & 3;
    const float alpha = 0.08838834764831845f;

    const float* qb = q + ((size_t)b * SEQ) * DIM + h * HDIM;
    const float* kb_ = k + ((size_t)b * SEQ) * DIM + h * HDIM;
    const float* vb = v + ((size_t)b * SEQ) * DIM + h * HDIM;

    uint32_t qf[8][4];
    {
        const float* qr0 = qb + (size_t)(q0 + w * 16 + g) * DIM;
        const float* qr1 = qr0 + 8 * DIM;
#pragma unroll
        for (int ks = 0; ks < 8; ks++) {
            int c0 = (ks * 8 + qd) * 2, c1 = (ks * 8 + qd + 4) * 2;
            float2 t00 = *(const float2*)(qr0 + c0);
            float2 t10 = *(const float2*)(qr1 + c0);
            float2 t01 = *(const float2*)(qr0 + c1);
            float2 t11 = *(const float2*)(qr1 + c1);
            qf[ks][0] = pack_bf2(t00.x * alpha, t00.y * alpha);
            qf[ks][1] = pack_bf2(t10.x * alpha, t10.y * alpha);
            qf[ks][2] = pack_bf2(t01.x * alpha, t01.y * alpha);
            qf[ks][3] = pack_bf2(t11.x * alpha, t11.y * alpha);
        }
    }

    float m0 = -1e30f, m1 = -1e30f, l0 = 0.f, l1 = 0.f;
    float out[16][4];
#pragma unroll
    for (int i = 0; i < 16; i++)
#pragma unroll
        for (int r = 0; r < 4; r++) out[i][r] = 0.f;

    int ktiles = q0 / 32 + 4;

    for (int kt = 0; kt < ktiles; kt++) {
        int k0 = kt * 32;
        __syncthreads();
        for (int i = tid; i < 32 * 32; i += 256) {
            int r = i >> 5, c4 = i & 31;
            float4 tk = *(const float4*)(kb_ + (size_t)(k0 + r) * DIM + c4 * 4);
            Ks[r][c4 * 2]     = pack_bf2(tk.x, tk.y);
            Ks[r][c4 * 2 + 1] = pack_bf2(tk.z, tk.w);
            float4 tv = *(const float4*)(vb + (size_t)(k0 + r) * DIM + c4 * 4);
            uint16_t* vt = (uint16_t*)Vt;
            vt[(c4 * 4 + 0) * 40 + r] = bf16bits(tv.x);
            vt[(c4 * 4 + 1) * 40 + r] = bf16bits(tv.y);
            vt[(c4 * 4 + 2) * 40 + r] = bf16bits(tv.z);
            vt[(c4 * 4 + 3) * 40 + r] = bf16bits(tv.w);
        }
        __syncthreads();

        float sc[4][4];
#pragma unroll
        for (int nt = 0; nt < 4; nt++)
#pragma unroll
            for (int r = 0; r < 4; r++) sc[nt][r] = 0.f;
#pragma unroll
        for (int ks = 0; ks < 8; ks++) {
            int kp = ks * 8;
#pragma unroll
            for (int nt = 0; nt < 4; nt++) {
                uint32_t b0 = Ks[nt * 8 + g][kp + qd];
                uint32_t b1 = Ks[nt * 8 + g][kp + qd + 4];
                mma_bf16(sc[nt], qf[ks][0], qf[ks][1], qf[ks][2], qf[ks][3], b0, b1);
            }
        }

        if (k0 + 31 > q0) {
            int rq0 = q0 + w * 16 + g;
            int rq1 = rq0 + 8;
#pragma unroll
            for (int nt = 0; nt < 4; nt++) {
                int kc = k0 + nt * 8 + qd * 2;
                if (kc     > rq0) sc[nt][0] = -1e30f;
                if (kc + 1 > rq0) sc[nt][1] = -1e30f;
                if (kc     > rq1) sc[nt][2] = -1e30f;
                if (kc + 1 > rq1) sc[nt][3] = -1e30f;
            }
        }

        float tm0 = -1e30f, tm1 = -1e30f;
#pragma unroll
        for (int nt = 0; nt < 4; nt++) {
            tm0 = fmaxf(tm0, fmaxf(sc[nt][0], sc[nt][1]));
            tm1 = fmaxf(tm1, fmaxf(sc[nt][2], sc[nt][3]));
        }
        tm0 = fmaxf(tm0, __shfl_xor_sync(0xffffffffu, tm0, 1));
        tm0 = fmaxf(tm0, __shfl_xor_sync(0xffffffffu, tm0, 2));
        tm1 = fmaxf(tm1, __shfl_xor_sync(0xffffffffu, tm1, 1));
        tm1 = fmaxf(tm1, __shfl_xor_sync(0xffffffffu, tm1, 2));

        float mn0 = fmaxf(m0, tm0), mn1 = fmaxf(m1, tm1);
        bool chg = (mn0 != m0) || (mn1 != m1);
        if (__any_sync(0xffffffffu, chg)) {
            float corr0 = __expf(m0 - mn0), corr1 = __expf(m1 - mn1);
            l0 *= corr0; l1 *= corr1;
#pragma unroll
            for (int nt = 0; nt < 16; nt++) {
                out[nt][0] *= corr0; out[nt][1] *= corr0;
                out[nt][2] *= corr1; out[nt][3] *= corr1;
            }
        }
        m0 = mn0; m1 = mn1;

        float s0 = 0.f, s1 = 0.f;
#pragma unroll
        for (int nt = 0; nt < 4; nt++) {
            float p0 = __expf(sc[nt][0] - m0);
            float p1 = __expf(sc[nt][1] - m0);
            float p2 = __expf(sc[nt][2] - m1);
            float p3 = __expf(sc[nt][3] - m1);
            s0 += p0 + p1; s1 += p2 + p3;
            Ps[w][g][nt * 4 + qd]     = pack_bf2(p0, p1);
            Ps[w][g + 8][nt * 4 + qd] = pack_bf2(p2, p3);
        }
        s0 += __shfl_xor_sync(0xffffffffu, s0, 1);
        s0 += __shfl_xor_sync(0xffffffffu, s0, 2);
        s1 += __shfl_xor_sync(0xffffffffu, s1, 1);
        s1 += __shfl_xor_sync(0xffffffffu, s1, 2);
        l0 += s0; l1 += s1;
        __syncwarp();

#pragma unroll
        for (int ks = 0; ks < 2; ks++) {
            int kp = ks * 8;
            uint32_t a0 = Ps[w][g][kp + qd];
            uint32_t a1 = Ps[w][g + 8][kp + qd];
            uint32_t a2 = Ps[w][g][kp + qd + 4];
            uint32_t a3 = Ps[w][g + 8][kp + qd + 4];
#pragma unroll
            for (int nt = 0; nt < 16; nt++) {
                uint32_t b0 = Vt[nt * 8 + g][kp + qd];
                uint32_t b1 = Vt[nt * 8 + g][kp + qd + 4];
                mma_bf16(out[nt], a0, a1, a2, a3, b0, b1);
            }
        }
        __syncwarp();
    }

    float inv0 = 1.f / l0, inv1 = 1.f / l1;
    int r0g = q0 + w * 16 + g;
    __half* ob = attnh + ((size_t)b * SEQ) * DIM + h * HDIM;
#pragma unroll
    for (int nt = 0; nt < 16; nt++) {
        int c = nt * 8 + qd * 2;
        *(uint32_t*)(ob + (size_t)r0g * DIM + c) =
            pack_h2(out[nt][0] * inv0, out[nt][1] * inv0);
        *(uint32_t*)(ob + (size_t)(r0g + 8) * DIM + c) =
            pack_h2(out[nt][2] * inv1, out[nt][3] * inv1);
    }
}

// ---------------- MoE gate -------------------------------------------------------------
__global__ void gate_kernel(const float* __restrict__ x, const float* __restrict__ wg,
                            float* __restrict__ comb) {
    int t = blockIdx.x;
    int tid = threadIdx.x;
    __shared__ float red[NE * 128];
    const float* xr = x + (size_t)t * DIM;
    float acc[NE] = {0.f, 0.f, 0.f, 0.f};
    for (int d = tid; d < DIM; d += 128) {
        float xv = xr[d];
#pragma unroll
        for (int e = 0; e < NE; e++) acc[e] += xv * wg[(size_t)d * NE + e];
    }
#pragma unroll
    for (int e = 0; e < NE; e++) red[e * 128 + tid] = acc[e];
    __syncthreads();
    for (int o = 64; o > 0; o >>= 1) {
        if (tid < o) {
#pragma unroll
            for (int e = 0; e < NE; e++) red[e * 128 + tid] += red[e * 128 + tid + o];
        }
        __syncthreads();
    }
    if (tid == 0) {
        float l[NE];
#pragma unroll
        for (int e = 0; e < NE; e++) l[e] = red[e * 128];
        float mx = fmaxf(fmaxf(l[0], l[1]), fmaxf(l[2], l[3]));
        float ex[NE], s = 0.f;
#pragma unroll
        for (int e = 0; e < NE; e++) { ex[e] = expf(l[e] - mx); s += ex[e]; }
        float p[NE];
#pragma unroll
        for (int e = 0; e < NE; e++) p[e] = ex[e] / s;
        int i0 = 0;
#pragma unroll
        for (int e = 1; e < NE; e++) if (p[e] > p[i0]) i0 = e;
        int i1 = (i0 == 0) ? 1 : 0;
#pragma unroll
        for (int e = 0; e < NE; e++) if (e != i0 && p[e] > p[i1]) i1 = e;
        float e1 = expf(p[i1] - p[i0]);
        float invs = 1.f / (1.f + e1);
        float c[NE] = {0.f, 0.f, 0.f, 0.f};
        c[i0] = invs;
        c[i1] = e1 * invs;
#pragma unroll
        for (int e = 0; e < NE; e++) comb[(size_t)t * NE + e] = c[e];
    }
}

// ---------------- Routing --------------------------------------------------------------
__global__ void zero_cnt_kernel(int* cnt) {
    if (threadIdx.x < NE) cnt[threadIdx.x] = 0;
}
__global__ void route_kernel(const float* __restrict__ comb, int* __restrict__ cnt,
                             int* __restrict__ idx) {
    int t = blockIdx.x * blockDim.x + threadIdx.x;
    if (t >= NTOK) return;
#pragma unroll
    for (int e = 0; e < NE; e++) {
        if (comb[(size_t)t * NE + e] > 0.f) {
            int pos = atomicAdd(&cnt[e], 1);
            idx[e * NTOK + pos] = t;
        }
    }
}

// ---------------- host orchestration ---------------------------------------------------
extern "C" void kernel_launch(void* const* d_in, const int* in_sizes, int n_in,
                              void* d_out, int out_size) {
    (void)in_sizes; (void)n_in; (void)out_size;
    const float* hs   = (const float*)d_in[0];
    const float* wq   = (const float*)d_in[1];
    const float* bq   = (const float*)d_in[2];
    const float* wk   = (const float*)d_in[3];
    const float* bk   = (const float*)d_in[4];
    const float* wv   = (const float*)d_in[5];
    const float* bv   = (const float*)d_in[6];
    const float* wo   = (const float*)d_in[7];
    const float* bo   = (const float*)d_in[8];
    const float* ln1w = (const float*)d_in[9];
    const float* ln1b = (const float*)d_in[10];
    const float* ln2w = (const float*)d_in[11];
    const float* ln2b = (const float*)d_in[12];
    const float* wg   = (const float*)d_in[13];
    const float* we1  = (const float*)d_in[14];
    const float* be1  = (const float*)d_in[15];
    const float* we2  = (const float*)d_in[16];
    const float* be2  = (const float*)d_in[17];
    float* out = (float*)d_out;

    float *p_ln, *p_q, *p_k, *p_v, *p_comb;
    __half *p_lnh, *p_attnh, *p_hmidh, *p_wbf;
    int *p_cnt, *p_idx;
    float2* p_rope;
    cudaGetSymbolAddress((void**)&p_ln, g_ln);
    cudaGetSymbolAddress((void**)&p_lnh, g_lnh);
    cudaGetSymbolAddress((void**)&p_q, g_q);
    cudaGetSymbolAddress((void**)&p_k, g_k);
    cudaGetSymbolAddress((void**)&p_v, g_v);
    cudaGetSymbolAddress((void**)&p_attnh, g_attnh);
    cudaGetSymbolAddress((void**)&p_hmidh, g_hmidh);
    cudaGetSymbolAddress((void**)&p_comb, g_comb);
    cudaGetSymbolAddress((void**)&p_cnt, g_cnt);
    cudaGetSymbolAddress((void**)&p_idx, g_idx);
    cudaGetSymbolAddress((void**)&p_wbf, g_wbf);
    cudaGetSymbolAddress((void**)&p_rope, g_rope);

    // 0. Weight prep + RoPE table
    dim3 gW(DIM / 32, DIM / 32, 12);
    wprep_kernel<<<gW, dim3(32, 8)>>>(wq, wk, wv, wo, we1, we2, p_wbf);
    rope_table_kernel<<<(SEQ * 64) / 256, 256>>>(p_rope);

    // 1. LN1 (fp32 + half)
    ln_kernel<<<NTOK, 256>>>(hs, ln1w, ln1b, p_ln, p_lnh);

    // 2. QKV projections (A = half LN output)
    dim3 gBig(DIM / 128, NTOK / 128);
    size_t WSZ = (size_t)DIM * DIM;
    gemm_f16<<<gBig, 128>>>(p_lnh, DIM, p_wbf + 0 * WSZ, DIM, bq, p_q, nullptr, DIM,
                            nullptr, 0, nullptr, 0, NTOK, DIM, DIM, 0, 0,
                            nullptr, nullptr, nullptr);
    gemm_f16<<<gBig, 128>>>(p_lnh, DIM, p_wbf + 1 * WSZ, DIM, bk, p_k, nullptr, DIM,
                            nullptr, 0, nullptr, 0, NTOK, DIM, DIM, 0, 0,
                            nullptr, nullptr, nullptr);
    gemm_f16<<<gBig, 128>>>(p_lnh, DIM, p_wbf + 2 * WSZ, DIM, bv, p_v, nullptr, DIM,
                            nullptr, 0, nullptr, 0, NTOK, DIM, DIM, 0, 0,
                            nullptr, nullptr, nullptr);

    // 3. RoPE (table lookup)
    int nrope = NTOK * NH * 64;
    rope_kernel<<<(nrope + 255) / 256, 256>>>(p_q, p_k, p_rope);

    // 4. Flash attention (half output)
    dim3 gFA(SEQ / 128, BATCH * NH);
    fa_kernel<<<gFA, 256>>>(p_q, p_k, p_v, p_attnh);

    // 5. O-proj + bias + residual -> out (= h)
    gemm_f16<<<gBig, 128>>>(p_attnh, DIM, p_wbf + 3 * WSZ, DIM, bo, out, nullptr, DIM,
                            hs, DIM, nullptr, 0, NTOK, DIM, DIM, 0, 0,
                            nullptr, nullptr, nullptr);

    // 6. LN2 (fp32 for gate + half for experts)
    ln_kernel<<<NTOK, 256>>>(out, ln2w, ln2b, p_ln, p_lnh);

    // 7. Gate + routing
    gate_kernel<<<NTOK, 128>>>(p_ln, wg, p_comb);
    zero_cnt_kernel<<<1, 32>>>(p_cnt);
    route_kernel<<<NTOK / 256, 256>>>(p_comb, p_cnt, p_idx);

    // 8. Sparse experts
    for (int e = 0; e < NE; e++) {
        const float* b1 = be1 + (size_t)e * IDIM;
        const float* b2 = be2 + (size_t)e * DIM;
        const int* idx_e = p_idx + e * NTOK;
        const int* cnt_e = p_cnt + e;
        // GEMM1: hmid(half) = gelu(lnh[idx] @ we1 + b1)
        gemm_f16<<<gBig, 128>>>(p_lnh, DIM, p_wbf + (4 + e) * WSZ, DIM, b1,
                                nullptr, p_hmidh, IDIM,
                                nullptr, 0, nullptr, 0, NTOK, IDIM, DIM, 1, 0,
                                idx_e, nullptr, cnt_e);
        // GEMM2: out[idx] += comb * (hmid @ we2 + b2)
        gemm_f16<<<gBig, 128>>>(p_hmidh, IDIM, p_wbf + (8 + e) * WSZ, IDIM, b2,
                                out, nullptr, DIM,
                                nullptr, 0, p_comb + e, NE, NTOK, DIM, IDIM, 0, 1,
                                nullptr, idx_e, cnt_e);
    }
}

// round 15
// speedup vs baseline: 2.0833x; 1.0678x over previous
#include <cuda_runtime.h>
#include <cuda_bf16.h>
#include <cuda_fp16.h>
#include <math.h>
#include <stdint.h>

#define BATCH 2
#define SEQ   2048
#define DIM   2048
#define NH    16
#define HDIM  128
#define NE    4
#define IDIM  2048
#define NTOK  (BATCH*SEQ)   // 4096

// ---------------- scratch (static device globals) ----
__device__ float  g_ln   [(size_t)NTOK*DIM];
__device__ __half g_lnh  [(size_t)NTOK*DIM];
__device__ float  g_q    [(size_t)NTOK*DIM];
__device__ float  g_k    [(size_t)NTOK*DIM];
__device__ float  g_v    [(size_t)NTOK*DIM];
__device__ __half g_attnh[(size_t)NTOK*DIM];
__device__ __half g_hmidh[(size_t)NE*NTOK*IDIM];  // per-expert hidden (64 MB)
__device__ float  g_comb [(size_t)NTOK*NE];
__device__ int    g_cnt  [NE];
__device__ int    g_idx  [NE*NTOK];
__device__ __half g_wbf  [(size_t)12*DIM*DIM];
__device__ float2 g_rope [(size_t)SEQ*64];

struct ZIO {
    const float* bias;
    float* C;
    __half* Ch;
    const float* resid;
    const float* rowscale;
    const int* amap;
    const int* cmap;
    const int* mcount;
};

__device__ __forceinline__ void mma_f16(float d[4], uint32_t a0, uint32_t a1,
                                        uint32_t a2, uint32_t a3,
                                        uint32_t b0, uint32_t b1) {
    asm volatile(
        "mma.sync.aligned.m16n8k16.row.col.f32.f16.f16.f32 "
        "{%0,%1,%2,%3}, {%4,%5,%6,%7}, {%8,%9}, {%0,%1,%2,%3};"
        : "+f"(d[0]), "+f"(d[1]), "+f"(d[2]), "+f"(d[3])
        : "r"(a0), "r"(a1), "r"(a2), "r"(a3), "r"(b0), "r"(b1));
}

__device__ __forceinline__ void mma_bf16(float d[4], uint32_t a0, uint32_t a1,
                                         uint32_t a2, uint32_t a3,
                                         uint32_t b0, uint32_t b1) {
    asm volatile(
        "mma.sync.aligned.m16n8k16.row.col.f32.bf16.bf16.f32 "
        "{%0,%1,%2,%3}, {%4,%5,%6,%7}, {%8,%9}, {%0,%1,%2,%3};"
        : "+f"(d[0]), "+f"(d[1]), "+f"(d[2]), "+f"(d[3])
        : "r"(a0), "r"(a1), "r"(a2), "r"(a3), "r"(b0), "r"(b1));
}

__device__ __forceinline__ uint32_t pack_bf2(float lo, float hi) {
    __nv_bfloat162 t = __floats2bfloat162_rn(lo, hi);
    return *(uint32_t*)&t;
}
__device__ __forceinline__ uint32_t pack_h2(float lo, float hi) {
    __half2 t = __floats2half2_rn(lo, hi);
    return *(uint32_t*)&t;
}
__device__ __forceinline__ uint16_t bf16bits(float x) {
    __nv_bfloat16 t = __float2bfloat16_rn(x);
    return *(uint16_t*)&t;
}
__device__ __forceinline__ void cp_async16(uint32_t saddr, const void* g) {
    asm volatile("cp.async.cg.shared.global [%0], [%1], 16;" :: "r"(saddr), "l"(g) : "memory");
}

// ---------------- Weight prep ----------------------------------------------------------
__global__ void wprep_kernel(const float* __restrict__ wq, const float* __restrict__ wk,
                             const float* __restrict__ wv, const float* __restrict__ wo,
                             const float* __restrict__ we1, const float* __restrict__ we2,
                             __half* __restrict__ wbf) {
    int z = blockIdx.z;
    const float* src;
    if (z == 0) src = wq;
    else if (z == 1) src = wk;
    else if (z == 2) src = wv;
    else if (z == 3) src = wo;
    else if (z < 8) src = we1 + (size_t)(z - 4) * DIM * IDIM;
    else src = we2 + (size_t)(z - 8) * IDIM * DIM;
    __half* dst = wbf + (size_t)z * DIM * DIM;
    __shared__ float tile[32][33];
    int k0 = blockIdx.y * 32, n0 = blockIdx.x * 32;
    int tx = threadIdx.x, ty = threadIdx.y;
#pragma unroll
    for (int r = ty; r < 32; r += 8)
        tile[r][tx] = src[(size_t)(k0 + r) * DIM + n0 + tx];
    __syncthreads();
#pragma unroll
    for (int r = ty; r < 32; r += 8)
        dst[(size_t)(n0 + r) * DIM + k0 + tx] = __float2half_rn(tile[tx][r]);
}

// ---------------- RoPE table -----------------------------------------------------------
__global__ void rope_table_kernel(float2* __restrict__ tab) {
    int idx = blockIdx.x * blockDim.x + threadIdx.x;
    if (idx >= SEQ * 64) return;
    int i = idx & 63;
    int s = idx >> 6;
    float invf = (float)(1.0 / pow(10000.0, (double)i / 64.0));
    float ang = (float)s * invf;
    double angd = (double)ang;
    tab[idx] = make_float2((float)cos(angd), (float)sin(angd));
}

// ---------------- RoPE apply -----------------------------------------------------------
__global__ void rope_kernel(float* __restrict__ q, float* __restrict__ k,
                            const float2* __restrict__ tab) {
    int idx = blockIdx.x * blockDim.x + threadIdx.x;
    if (idx >= NTOK * NH * 64) return;
    int i = idx & 63;
    int rem = idx >> 6;
    int h = rem % NH;
    int t = rem / NH;
    int s = t % SEQ;
    float2 cs = tab[s * 64 + i];
    float c = cs.x, sn = cs.y;
    size_t base = (size_t)t * DIM + (size_t)h * HDIM;
    float q1 = q[base + i], q2 = q[base + 64 + i];
    q[base + i]      = q1 * c - q2 * sn;
    q[base + 64 + i] = q2 * c + q1 * sn;
    float k1 = k[base + i], k2 = k[base + 64 + i];
    k[base + i]      = k1 * c - k2 * sn;
    k[base + 64 + i] = k2 * c + k1 * sn;
}

// ---------------- LayerNorm ------------------------------------------------------------
__global__ void ln_kernel(const float* __restrict__ x, const float* __restrict__ w,
                          const float* __restrict__ b, float* __restrict__ y,
                          __half* __restrict__ yh) {
    int row = blockIdx.x;
    const float* xr = x + (size_t)row * DIM;
    float* yr = y + (size_t)row * DIM;
    __half* yhr = yh + (size_t)row * DIM;
    __shared__ float red[256];
    int tid = threadIdx.x;
    float s = 0.f;
    for (int i = tid; i < DIM; i += 256) s += xr[i];
    red[tid] = s; __syncthreads();
    for (int o = 128; o > 0; o >>= 1) { if (tid < o) red[tid] += red[tid + o]; __syncthreads(); }
    float mu = red[0] * (1.f / DIM);
    __syncthreads();
    float v = 0.f;
    for (int i = tid; i < DIM; i += 256) { float d = xr[i] - mu; v += d * d; }
    red[tid] = v; __syncthreads();
    for (int o = 128; o > 0; o >>= 1) { if (tid < o) red[tid] += red[tid + o]; __syncthreads(); }
    float inv = rsqrtf(red[0] * (1.f / DIM) + 1e-5f);
    for (int i = tid; i < DIM; i += 256) {
        float val = (xr[i] - mu) * inv * w[i] + b[i];
        yr[i] = val;
        yhr[i] = __float2half_rn(val);
    }
}

// ---------------- FP16 GEMM, cp.async 2-stage, batched over blockIdx.z -----------------
__device__ __forceinline__ void epi(float v, int gm, int gn,
                                    const float* bias, int act,
                                    const float* resid, int ldr,
                                    const float* rowscale, int rss,
                                    float* C, __half* Ch, int ldc, int accum) {
    if (bias) v += bias[gn];
    if (act) v = 0.5f * v * (1.f + erff(v * 0.70710678118654752f));
    if (resid) v += resid[(size_t)gm * ldr + gn];
    if (rowscale) v *= rowscale[(size_t)gm * rss];
    size_t o = (size_t)gm * ldc + gn;
    if (C) {
        if (accum == 2) atomicAdd(&C[o], v);
        else if (accum == 1) C[o] += v;
        else C[o] = v;
    }
    if (Ch) Ch[o] = __float2half_rn(v);
}

__global__ void __launch_bounds__(128)
gemm_f16(const __half* __restrict__ Abase, size_t strideAz, int lda,
         const __half* __restrict__ Bbase, size_t strideBz, int ldb,
         ZIO z0, ZIO z1, ZIO z2, ZIO z3,
         int ldc, int ldr, int rss,
         int M, int N, int K, int act, int accum) {
    int z = blockIdx.z;
    ZIO io = (z == 0) ? z0 : ((z == 1) ? z1 : ((z == 2) ? z2 : z3));
    const __half* A = Abase + (size_t)z * strideAz;
    const __half* Bt = Bbase + (size_t)z * strideBz;

    int M_eff = io.mcount ? *io.mcount : M;
    int row0 = blockIdx.y * 128, col0 = blockIdx.x * 128;
    if (row0 >= M_eff) return;

    __shared__ uint32_t As[2][128][20];
    __shared__ uint32_t Bs[2][128][20];
    const uint32_t SB = 128 * 20 * 4;
    int tid = threadIdx.x;
    int w = tid >> 5, lane = tid & 31;
    int wm = w >> 1, wn = w & 1;
    int m_w = wm * 64, n_w = wn * 64;
    int g = lane >> 2, q = lane & 3;

    float acc[4][8][4];
#pragma unroll
    for (int i = 0; i < 4; i++)
#pragma unroll
        for (int j = 0; j < 8; j++)
#pragma unroll
            for (int r = 0; r < 4; r++) acc[i][j][r] = 0.f;

    const __half *Apt[4], *Bpt[4];
    uint32_t offS[4];
#pragma unroll
    for (int j = 0; j < 4; j++) {
        int cidx = tid + j * 128;
        int row = cidx >> 2, ch = cidx & 3;
        int gm = row0 + row;
        int cl = gm < M_eff ? gm : M_eff - 1;
        int ar = io.amap ? io.amap[cl] : cl;
        Apt[j] = A + (size_t)ar * lda + ch * 8;
        Bpt[j] = Bt + (size_t)(col0 + row) * ldb + ch * 8;
        offS[j] = (uint32_t)(row * 20 + ch * 4) * 4;
    }
    uint32_t baseA = (uint32_t)__cvta_generic_to_shared(&As[0][0][0]);
    uint32_t baseB = (uint32_t)__cvta_generic_to_shared(&Bs[0][0][0]);

    int nk = K / 32;

#define GEMM_ISSUE(T_) do {                                            \
        int tt = (T_);                                                 \
        if (tt < nk) {                                                 \
            int st_ = tt & 1;                                          \
            int k0_ = tt * 32;                                         \
            uint32_t ab = baseA + st_ * SB, bb = baseB + st_ * SB;     \
            _Pragma("unroll")                                          \
            for (int j = 0; j < 4; j++) {                              \
                cp_async16(ab + offS[j], Apt[j] + k0_);                \
                cp_async16(bb + offS[j], Bpt[j] + k0_);                \
            }                                                          \
        }                                                              \
        asm volatile("cp.async.commit_group;" ::: "memory");           \
    } while (0)

    GEMM_ISSUE(0);
    for (int t = 0; t < nk; t++) {
        __syncthreads();
        GEMM_ISSUE(t + 1);
        asm volatile("cp.async.wait_group 1;" ::: "memory");
        __syncthreads();
        int st = t & 1;

#pragma unroll
        for (int ks = 0; ks < 2; ks++) {
            int kp = ks * 8;
            uint32_t af[4][4], bf[8][2];
#pragma unroll
            for (int i = 0; i < 4; i++) {
                int r = m_w + i * 16 + g;
                af[i][0] = As[st][r][kp + q];
                af[i][1] = As[st][r + 8][kp + q];
                af[i][2] = As[st][r][kp + q + 4];
                af[i][3] = As[st][r + 8][kp + q + 4];
            }
#pragma unroll
            for (int j = 0; j < 8; j++) {
                int c = n_w + j * 8 + g;
                bf[j][0] = Bs[st][c][kp + q];
                bf[j][1] = Bs[st][c][kp + q + 4];
            }
#pragma unroll
            for (int i = 0; i < 4; i++)
#pragma unroll
                for (int j = 0; j < 8; j++)
                    mma_f16(acc[i][j], af[i][0], af[i][1], af[i][2], af[i][3],
                            bf[j][0], bf[j][1]);
        }
    }
#undef GEMM_ISSUE

#pragma unroll
    for (int i = 0; i < 4; i++) {
        int gm = row0 + m_w + i * 16 + g;
        if (gm < M_eff) {
            int cr = io.cmap ? io.cmap[gm] : gm;
#pragma unroll
            for (int j = 0; j < 8; j++) {
                int cb = col0 + n_w + j * 8 + q * 2;
                epi(acc[i][j][0], cr, cb,     io.bias, act, io.resid, ldr, io.rowscale, rss, io.C, io.Ch, ldc, accum);
                epi(acc[i][j][1], cr, cb + 1, io.bias, act, io.resid, ldr, io.rowscale, rss, io.C, io.Ch, ldc, accum);
            }
        }
        int gm2 = gm + 8;
        if (gm2 < M_eff) {
            int cr2 = io.cmap ? io.cmap[gm2] : gm2;
#pragma unroll
            for (int j = 0; j < 8; j++) {
                int cb = col0 + n_w + j * 8 + q * 2;
                epi(acc[i][j][2], cr2, cb,     io.bias, act, io.resid, ldr, io.rowscale, rss, io.C, io.Ch, ldc, accum);
                epi(acc[i][j][3], cr2, cb + 1, io.bias, act, io.resid, ldr, io.rowscale, rss, io.C, io.Ch, ldc, accum);
            }
        }
    }
}

// ---------------- Flash attention (R13 numerics; heavy blocks launch first) ------------
__global__ void __launch_bounds__(256)
fa_kernel(const float* __restrict__ q, const float* __restrict__ k,
          const float* __restrict__ v, __half* __restrict__ attnh) {
    __shared__ uint32_t Ks[32][68];
    __shared__ uint32_t Vt[128][20];
    __shared__ uint32_t Ps[8][16][20];

    int bh = blockIdx.y;
    int b = bh / NH, h = bh % NH;
    int q0 = ((int)gridDim.x - 1 - (int)blockIdx.x) * 128;   // heavy (large q0) first
    int tid = threadIdx.x, w = tid >> 5, lane = tid & 31;
    int g = lane >> 2, qd = lane & 3;
    const float alpha = 0.08838834764831845f;

    const float* qb = q + ((size_t)b * SEQ) * DIM + h * HDIM;
    const float* kb_ = k + ((size_t)b * SEQ) * DIM + h * HDIM;
    const float* vb = v + ((size_t)b * SEQ) * DIM + h * HDIM;

    uint32_t qf[8][4];
    {
        const float* qr0 = qb + (size_t)(q0 + w * 16 + g) * DIM;
        const float* qr1 = qr0 + 8 * DIM;
#pragma unroll
        for (int ks = 0; ks < 8; ks++) {
            int c0 = (ks * 8 + qd) * 2, c1 = (ks * 8 + qd + 4) * 2;
            float2 t00 = *(const float2*)(qr0 + c0);
            float2 t10 = *(const float2*)(qr1 + c0);
            float2 t01 = *(const float2*)(qr0 + c1);
            float2 t11 = *(const float2*)(qr1 + c1);
            qf[ks][0] = pack_bf2(t00.x * alpha, t00.y * alpha);
            qf[ks][1] = pack_bf2(t10.x * alpha, t10.y * alpha);
            qf[ks][2] = pack_bf2(t01.x * alpha, t01.y * alpha);
            qf[ks][3] = pack_bf2(t11.x * alpha, t11.y * alpha);
        }
    }

    float m0 = -1e30f, m1 = -1e30f, l0 = 0.f, l1 = 0.f;
    float out[16][4];
#pragma unroll
    for (int i = 0; i < 16; i++)
#pragma unroll
        for (int r = 0; r < 4; r++) out[i][r] = 0.f;

    int ktiles = q0 / 32 + 4;

    for (int kt = 0; kt < ktiles; kt++) {
        int k0 = kt * 32;
        __syncthreads();
        for (int i = tid; i < 32 * 32; i += 256) {
            int r = i >> 5, c4 = i & 31;
            float4 tk = *(const float4*)(kb_ + (size_t)(k0 + r) * DIM + c4 * 4);
            Ks[r][c4 * 2]     = pack_bf2(tk.x, tk.y);
            Ks[r][c4 * 2 + 1] = pack_bf2(tk.z, tk.w);
            float4 tv = *(const float4*)(vb + (size_t)(k0 + r) * DIM + c4 * 4);
            uint16_t* vt = (uint16_t*)Vt;
            vt[(c4 * 4 + 0) * 40 + r] = bf16bits(tv.x);
            vt[(c4 * 4 + 1) * 40 + r] = bf16bits(tv.y);
            vt[(c4 * 4 + 2) * 40 + r] = bf16bits(tv.z);
            vt[(c4 * 4 + 3) * 40 + r] = bf16bits(tv.w);
        }
        __syncthreads();

        float sc[4][4];
#pragma unroll
        for (int nt = 0; nt < 4; nt++)
#pragma unroll
            for (int r = 0; r < 4; r++) sc[nt][r] = 0.f;
#pragma unroll
        for (int ks = 0; ks < 8; ks++) {
            int kp = ks * 8;
#pragma unroll
            for (int nt = 0; nt < 4; nt++) {
                uint32_t b0 = Ks[nt * 8 + g][kp + qd];
                uint32_t b1 = Ks[nt * 8 + g][kp + qd + 4];
                mma_bf16(sc[nt], qf[ks][0], qf[ks][1], qf[ks][2], qf[ks][3], b0, b1);
            }
        }

        if (k0 + 31 > q0) {
            int rq0 = q0 + w * 16 + g;
            int rq1 = rq0 + 8;
#pragma unroll
            for (int nt = 0; nt < 4; nt++) {
                int kc = k0 + nt * 8 + qd * 2;
                if (kc     > rq0) sc[nt][0] = -1e30f;
                if (kc + 1 > rq0) sc[nt][1] = -1e30f;
                if (kc     > rq1) sc[nt][2] = -1e30f;
                if (kc + 1 > rq1) sc[nt][3] = -1e30f;
            }
        }

        float tm0 = -1e30f, tm1 = -1e30f;
#pragma unroll
        for (int nt = 0; nt < 4; nt++) {
            tm0 = fmaxf(tm0, fmaxf(sc[nt][0], sc[nt][1]));
            tm1 = fmaxf(tm1, fmaxf(sc[nt][2], sc[nt][3]));
        }
        tm0 = fmaxf(tm0, __shfl_xor_sync(0xffffffffu, tm0, 1));
        tm0 = fmaxf(tm0, __shfl_xor_sync(0xffffffffu, tm0, 2));
        tm1 = fmaxf(tm1, __shfl_xor_sync(0xffffffffu, tm1, 1));
        tm1 = fmaxf(tm1, __shfl_xor_sync(0xffffffffu, tm1, 2));

        float mn0 = fmaxf(m0, tm0), mn1 = fmaxf(m1, tm1);
        bool chg = (mn0 != m0) || (mn1 != m1);
        if (__any_sync(0xffffffffu, chg)) {
            float corr0 = __expf(m0 - mn0), corr1 = __expf(m1 - mn1);
            l0 *= corr0; l1 *= corr1;
#pragma unroll
            for (int nt = 0; nt < 16; nt++) {
                out[nt][0] *= corr0; out[nt][1] *= corr0;
                out[nt][2] *= corr1; out[nt][3] *= corr1;
            }
        }
        m0 = mn0; m1 = mn1;

        float s0 = 0.f, s1 = 0.f;
#pragma unroll
        for (int nt = 0; nt < 4; nt++) {
            float p0 = __expf(sc[nt][0] - m0);
            float p1 = __expf(sc[nt][1] - m0);
            float p2 = __expf(sc[nt][2] - m1);
            float p3 = __expf(sc[nt][3] - m1);
            s0 += p0 + p1; s1 += p2 + p3;
            Ps[w][g][nt * 4 + qd]     = pack_bf2(p0, p1);
            Ps[w][g + 8][nt * 4 + qd] = pack_bf2(p2, p3);
        }
        s0 += __shfl_xor_sync(0xffffffffu, s0, 1);
        s0 += __shfl_xor_sync(0xffffffffu, s0, 2);
        s1 += __shfl_xor_sync(0xffffffffu, s1, 1);
        s1 += __shfl_xor_sync(0xffffffffu, s1, 2);
        l0 += s0; l1 += s1;
        __syncwarp();

#pragma unroll
        for (int ks = 0; ks < 2; ks++) {
            int kp = ks * 8;
            uint32_t a0 = Ps[w][g][kp + qd];
            uint32_t a1 = Ps[w][g + 8][kp + qd];
            uint32_t a2 = Ps[w][g][kp + qd + 4];
            uint32_t a3 = Ps[w][g + 8][kp + qd + 4];
#pragma unroll
            for (int nt = 0; nt < 16; nt++) {
                uint32_t b0 = Vt[nt * 8 + g][kp + qd];
                uint32_t b1 = Vt[nt * 8 + g][kp + qd + 4];
                mma_bf16(out[nt], a0, a1, a2, a3, b0, b1);
            }
        }
        __syncwarp();
    }

    float inv0 = 1.f / l0, inv1 = 1.f / l1;
    int r0g = q0 + w * 16 + g;
    __half* ob = attnh + ((size_t)b * SEQ) * DIM + h * HDIM;
#pragma unroll
    for (int nt = 0; nt < 16; nt++) {
        int c = nt * 8 + qd * 2;
        *(uint32_t*)(ob + (size_t)r0g * DIM + c) =
            pack_h2(out[nt][0] * inv0, out[nt][1] * inv0);
        *(uint32_t*)(ob + (size_t)(r0g + 8) * DIM + c) =
            pack_h2(out[nt][2] * inv1, out[nt][3] * inv1);
    }
}

// ---------------- MoE gate -------------------------------------------------------------
__global__ void gate_kernel(const float* __restrict__ x, const float* __restrict__ wg,
                            float* __restrict__ comb) {
    int t = blockIdx.x;
    int tid = threadIdx.x;
    __shared__ float red[NE * 128];
    const float* xr = x + (size_t)t * DIM;
    float acc[NE] = {0.f, 0.f, 0.f, 0.f};
    for (int d = tid; d < DIM; d += 128) {
        float xv = xr[d];
#pragma unroll
        for (int e = 0; e < NE; e++) acc[e] += xv * wg[(size_t)d * NE + e];
    }
#pragma unroll
    for (int e = 0; e < NE; e++) red[e * 128 + tid] = acc[e];
    __syncthreads();
    for (int o = 64; o > 0; o >>= 1) {
        if (tid < o) {
#pragma unroll
            for (int e = 0; e < NE; e++) red[e * 128 + tid] += red[e * 128 + tid + o];
        }
        __syncthreads();
    }
    if (tid == 0) {
        float l[NE];
#pragma unroll
        for (int e = 0; e < NE; e++) l[e] = red[e * 128];
        float mx = fmaxf(fmaxf(l[0], l[1]), fmaxf(l[2], l[3]));
        float ex[NE], s = 0.f;
#pragma unroll
        for (int e = 0; e < NE; e++) { ex[e] = expf(l[e] - mx); s += ex[e]; }
        float p[NE];
#pragma unroll
        for (int e = 0; e < NE; e++) p[e] = ex[e] / s;
        int i0 = 0;
#pragma unroll
        for (int e = 1; e < NE; e++) if (p[e] > p[i0]) i0 = e;
        int i1 = (i0 == 0) ? 1 : 0;
#pragma unroll
        for (int e = 0; e < NE; e++) if (e != i0 && p[e] > p[i1]) i1 = e;
        float e1 = expf(p[i1] - p[i0]);
        float invs = 1.f / (1.f + e1);
        float c[NE] = {0.f, 0.f, 0.f, 0.f};
        c[i0] = invs;
        c[i1] = e1 * invs;
#pragma unroll
        for (int e = 0; e < NE; e++) comb[(size_t)t * NE + e] = c[e];
    }
}

// ---------------- Routing --------------------------------------------------------------
__global__ void zero_cnt_kernel(int* cnt) {
    if (threadIdx.x < NE) cnt[threadIdx.x] = 0;
}
__global__ void route_kernel(const float* __restrict__ comb, int* __restrict__ cnt,
                             int* __restrict__ idx) {
    int t = blockIdx.x * blockDim.x + threadIdx.x;
    if (t >= NTOK) return;
#pragma unroll
    for (int e = 0; e < NE; e++) {
        if (comb[(size_t)t * NE + e] > 0.f) {
            int pos = atomicAdd(&cnt[e], 1);
            idx[e * NTOK + pos] = t;
        }
    }
}

// ---------------- host orchestration ---------------------------------------------------
extern "C" void kernel_launch(void* const* d_in, const int* in_sizes, int n_in,
                              void* d_out, int out_size) {
    (void)in_sizes; (void)n_in; (void)out_size;
    const float* hs   = (const float*)d_in[0];
    const float* wq   = (const float*)d_in[1];
    const float* bq   = (const float*)d_in[2];
    const float* wk   = (const float*)d_in[3];
    const float* bk   = (const float*)d_in[4];
    const float* wv   = (const float*)d_in[5];
    const float* bv   = (const float*)d_in[6];
    const float* wo   = (const float*)d_in[7];
    const float* bo   = (const float*)d_in[8];
    const float* ln1w = (const float*)d_in[9];
    const float* ln1b = (const float*)d_in[10];
    const float* ln2w = (const float*)d_in[11];
    const float* ln2b = (const float*)d_in[12];
    const float* wg   = (const float*)d_in[13];
    const float* we1  = (const float*)d_in[14];
    const float* be1  = (const float*)d_in[15];
    const float* we2  = (const float*)d_in[16];
    const float* be2  = (const float*)d_in[17];
    float* out = (float*)d_out;

    float *p_ln, *p_q, *p_k, *p_v, *p_comb;
    __half *p_lnh, *p_attnh, *p_hmidh, *p_wbf;
    int *p_cnt, *p_idx;
    float2* p_rope;
    cudaGetSymbolAddress((void**)&p_ln, g_ln);
    cudaGetSymbolAddress((void**)&p_lnh, g_lnh);
    cudaGetSymbolAddress((void**)&p_q, g_q);
    cudaGetSymbolAddress((void**)&p_k, g_k);
    cudaGetSymbolAddress((void**)&p_v, g_v);
    cudaGetSymbolAddress((void**)&p_attnh, g_attnh);
    cudaGetSymbolAddress((void**)&p_hmidh, g_hmidh);
    cudaGetSymbolAddress((void**)&p_comb, g_comb);
    cudaGetSymbolAddress((void**)&p_cnt, g_cnt);
    cudaGetSymbolAddress((void**)&p_idx, g_idx);
    cudaGetSymbolAddress((void**)&p_wbf, g_wbf);
    cudaGetSymbolAddress((void**)&p_rope, g_rope);

    size_t WSZ = (size_t)DIM * DIM;
    ZIO zn = {nullptr, nullptr, nullptr, nullptr, nullptr, nullptr, nullptr, nullptr};

    // 0. Weight prep + RoPE table
    dim3 gW(DIM / 32, DIM / 32, 12);
    wprep_kernel<<<gW, dim3(32, 8)>>>(wq, wk, wv, wo, we1, we2, p_wbf);
    rope_table_kernel<<<(SEQ * 64) / 256, 256>>>(p_rope);

    // 1. LN1
    ln_kernel<<<NTOK, 256>>>(hs, ln1w, ln1b, p_ln, p_lnh);

    // 2. QKV: one batched launch (z = 0,1,2)
    {
        ZIO zq = zn; zq.bias = bq; zq.C = p_q;
        ZIO zk = zn; zk.bias = bk; zk.C = p_k;
        ZIO zv = zn; zv.bias = bv; zv.C = p_v;
        dim3 grid(DIM / 128, NTOK / 128, 3);
        gemm_f16<<<grid, 128>>>(p_lnh, 0, DIM, p_wbf, WSZ, DIM,
                                zq, zk, zv, zn,
                                DIM, 0, 0, NTOK, DIM, DIM, 0, 0);
    }

    // 3. RoPE
    int nrope = NTOK * NH * 64;
    rope_kernel<<<(nrope + 255) / 256, 256>>>(p_q, p_k, p_rope);

    // 4. Flash attention
    dim3 gFA(SEQ / 128, BATCH * NH);
    fa_kernel<<<gFA, 256>>>(p_q, p_k, p_v, p_attnh);

    // 5. O-proj + bias + residual -> out (= h)
    {
        ZIO zo = zn; zo.bias = bo; zo.C = out; zo.resid = hs;
        dim3 grid(DIM / 128, NTOK / 128, 1);
        gemm_f16<<<grid, 128>>>(p_attnh, 0, DIM, p_wbf + 3 * WSZ, 0, DIM,
                                zo, zn, zn, zn,
                                DIM, DIM, 0, NTOK, DIM, DIM, 0, 0);
    }

    // 6. LN2
    ln_kernel<<<NTOK, 256>>>(out, ln2w, ln2b, p_ln, p_lnh);

    // 7. Gate + routing
    gate_kernel<<<NTOK, 128>>>(p_ln, wg, p_comb);
    zero_cnt_kernel<<<1, 32>>>(p_cnt);
    route_kernel<<<NTOK / 256, 256>>>(p_comb, p_cnt, p_idx);

    // 8a. Expert GEMM1 (all 4 experts, one launch): hmid_e = gelu(lnh[idx_e] @ we1_e + b1_e)
    {
        ZIO ze[4];
        for (int e = 0; e < NE; e++) {
            ze[e] = zn;
            ze[e].bias = be1 + (size_t)e * IDIM;
            ze[e].Ch = p_hmidh + (size_t)e * NTOK * IDIM;
            ze[e].amap = p_idx + e * NTOK;
            ze[e].mcount = p_cnt + e;
        }
        dim3 grid(IDIM / 128, NTOK / 128, NE);
        gemm_f16<<<grid, 128>>>(p_lnh, 0, DIM, p_wbf + 4 * WSZ, WSZ, DIM,
                                ze[0], ze[1], ze[2], ze[3],
                                IDIM, 0, 0, NTOK, IDIM, DIM, 1, 0);
    }

    // 8b. Expert GEMM2 (all 4 experts, one launch, atomic accumulate into out)
    {
        ZIO ze[4];
        for (int e = 0; e < NE; e++) {
            ze[e] = zn;
            ze[e].bias = be2 + (size_t)e * DIM;
            ze[e].C = out;
            ze[e].rowscale = p_comb + e;
            ze[e].cmap = p_idx + e * NTOK;
            ze[e].mcount = p_cnt + e;
        }
        dim3 grid(DIM / 128, NTOK / 128, NE);
        gemm_f16<<<grid, 128>>>(p_hmidh, (size_t)NTOK * IDIM, IDIM,
                                p_wbf + 8 * WSZ, WSZ, IDIM,
                                ze[0], ze[1], ze[2], ze[3],
                                DIM, 0, NE, NTOK, DIM, IDIM, 0, 2);
    }
}

// round 16
// speedup vs baseline: 2.1814x; 1.0471x over previous
#include <cuda_runtime.h>
#include <cuda_bf16.h>
#include <cuda_fp16.h>
#include <math.h>
#include <stdint.h>

#define BATCH 2
#define SEQ   2048
#define DIM   2048
#define NH    16
#define HDIM  128
#define NE    4
#define IDIM  2048
#define NTOK  (BATCH*SEQ)   // 4096

// ---------------- scratch (static device globals) ----
__device__ float  g_ln   [(size_t)NTOK*DIM];
__device__ __half g_lnh  [(size_t)NTOK*DIM];
__device__ float  g_q    [(size_t)NTOK*DIM];
__device__ float  g_k    [(size_t)NTOK*DIM];
__device__ float  g_v    [(size_t)NTOK*DIM];
__device__ __half g_attnh[(size_t)NTOK*DIM];
__device__ __half g_hmidh[(size_t)NE*NTOK*IDIM];  // per-expert hidden (64 MB)
__device__ float  g_comb [(size_t)NTOK*NE];
__device__ int    g_cnt  [NE];
__device__ int    g_idx  [NE*NTOK];
__device__ __half g_wbf  [(size_t)12*DIM*DIM];
__device__ float2 g_rope [(size_t)SEQ*64];

struct ZIO {
    const float* bias;
    float* C;
    __half* Ch;
    const float* resid;
    const float* rowscale;
    const int* amap;
    const int* cmap;
    const int* mcount;
};

__device__ __forceinline__ void mma_f16(float d[4], uint32_t a0, uint32_t a1,
                                        uint32_t a2, uint32_t a3,
                                        uint32_t b0, uint32_t b1) {
    asm volatile(
        "mma.sync.aligned.m16n8k16.row.col.f32.f16.f16.f32 "
        "{%0,%1,%2,%3}, {%4,%5,%6,%7}, {%8,%9}, {%0,%1,%2,%3};"
        : "+f"(d[0]), "+f"(d[1]), "+f"(d[2]), "+f"(d[3])
        : "r"(a0), "r"(a1), "r"(a2), "r"(a3), "r"(b0), "r"(b1));
}

__device__ __forceinline__ void mma_bf16(float d[4], uint32_t a0, uint32_t a1,
                                         uint32_t a2, uint32_t a3,
                                         uint32_t b0, uint32_t b1) {
    asm volatile(
        "mma.sync.aligned.m16n8k16.row.col.f32.bf16.bf16.f32 "
        "{%0,%1,%2,%3}, {%4,%5,%6,%7}, {%8,%9}, {%0,%1,%2,%3};"
        : "+f"(d[0]), "+f"(d[1]), "+f"(d[2]), "+f"(d[3])
        : "r"(a0), "r"(a1), "r"(a2), "r"(a3), "r"(b0), "r"(b1));
}

__device__ __forceinline__ uint32_t pack_bf2(float lo, float hi) {
    __nv_bfloat162 t = __floats2bfloat162_rn(lo, hi);
    return *(uint32_t*)&t;
}
__device__ __forceinline__ uint32_t pack_h2(float lo, float hi) {
    __half2 t = __floats2half2_rn(lo, hi);
    return *(uint32_t*)&t;
}
__device__ __forceinline__ uint16_t bf16bits(float x) {
    __nv_bfloat16 t = __float2bfloat16_rn(x);
    return *(uint16_t*)&t;
}
__device__ __forceinline__ void cp_async16(uint32_t saddr, const void* g) {
    asm volatile("cp.async.cg.shared.global [%0], [%1], 16;" :: "r"(saddr), "l"(g) : "memory");
}

// ---------------- Weight prep ----------------------------------------------------------
__global__ void wprep_kernel(const float* __restrict__ wq, const float* __restrict__ wk,
                             const float* __restrict__ wv, const float* __restrict__ wo,
                             const float* __restrict__ we1, const float* __restrict__ we2,
                             __half* __restrict__ wbf) {
    int z = blockIdx.z;
    const float* src;
    if (z == 0) src = wq;
    else if (z == 1) src = wk;
    else if (z == 2) src = wv;
    else if (z == 3) src = wo;
    else if (z < 8) src = we1 + (size_t)(z - 4) * DIM * IDIM;
    else src = we2 + (size_t)(z - 8) * IDIM * DIM;
    __half* dst = wbf + (size_t)z * DIM * DIM;
    __shared__ float tile[32][33];
    int k0 = blockIdx.y * 32, n0 = blockIdx.x * 32;
    int tx = threadIdx.x, ty = threadIdx.y;
#pragma unroll
    for (int r = ty; r < 32; r += 8)
        tile[r][tx] = src[(size_t)(k0 + r) * DIM + n0 + tx];
    __syncthreads();
#pragma unroll
    for (int r = ty; r < 32; r += 8)
        dst[(size_t)(n0 + r) * DIM + k0 + tx] = __float2half_rn(tile[tx][r]);
}

// ---------------- RoPE table -----------------------------------------------------------
__global__ void rope_table_kernel(float2* __restrict__ tab) {
    int idx = blockIdx.x * blockDim.x + threadIdx.x;
    if (idx >= SEQ * 64) return;
    int i = idx & 63;
    int s = idx >> 6;
    float invf = (float)(1.0 / pow(10000.0, (double)i / 64.0));
    float ang = (float)s * invf;
    double angd = (double)ang;
    tab[idx] = make_float2((float)cos(angd), (float)sin(angd));
}

// ---------------- RoPE apply -----------------------------------------------------------
__global__ void rope_kernel(float* __restrict__ q, float* __restrict__ k,
                            const float2* __restrict__ tab) {
    int idx = blockIdx.x * blockDim.x + threadIdx.x;
    if (idx >= NTOK * NH * 64) return;
    int i = idx & 63;
    int rem = idx >> 6;
    int h = rem % NH;
    int t = rem / NH;
    int s = t % SEQ;
    float2 cs = tab[s * 64 + i];
    float c = cs.x, sn = cs.y;
    size_t base = (size_t)t * DIM + (size_t)h * HDIM;
    float q1 = q[base + i], q2 = q[base + 64 + i];
    q[base + i]      = q1 * c - q2 * sn;
    q[base + 64 + i] = q2 * c + q1 * sn;
    float k1 = k[base + i], k2 = k[base + 64 + i];
    k[base + i]      = k1 * c - k2 * sn;
    k[base + 64 + i] = k2 * c + k1 * sn;
}

// ---------------- LayerNorm ------------------------------------------------------------
__global__ void ln_kernel(const float* __restrict__ x, const float* __restrict__ w,
                          const float* __restrict__ b, float* __restrict__ y,
                          __half* __restrict__ yh) {
    int row = blockIdx.x;
    const float* xr = x + (size_t)row * DIM;
    float* yr = y + (size_t)row * DIM;
    __half* yhr = yh + (size_t)row * DIM;
    __shared__ float red[256];
    int tid = threadIdx.x;
    float s = 0.f;
    for (int i = tid; i < DIM; i += 256) s += xr[i];
    red[tid] = s; __syncthreads();
    for (int o = 128; o > 0; o >>= 1) { if (tid < o) red[tid] += red[tid + o]; __syncthreads(); }
    float mu = red[0] * (1.f / DIM);
    __syncthreads();
    float v = 0.f;
    for (int i = tid; i < DIM; i += 256) { float d = xr[i] - mu; v += d * d; }
    red[tid] = v; __syncthreads();
    for (int o = 128; o > 0; o >>= 1) { if (tid < o) red[tid] += red[tid + o]; __syncthreads(); }
    float inv = rsqrtf(red[0] * (1.f / DIM) + 1e-5f);
    for (int i = tid; i < DIM; i += 256) {
        float val = (xr[i] - mu) * inv * w[i] + b[i];
        yr[i] = val;
        yhr[i] = __float2half_rn(val);
    }
}

// ---------------- FP16 GEMM, cp.async 3-stage, single sync/iter, batched over z --------
__device__ __forceinline__ void epi(float v, int gm, int gn,
                                    const float* bias, int act,
                                    const float* resid, int ldr,
                                    const float* rowscale, int rss,
                                    float* C, __half* Ch, int ldc, int accum) {
    if (bias) v += bias[gn];
    if (act) v = 0.5f * v * (1.f + erff(v * 0.70710678118654752f));
    if (resid) v += resid[(size_t)gm * ldr + gn];
    if (rowscale) v *= rowscale[(size_t)gm * rss];
    size_t o = (size_t)gm * ldc + gn;
    if (C) {
        if (accum == 2) atomicAdd(&C[o], v);
        else if (accum == 1) C[o] += v;
        else C[o] = v;
    }
    if (Ch) Ch[o] = __float2half_rn(v);
}

#define GF_AU32   (128 * 20)                 // A stage, uint32 words
#define GF_SU32   (2 * GF_AU32)              // full stage (A+B)
#define GF_SBYTES (GF_SU32 * 4)              // 20480 B
#define GF_SMEM   (3 * GF_SBYTES)            // 61440 B dynamic

__global__ void __launch_bounds__(128)
gemm_f16(const __half* __restrict__ Abase, size_t strideAz, int lda,
         const __half* __restrict__ Bbase, size_t strideBz, int ldb,
         ZIO z0, ZIO z1, ZIO z2, ZIO z3,
         int ldc, int ldr, int rss,
         int M, int N, int K, int act, int accum) {
    extern __shared__ uint32_t smbuf[];
    int z = blockIdx.z;
    ZIO io = (z == 0) ? z0 : ((z == 1) ? z1 : ((z == 2) ? z2 : z3));
    const __half* A = Abase + (size_t)z * strideAz;
    const __half* Bt = Bbase + (size_t)z * strideBz;

    int M_eff = io.mcount ? *io.mcount : M;
    int row0 = blockIdx.y * 128, col0 = blockIdx.x * 128;
    if (row0 >= M_eff) return;

    int tid = threadIdx.x;
    int w = tid >> 5, lane = tid & 31;
    int wm = w >> 1, wn = w & 1;
    int m_w = wm * 64, n_w = wn * 64;
    int g = lane >> 2, q = lane & 3;

    float acc[4][8][4];
#pragma unroll
    for (int i = 0; i < 4; i++)
#pragma unroll
        for (int j = 0; j < 8; j++)
#pragma unroll
            for (int r = 0; r < 4; r++) acc[i][j][r] = 0.f;

    const __half *Apt[4], *Bpt[4];
    uint32_t offS[4];
#pragma unroll
    for (int j = 0; j < 4; j++) {
        int cidx = tid + j * 128;
        int row = cidx >> 2, ch = cidx & 3;
        int gm = row0 + row;
        int cl = gm < M_eff ? gm : M_eff - 1;
        int ar = io.amap ? io.amap[cl] : cl;
        Apt[j] = A + (size_t)ar * lda + ch * 8;
        Bpt[j] = Bt + (size_t)(col0 + row) * ldb + ch * 8;
        offS[j] = (uint32_t)(row * 20 + ch * 4) * 4;
    }
    uint32_t base0 = (uint32_t)__cvta_generic_to_shared(smbuf);

    int nk = K / 32;

#define GEMM_ISSUE(T_) do {                                            \
        int tt = (T_);                                                 \
        if (tt < nk) {                                                 \
            int st_ = tt % 3;                                          \
            int k0_ = tt * 32;                                         \
            uint32_t ab = base0 + st_ * GF_SBYTES;                     \
            uint32_t bb = ab + GF_AU32 * 4;                            \
            _Pragma("unroll")                                          \
            for (int j = 0; j < 4; j++) {                              \
                cp_async16(ab + offS[j], Apt[j] + k0_);                \
                cp_async16(bb + offS[j], Bpt[j] + k0_);                \
            }                                                          \
        }                                                              \
        asm volatile("cp.async.commit_group;" ::: "memory");           \
    } while (0)

    GEMM_ISSUE(0);
    GEMM_ISSUE(1);
    for (int t = 0; t < nk; t++) {
        asm volatile("cp.async.wait_group 1;" ::: "memory");  // tile t data complete
        __syncthreads();   // data visible; all warps done with compute(t-1)
        GEMM_ISSUE(t + 2); // stage (t+2)%3 — last read at compute(t-1), fenced above
        int st = t % 3;
        const uint32_t (*As)[20] = (const uint32_t (*)[20])(smbuf + st * GF_SU32);
        const uint32_t (*Bs)[20] = (const uint32_t (*)[20])(smbuf + st * GF_SU32 + GF_AU32);

#pragma unroll
        for (int ks = 0; ks < 2; ks++) {
            int kp = ks * 8;
            uint32_t af[4][4], bf[8][2];
#pragma unroll
            for (int i = 0; i < 4; i++) {
                int r = m_w + i * 16 + g;
                af[i][0] = As[r][kp + q];
                af[i][1] = As[r + 8][kp + q];
                af[i][2] = As[r][kp + q + 4];
                af[i][3] = As[r + 8][kp + q + 4];
            }
#pragma unroll
            for (int j = 0; j < 8; j++) {
                int c = n_w + j * 8 + g;
                bf[j][0] = Bs[c][kp + q];
                bf[j][1] = Bs[c][kp + q + 4];
            }
#pragma unroll
            for (int i = 0; i < 4; i++)
#pragma unroll
                for (int j = 0; j < 8; j++)
                    mma_f16(acc[i][j], af[i][0], af[i][1], af[i][2], af[i][3],
                            bf[j][0], bf[j][1]);
        }
    }
#undef GEMM_ISSUE

#pragma unroll
    for (int i = 0; i < 4; i++) {
        int gm = row0 + m_w + i * 16 + g;
        if (gm < M_eff) {
            int cr = io.cmap ? io.cmap[gm] : gm;
#pragma unroll
            for (int j = 0; j < 8; j++) {
                int cb = col0 + n_w + j * 8 + q * 2;
                epi(acc[i][j][0], cr, cb,     io.bias, act, io.resid, ldr, io.rowscale, rss, io.C, io.Ch, ldc, accum);
                epi(acc[i][j][1], cr, cb + 1, io.bias, act, io.resid, ldr, io.rowscale, rss, io.C, io.Ch, ldc, accum);
            }
        }
        int gm2 = gm + 8;
        if (gm2 < M_eff) {
            int cr2 = io.cmap ? io.cmap[gm2] : gm2;
#pragma unroll
            for (int j = 0; j < 8; j++) {
                int cb = col0 + n_w + j * 8 + q * 2;
                epi(acc[i][j][2], cr2, cb,     io.bias, act, io.resid, ldr, io.rowscale, rss, io.C, io.Ch, ldc, accum);
                epi(acc[i][j][3], cr2, cb + 1, io.bias, act, io.resid, ldr, io.rowscale, rss, io.C, io.Ch, ldc, accum);
            }
        }
    }
}

// ---------------- Flash attention (R14, proven) ----------------------------------------
__global__ void __launch_bounds__(256)
fa_kernel(const float* __restrict__ q, const float* __restrict__ k,
          const float* __restrict__ v, __half* __restrict__ attnh) {
    __shared__ uint32_t Ks[32][68];
    __shared__ uint32_t Vt[128][20];
    __shared__ uint32_t Ps[8][16][20];

    int bh = blockIdx.y;
    int b = bh / NH, h = bh % NH;
    int q0 = ((int)gridDim.x - 1 - (int)blockIdx.x) * 128;   // heavy blocks first
    int tid = threadIdx.x, w = tid >> 5, lane = tid & 31;
    int g = lane >> 2, qd = lane & 3;
    const float alpha = 0.08838834764831845f;

    const float* qb = q + ((size_t)b * SEQ) * DIM + h * HDIM;
    const float* kb_ = k + ((size_t)b * SEQ) * DIM + h * HDIM;
    const float* vb = v + ((size_t)b * SEQ) * DIM + h * HDIM;

    uint32_t qf[8][4];
    {
        const float* qr0 = qb + (size_t)(q0 + w * 16 + g) * DIM;
        const float* qr1 = qr0 + 8 * DIM;
#pragma unroll
        for (int ks = 0; ks < 8; ks++) {
            int c0 = (ks * 8 + qd) * 2, c1 = (ks * 8 + qd + 4) * 2;
            float2 t00 = *(const float2*)(qr0 + c0);
            float2 t10 = *(const float2*)(qr1 + c0);
            float2 t01 = *(const float2*)(qr0 + c1);
            float2 t11 = *(const float2*)(qr1 + c1);
            qf[ks][0] = pack_bf2(t00.x * alpha, t00.y * alpha);
            qf[ks][1] = pack_bf2(t10.x * alpha, t10.y * alpha);
            qf[ks][2] = pack_bf2(t01.x * alpha, t01.y * alpha);
            qf[ks][3] = pack_bf2(t11.x * alpha, t11.y * alpha);
        }
    }

    float m0 = -1e30f, m1 = -1e30f, l0 = 0.f, l1 = 0.f;
    float out[16][4];
#pragma unroll
    for (int i = 0; i < 16; i++)
#pragma unroll
        for (int r = 0; r < 4; r++) out[i][r] = 0.f;

    int ktiles = q0 / 32 + 4;

    for (int kt = 0; kt < ktiles; kt++) {
        int k0 = kt * 32;
        __syncthreads();
        for (int i = tid; i < 32 * 32; i += 256) {
            int r = i >> 5, c4 = i & 31;
            float4 tk = *(const float4*)(kb_ + (size_t)(k0 + r) * DIM + c4 * 4);
            Ks[r][c4 * 2]     = pack_bf2(tk.x, tk.y);
            Ks[r][c4 * 2 + 1] = pack_bf2(tk.z, tk.w);
            float4 tv = *(const float4*)(vb + (size_t)(k0 + r) * DIM + c4 * 4);
            uint16_t* vt = (uint16_t*)Vt;
            vt[(c4 * 4 + 0) * 40 + r] = bf16bits(tv.x);
            vt[(c4 * 4 + 1) * 40 + r] = bf16bits(tv.y);
            vt[(c4 * 4 + 2) * 40 + r] = bf16bits(tv.z);
            vt[(c4 * 4 + 3) * 40 + r] = bf16bits(tv.w);
        }
        __syncthreads();

        float sc[4][4];
#pragma unroll
        for (int nt = 0; nt < 4; nt++)
#pragma unroll
            for (int r = 0; r < 4; r++) sc[nt][r] = 0.f;
#pragma unroll
        for (int ks = 0; ks < 8; ks++) {
            int kp = ks * 8;
#pragma unroll
            for (int nt = 0; nt < 4; nt++) {
                uint32_t b0 = Ks[nt * 8 + g][kp + qd];
                uint32_t b1 = Ks[nt * 8 + g][kp + qd + 4];
                mma_bf16(sc[nt], qf[ks][0], qf[ks][1], qf[ks][2], qf[ks][3], b0, b1);
            }
        }

        if (k0 + 31 > q0) {
            int rq0 = q0 + w * 16 + g;
            int rq1 = rq0 + 8;
#pragma unroll
            for (int nt = 0; nt < 4; nt++) {
                int kc = k0 + nt * 8 + qd * 2;
                if (kc     > rq0) sc[nt][0] = -1e30f;
                if (kc + 1 > rq0) sc[nt][1] = -1e30f;
                if (kc     > rq1) sc[nt][2] = -1e30f;
                if (kc + 1 > rq1) sc[nt][3] = -1e30f;
            }
        }

        float tm0 = -1e30f, tm1 = -1e30f;
#pragma unroll
        for (int nt = 0; nt < 4; nt++) {
            tm0 = fmaxf(tm0, fmaxf(sc[nt][0], sc[nt][1]));
            tm1 = fmaxf(tm1, fmaxf(sc[nt][2], sc[nt][3]));
        }
        tm0 = fmaxf(tm0, __shfl_xor_sync(0xffffffffu, tm0, 1));
        tm0 = fmaxf(tm0, __shfl_xor_sync(0xffffffffu, tm0, 2));
        tm1 = fmaxf(tm1, __shfl_xor_sync(0xffffffffu, tm1, 1));
        tm1 = fmaxf(tm1, __shfl_xor_sync(0xffffffffu, tm1, 2));

        float mn0 = fmaxf(m0, tm0), mn1 = fmaxf(m1, tm1);
        bool chg = (mn0 != m0) || (mn1 != m1);
        if (__any_sync(0xffffffffu, chg)) {
            float corr0 = __expf(m0 - mn0), corr1 = __expf(m1 - mn1);
            l0 *= corr0; l1 *= corr1;
#pragma unroll
            for (int nt = 0; nt < 16; nt++) {
                out[nt][0] *= corr0; out[nt][1] *= corr0;
                out[nt][2] *= corr1; out[nt][3] *= corr1;
            }
        }
        m0 = mn0; m1 = mn1;

        float s0 = 0.f, s1 = 0.f;
#pragma unroll
        for (int nt = 0; nt < 4; nt++) {
            float p0 = __expf(sc[nt][0] - m0);
            float p1 = __expf(sc[nt][1] - m0);
            float p2 = __expf(sc[nt][2] - m1);
            float p3 = __expf(sc[nt][3] - m1);
            s0 += p0 + p1; s1 += p2 + p3;
            Ps[w][g][nt * 4 + qd]     = pack_bf2(p0, p1);
            Ps[w][g + 8][nt * 4 + qd] = pack_bf2(p2, p3);
        }
        s0 += __shfl_xor_sync(0xffffffffu, s0, 1);
        s0 += __shfl_xor_sync(0xffffffffu, s0, 2);
        s1 += __shfl_xor_sync(0xffffffffu, s1, 1);
        s1 += __shfl_xor_sync(0xffffffffu, s1, 2);
        l0 += s0; l1 += s1;
        __syncwarp();

#pragma unroll
        for (int ks = 0; ks < 2; ks++) {
            int kp = ks * 8;
            uint32_t a0 = Ps[w][g][kp + qd];
            uint32_t a1 = Ps[w][g + 8][kp + qd];
            uint32_t a2 = Ps[w][g][kp + qd + 4];
            uint32_t a3 = Ps[w][g + 8][kp + qd + 4];
#pragma unroll
            for (int nt = 0; nt < 16; nt++) {
                uint32_t b0 = Vt[nt * 8 + g][kp + qd];
                uint32_t b1 = Vt[nt * 8 + g][kp + qd + 4];
                mma_bf16(out[nt], a0, a1, a2, a3, b0, b1);
            }
        }
        __syncwarp();
    }

    float inv0 = 1.f / l0, inv1 = 1.f / l1;
    int r0g = q0 + w * 16 + g;
    __half* ob = attnh + ((size_t)b * SEQ) * DIM + h * HDIM;
#pragma unroll
    for (int nt = 0; nt < 16; nt++) {
        int c = nt * 8 + qd * 2;
        *(uint32_t*)(ob + (size_t)r0g * DIM + c) =
            pack_h2(out[nt][0] * inv0, out[nt][1] * inv0);
        *(uint32_t*)(ob + (size_t)(r0g + 8) * DIM + c) =
            pack_h2(out[nt][2] * inv1, out[nt][3] * inv1);
    }
}

// ---------------- MoE gate -------------------------------------------------------------
__global__ void gate_kernel(const float* __restrict__ x, const float* __restrict__ wg,
                            float* __restrict__ comb) {
    int t = blockIdx.x;
    int tid = threadIdx.x;
    __shared__ float red[NE * 128];
    const float* xr = x + (size_t)t * DIM;
    float acc[NE] = {0.f, 0.f, 0.f, 0.f};
    for (int d = tid; d < DIM; d += 128) {
        float xv = xr[d];
#pragma unroll
        for (int e = 0; e < NE; e++) acc[e] += xv * wg[(size_t)d * NE + e];
    }
#pragma unroll
    for (int e = 0; e < NE; e++) red[e * 128 + tid] = acc[e];
    __syncthreads();
    for (int o = 64; o > 0; o >>= 1) {
        if (tid < o) {
#pragma unroll
            for (int e = 0; e < NE; e++) red[e * 128 + tid] += red[e * 128 + tid + o];
        }
        __syncthreads();
    }
    if (tid == 0) {
        float l[NE];
#pragma unroll
        for (int e = 0; e < NE; e++) l[e] = red[e * 128];
        float mx = fmaxf(fmaxf(l[0], l[1]), fmaxf(l[2], l[3]));
        float ex[NE], s = 0.f;
#pragma unroll
        for (int e = 0; e < NE; e++) { ex[e] = expf(l[e] - mx); s += ex[e]; }
        float p[NE];
#pragma unroll
        for (int e = 0; e < NE; e++) p[e] = ex[e] / s;
        int i0 = 0;
#pragma unroll
        for (int e = 1; e < NE; e++) if (p[e] > p[i0]) i0 = e;
        int i1 = (i0 == 0) ? 1 : 0;
#pragma unroll
        for (int e = 0; e < NE; e++) if (e != i0 && p[e] > p[i1]) i1 = e;
        float e1 = expf(p[i1] - p[i0]);
        float invs = 1.f / (1.f + e1);
        float c[NE] = {0.f, 0.f, 0.f, 0.f};
        c[i0] = invs;
        c[i1] = e1 * invs;
#pragma unroll
        for (int e = 0; e < NE; e++) comb[(size_t)t * NE + e] = c[e];
    }
}

// ---------------- Routing --------------------------------------------------------------
__global__ void zero_cnt_kernel(int* cnt) {
    if (threadIdx.x < NE) cnt[threadIdx.x] = 0;
}
__global__ void route_kernel(const float* __restrict__ comb, int* __restrict__ cnt,
                             int* __restrict__ idx) {
    int t = blockIdx.x * blockDim.x + threadIdx.x;
    if (t >= NTOK) return;
#pragma unroll
    for (int e = 0; e < NE; e++) {
        if (comb[(size_t)t * NE + e] > 0.f) {
            int pos = atomicAdd(&cnt[e], 1);
            idx[e * NTOK + pos] = t;
        }
    }
}

// ---------------- host orchestration ---------------------------------------------------
extern "C" void kernel_launch(void* const* d_in, const int* in_sizes, int n_in,
                              void* d_out, int out_size) {
    (void)in_sizes; (void)n_in; (void)out_size;
    const float* hs   = (const float*)d_in[0];
    const float* wq   = (const float*)d_in[1];
    const float* bq   = (const float*)d_in[2];
    const float* wk   = (const float*)d_in[3];
    const float* bk   = (const float*)d_in[4];
    const float* wv   = (const float*)d_in[5];
    const float* bv   = (const float*)d_in[6];
    const float* wo   = (const float*)d_in[7];
    const float* bo   = (const float*)d_in[8];
    const float* ln1w = (const float*)d_in[9];
    const float* ln1b = (const float*)d_in[10];
    const float* ln2w = (const float*)d_in[11];
    const float* ln2b = (const float*)d_in[12];
    const float* wg   = (const float*)d_in[13];
    const float* we1  = (const float*)d_in[14];
    const float* be1  = (const float*)d_in[15];
    const float* we2  = (const float*)d_in[16];
    const float* be2  = (const float*)d_in[17];
    float* out = (float*)d_out;

    float *p_ln, *p_q, *p_k, *p_v, *p_comb;
    __half *p_lnh, *p_attnh, *p_hmidh, *p_wbf;
    int *p_cnt, *p_idx;
    float2* p_rope;
    cudaGetSymbolAddress((void**)&p_ln, g_ln);
    cudaGetSymbolAddress((void**)&p_lnh, g_lnh);
    cudaGetSymbolAddress((void**)&p_q, g_q);
    cudaGetSymbolAddress((void**)&p_k, g_k);
    cudaGetSymbolAddress((void**)&p_v, g_v);
    cudaGetSymbolAddress((void**)&p_attnh, g_attnh);
    cudaGetSymbolAddress((void**)&p_hmidh, g_hmidh);
    cudaGetSymbolAddress((void**)&p_comb, g_comb);
    cudaGetSymbolAddress((void**)&p_cnt, g_cnt);
    cudaGetSymbolAddress((void**)&p_idx, g_idx);
    cudaGetSymbolAddress((void**)&p_wbf, g_wbf);
    cudaGetSymbolAddress((void**)&p_rope, g_rope);

    cudaFuncSetAttribute(gemm_f16, cudaFuncAttributeMaxDynamicSharedMemorySize, GF_SMEM);

    size_t WSZ = (size_t)DIM * DIM;
    ZIO zn = {nullptr, nullptr, nullptr, nullptr, nullptr, nullptr, nullptr, nullptr};

    // 0. Weight prep + RoPE table
    dim3 gW(DIM / 32, DIM / 32, 12);
    wprep_kernel<<<gW, dim3(32, 8)>>>(wq, wk, wv, wo, we1, we2, p_wbf);
    rope_table_kernel<<<(SEQ * 64) / 256, 256>>>(p_rope);

    // 1. LN1
    ln_kernel<<<NTOK, 256>>>(hs, ln1w, ln1b, p_ln, p_lnh);

    // 2. QKV: one batched launch (z = 0,1,2)
    {
        ZIO zq = zn; zq.bias = bq; zq.C = p_q;
        ZIO zk = zn; zk.bias = bk; zk.C = p_k;
        ZIO zv = zn; zv.bias = bv; zv.C = p_v;
        dim3 grid(DIM / 128, NTOK / 128, 3);
        gemm_f16<<<grid, 128, GF_SMEM>>>(p_lnh, 0, DIM, p_wbf, WSZ, DIM,
                                         zq, zk, zv, zn,
                                         DIM, 0, 0, NTOK, DIM, DIM, 0, 0);
    }

    // 3. RoPE
    int nrope = NTOK * NH * 64;
    rope_kernel<<<(nrope + 255) / 256, 256>>>(p_q, p_k, p_rope);

    // 4. Flash attention
    dim3 gFA(SEQ / 128, BATCH * NH);
    fa_kernel<<<gFA, 256>>>(p_q, p_k, p_v, p_attnh);

    // 5. O-proj + bias + residual -> out (= h)
    {
        ZIO zo = zn; zo.bias = bo; zo.C = out; zo.resid = hs;
        dim3 grid(DIM / 128, NTOK / 128, 1);
        gemm_f16<<<grid, 128, GF_SMEM>>>(p_attnh, 0, DIM, p_wbf + 3 * WSZ, 0, DIM,
                                         zo, zn, zn, zn,
                                         DIM, DIM, 0, NTOK, DIM, DIM, 0, 0);
    }

    // 6. LN2
    ln_kernel<<<NTOK, 256>>>(out, ln2w, ln2b, p_ln, p_lnh);

    // 7. Gate + routing
    gate_kernel<<<NTOK, 128>>>(p_ln, wg, p_comb);
    zero_cnt_kernel<<<1, 32>>>(p_cnt);
    route_kernel<<<NTOK / 256, 256>>>(p_comb, p_cnt, p_idx);

    // 8a. Expert GEMM1 (all 4 experts, one launch)
    {
        ZIO ze[4];
        for (int e = 0; e < NE; e++) {
            ze[e] = zn;
            ze[e].bias = be1 + (size_t)e * IDIM;
            ze[e].Ch = p_hmidh + (size_t)e * NTOK * IDIM;
            ze[e].amap = p_idx + e * NTOK;
            ze[e].mcount = p_cnt + e;
        }
        dim3 grid(IDIM / 128, NTOK / 128, NE);
        gemm_f16<<<grid, 128, GF_SMEM>>>(p_lnh, 0, DIM, p_wbf + 4 * WSZ, WSZ, DIM,
                                         ze[0], ze[1], ze[2], ze[3],
                                         IDIM, 0, 0, NTOK, IDIM, DIM, 1, 0);
    }

    // 8b. Expert GEMM2 (all 4 experts, one launch, atomic accumulate into out)
    {
        ZIO ze[4];
        for (int e = 0; e < NE; e++) {
            ze[e] = zn;
            ze[e].bias = be2 + (size_t)e * DIM;
            ze[e].C = out;
            ze[e].rowscale = p_comb + e;
            ze[e].cmap = p_idx + e * NTOK;
            ze[e].mcount = p_cnt + e;
        }
        dim3 grid(DIM / 128, NTOK / 128, NE);
        gemm_f16<<<grid, 128, GF_SMEM>>>(p_hmidh, (size_t)NTOK * IDIM, IDIM,
                                         p_wbf + 8 * WSZ, WSZ, IDIM,
                                         ze[0], ze[1], ze[2], ze[3],
                                         DIM, 0, NE, NTOK, DIM, IDIM, 0, 2);
    }
}

// round 17
// speedup vs baseline: 2.2049x; 1.0108x over previous
#include <cuda_runtime.h>
#include <cuda_bf16.h>
#include <cuda_fp16.h>
#include <math.h>
#include <stdint.h>

#define BATCH 2
#define SEQ   2048
#define DIM   2048
#define NH    16
#define HDIM  128
#define NE    4
#define IDIM  2048
#define NTOK  (BATCH*SEQ)   // 4096

// ---------------- scratch (static device globals) ----
__device__ float  g_ln   [(size_t)NTOK*DIM];
__device__ __half g_lnh  [(size_t)NTOK*DIM];
__device__ float  g_q    [(size_t)NTOK*DIM];
__device__ float  g_k    [(size_t)NTOK*DIM];
__device__ float  g_v    [(size_t)NTOK*DIM];
__device__ __half g_attnh[(size_t)NTOK*DIM];
__device__ __half g_hmidh[(size_t)NE*NTOK*IDIM];  // per-expert hidden (64 MB)
__device__ float  g_comb [(size_t)NTOK*NE];
__device__ int    g_cnt  [NE];
__device__ int    g_idx  [NE*NTOK];
__device__ __half g_wbf  [(size_t)12*DIM*DIM];
__device__ float2 g_rope [(size_t)SEQ*64];

struct ZIO {
    const float* bias;
    float* C;
    __half* Ch;
    const float* resid;
    const float* rowscale;
    const int* amap;
    const int* cmap;
    const int* mcount;
};

__device__ __forceinline__ void mma_f16(float d[4], uint32_t a0, uint32_t a1,
                                        uint32_t a2, uint32_t a3,
                                        uint32_t b0, uint32_t b1) {
    asm volatile(
        "mma.sync.aligned.m16n8k16.row.col.f32.f16.f16.f32 "
        "{%0,%1,%2,%3}, {%4,%5,%6,%7}, {%8,%9}, {%0,%1,%2,%3};"
        : "+f"(d[0]), "+f"(d[1]), "+f"(d[2]), "+f"(d[3])
        : "r"(a0), "r"(a1), "r"(a2), "r"(a3), "r"(b0), "r"(b1));
}

__device__ __forceinline__ void mma_bf16(float d[4], uint32_t a0, uint32_t a1,
                                         uint32_t a2, uint32_t a3,
                                         uint32_t b0, uint32_t b1) {
    asm volatile(
        "mma.sync.aligned.m16n8k16.row.col.f32.bf16.bf16.f32 "
        "{%0,%1,%2,%3}, {%4,%5,%6,%7}, {%8,%9}, {%0,%1,%2,%3};"
        : "+f"(d[0]), "+f"(d[1]), "+f"(d[2]), "+f"(d[3])
        : "r"(a0), "r"(a1), "r"(a2), "r"(a3), "r"(b0), "r"(b1));
}

__device__ __forceinline__ void ldsm4(uint32_t r[4], uint32_t addr) {
    asm volatile("ldmatrix.sync.aligned.m8n8.x4.shared.b16 {%0,%1,%2,%3}, [%4];"
                 : "=r"(r[0]), "=r"(r[1]), "=r"(r[2]), "=r"(r[3]) : "r"(addr));
}

__device__ __forceinline__ uint32_t pack_bf2(float lo, float hi) {
    __nv_bfloat162 t = __floats2bfloat162_rn(lo, hi);
    return *(uint32_t*)&t;
}
__device__ __forceinline__ uint32_t pack_h2(float lo, float hi) {
    __half2 t = __floats2half2_rn(lo, hi);
    return *(uint32_t*)&t;
}
__device__ __forceinline__ uint16_t bf16bits(float x) {
    __nv_bfloat16 t = __float2bfloat16_rn(x);
    return *(uint16_t*)&t;
}
__device__ __forceinline__ void cp_async16(uint32_t saddr, const void* g) {
    asm volatile("cp.async.cg.shared.global [%0], [%1], 16;" :: "r"(saddr), "l"(g) : "memory");
}

// ---------------- Weight prep ----------------------------------------------------------
__global__ void wprep_kernel(const float* __restrict__ wq, const float* __restrict__ wk,
                             const float* __restrict__ wv, const float* __restrict__ wo,
                             const float* __restrict__ we1, const float* __restrict__ we2,
                             __half* __restrict__ wbf) {
    int z = blockIdx.z;
    const float* src;
    if (z == 0) src = wq;
    else if (z == 1) src = wk;
    else if (z == 2) src = wv;
    else if (z == 3) src = wo;
    else if (z < 8) src = we1 + (size_t)(z - 4) * DIM * IDIM;
    else src = we2 + (size_t)(z - 8) * IDIM * DIM;
    __half* dst = wbf + (size_t)z * DIM * DIM;
    __shared__ float tile[32][33];
    int k0 = blockIdx.y * 32, n0 = blockIdx.x * 32;
    int tx = threadIdx.x, ty = threadIdx.y;
#pragma unroll
    for (int r = ty; r < 32; r += 8)
        tile[r][tx] = src[(size_t)(k0 + r) * DIM + n0 + tx];
    __syncthreads();
#pragma unroll
    for (int r = ty; r < 32; r += 8)
        dst[(size_t)(n0 + r) * DIM + k0 + tx] = __float2half_rn(tile[tx][r]);
}

// ---------------- RoPE table -----------------------------------------------------------
__global__ void rope_table_kernel(float2* __restrict__ tab) {
    int idx = blockIdx.x * blockDim.x + threadIdx.x;
    if (idx >= SEQ * 64) return;
    int i = idx & 63;
    int s = idx >> 6;
    float invf = (float)(1.0 / pow(10000.0, (double)i / 64.0));
    float ang = (float)s * invf;
    double angd = (double)ang;
    tab[idx] = make_float2((float)cos(angd), (float)sin(angd));
}

// ---------------- RoPE apply -----------------------------------------------------------
__global__ void rope_kernel(float* __restrict__ q, float* __restrict__ k,
                            const float2* __restrict__ tab) {
    int idx = blockIdx.x * blockDim.x + threadIdx.x;
    if (idx >= NTOK * NH * 64) return;
    int i = idx & 63;
    int rem = idx >> 6;
    int h = rem % NH;
    int t = rem / NH;
    int s = t % SEQ;
    float2 cs = tab[s * 64 + i];
    float c = cs.x, sn = cs.y;
    size_t base = (size_t)t * DIM + (size_t)h * HDIM;
    float q1 = q[base + i], q2 = q[base + 64 + i];
    q[base + i]      = q1 * c - q2 * sn;
    q[base + 64 + i] = q2 * c + q1 * sn;
    float k1 = k[base + i], k2 = k[base + 64 + i];
    k[base + i]      = k1 * c - k2 * sn;
    k[base + 64 + i] = k2 * c + k1 * sn;
}

// ---------------- LayerNorm ------------------------------------------------------------
__global__ void ln_kernel(const float* __restrict__ x, const float* __restrict__ w,
                          const float* __restrict__ b, float* __restrict__ y,
                          __half* __restrict__ yh) {
    int row = blockIdx.x;
    const float* xr = x + (size_t)row * DIM;
    float* yr = y + (size_t)row * DIM;
    __half* yhr = yh + (size_t)row * DIM;
    __shared__ float red[256];
    int tid = threadIdx.x;
    float s = 0.f;
    for (int i = tid; i < DIM; i += 256) s += xr[i];
    red[tid] = s; __syncthreads();
    for (int o = 128; o > 0; o >>= 1) { if (tid < o) red[tid] += red[tid + o]; __syncthreads(); }
    float mu = red[0] * (1.f / DIM);
    __syncthreads();
    float v = 0.f;
    for (int i = tid; i < DIM; i += 256) { float d = xr[i] - mu; v += d * d; }
    red[tid] = v; __syncthreads();
    for (int o = 128; o > 0; o >>= 1) { if (tid < o) red[tid] += red[tid + o]; __syncthreads(); }
    float inv = rsqrtf(red[0] * (1.f / DIM) + 1e-5f);
    for (int i = tid; i < DIM; i += 256) {
        float val = (xr[i] - mu) * inv * w[i] + b[i];
        yr[i] = val;
        yhr[i] = __float2half_rn(val);
    }
}

// ---------------- FP16 GEMM: K-tile 64, 2-stage cp.async, ldmatrix fragments ------------
__device__ __forceinline__ void epi(float v, int gm, int gn,
                                    const float* bias, int act,
                                    const float* resid, int ldr,
                                    const float* rowscale, int rss,
                                    float* C, __half* Ch, int ldc, int accum) {
    if (bias) v += bias[gn];
    if (act) v = 0.5f * v * (1.f + erff(v * 0.70710678118654752f));
    if (resid) v += resid[(size_t)gm * ldr + gn];
    if (rowscale) v *= rowscale[(size_t)gm * rss];
    size_t o = (size_t)gm * ldc + gn;
    if (C) {
        if (accum == 2) atomicAdd(&C[o], v);
        else if (accum == 1) C[o] += v;
        else C[o] = v;
    }
    if (Ch) Ch[o] = __float2half_rn(v);
}

#define GF_ROWW  36                       // words per 64-half row (32 data + 4 pad)
#define GF_AW    (128 * GF_ROWW)          // A words per stage
#define GF_STB   (2 * GF_AW * 4)          // stage bytes (A+B) = 36864
#define GF_SMEM  (2 * GF_STB)             // 73728 B dynamic (2 stages)
#define GF_CSTEP (16 * GF_ROWW * 4)       // 16 rows in bytes = 2304

__global__ void __launch_bounds__(128)
gemm_f16(const __half* __restrict__ Abase, size_t strideAz, int lda,
         const __half* __restrict__ Bbase, size_t strideBz, int ldb,
         ZIO z0, ZIO z1, ZIO z2, ZIO z3,
         int ldc, int ldr, int rss,
         int M, int N, int K, int act, int accum) {
    extern __shared__ uint32_t smbuf[];
    int z = blockIdx.z;
    ZIO io = (z == 0) ? z0 : ((z == 1) ? z1 : ((z == 2) ? z2 : z3));
    const __half* A = Abase + (size_t)z * strideAz;
    const __half* Bt = Bbase + (size_t)z * strideBz;

    int M_eff = io.mcount ? *io.mcount : M;
    int row0 = blockIdx.y * 128, col0 = blockIdx.x * 128;
    if (row0 >= M_eff) return;

    int tid = threadIdx.x;
    int w = tid >> 5, lane = tid & 31;
    int wm = w >> 1, wn = w & 1;
    int m_w = wm * 64, n_w = wn * 64;
    int g = lane >> 2, q = lane & 3;
    (void)g; (void)q;

    float acc[4][8][4];
#pragma unroll
    for (int i = 0; i < 4; i++)
#pragma unroll
        for (int j = 0; j < 8; j++)
#pragma unroll
            for (int r = 0; r < 4; r++) acc[i][j][r] = 0.f;

    // staging: 8 x 16B cp.async each for A and B per thread per K64 tile
    int srow = tid >> 3, sch = tid & 7;                  // row 0..15, chunk 0..7
    uint32_t offS = (uint32_t)(srow * GF_ROWW + sch * 4) * 4;
    const __half* Apt[8];
#pragma unroll
    for (int c = 0; c < 8; c++) {
        int gm = row0 + srow + c * 16;
        int cl = gm < M_eff ? gm : M_eff - 1;
        int ar = io.amap ? io.amap[cl] : cl;
        Apt[c] = A + (size_t)ar * lda + sch * 8;
    }
    const __half* Bpt = Bt + (size_t)(col0 + srow) * ldb + sch * 8;
    uint32_t base0 = (uint32_t)__cvta_generic_to_shared(smbuf);

    // ldmatrix per-lane offsets (within stage)
    uint32_t offA = (uint32_t)((m_w + (lane & 15)) * GF_ROWW + ((lane >> 4) & 1) * 4) * 4;
    uint32_t offB = (uint32_t)((n_w + ((lane >> 4) & 1) * 8 + (lane & 7)) * GF_ROWW
                               + ((lane >> 3) & 1) * 4) * 4;

    int nk = K / 64;

#define GEMM_ISSUE(T_) do {                                            \
        int tt = (T_);                                                 \
        if (tt < nk) {                                                 \
            int st_ = tt & 1;                                          \
            int k0_ = tt * 64;                                         \
            uint32_t ab = base0 + st_ * GF_STB;                        \
            uint32_t bb = ab + GF_AW * 4;                              \
            _Pragma("unroll")                                          \
            for (int c = 0; c < 8; c++) {                              \
                cp_async16(ab + offS + c * GF_CSTEP, Apt[c] + k0_);    \
                cp_async16(bb + offS + c * GF_CSTEP,                   \
                           Bpt + (size_t)c * 16 * ldb + k0_);          \
            }                                                          \
        }                                                              \
        asm volatile("cp.async.commit_group;" ::: "memory");           \
    } while (0)

    GEMM_ISSUE(0);
    for (int t = 0; t < nk; t++) {
        asm volatile("cp.async.wait_group 0;" ::: "memory");  // tile t complete
        __syncthreads();   // visibility + all warps done with compute(t-1)
        GEMM_ISSUE(t + 1); // writes the other stage, last read in compute(t-1)
        uint32_t ab = base0 + (t & 1) * GF_STB;
        uint32_t bb = ab + GF_AW * 4;

#pragma unroll
        for (int ks = 0; ks < 4; ks++) {
            uint32_t Af[4][4], Bf[4][4];
#pragma unroll
            for (int i = 0; i < 4; i++)
                ldsm4(Af[i], ab + offA + i * GF_CSTEP + ks * 32);
#pragma unroll
            for (int p = 0; p < 4; p++)
                ldsm4(Bf[p], bb + offB + p * GF_CSTEP + ks * 32);
#pragma unroll
            for (int i = 0; i < 4; i++)
#pragma unroll
                for (int j = 0; j < 8; j++)
                    mma_f16(acc[i][j], Af[i][0], Af[i][1], Af[i][2], Af[i][3],
                            Bf[j >> 1][(j & 1) * 2], Bf[j >> 1][(j & 1) * 2 + 1]);
        }
    }
#undef GEMM_ISSUE

    int gg = lane >> 2, qq = lane & 3;
#pragma unroll
    for (int i = 0; i < 4; i++) {
        int gm = row0 + m_w + i * 16 + gg;
        if (gm < M_eff) {
            int cr = io.cmap ? io.cmap[gm] : gm;
#pragma unroll
            for (int j = 0; j < 8; j++) {
                int cb = col0 + n_w + j * 8 + qq * 2;
                epi(acc[i][j][0], cr, cb,     io.bias, act, io.resid, ldr, io.rowscale, rss, io.C, io.Ch, ldc, accum);
                epi(acc[i][j][1], cr, cb + 1, io.bias, act, io.resid, ldr, io.rowscale, rss, io.C, io.Ch, ldc, accum);
            }
        }
        int gm2 = gm + 8;
        if (gm2 < M_eff) {
            int cr2 = io.cmap ? io.cmap[gm2] : gm2;
#pragma unroll
            for (int j = 0; j < 8; j++) {
                int cb = col0 + n_w + j * 8 + qq * 2;
                epi(acc[i][j][2], cr2, cb,     io.bias, act, io.resid, ldr, io.rowscale, rss, io.C, io.Ch, ldc, accum);
                epi(acc[i][j][3], cr2, cb + 1, io.bias, act, io.resid, ldr, io.rowscale, rss, io.C, io.Ch, ldc, accum);
            }
        }
    }
}

// ---------------- Flash attention (R15, proven) ----------------------------------------
__global__ void __launch_bounds__(256)
fa_kernel(const float* __restrict__ q, const float* __restrict__ k,
          const float* __restrict__ v, __half* __restrict__ attnh) {
    __shared__ uint32_t Ks[32][68];
    __shared__ uint32_t Vt[128][20];
    __shared__ uint32_t Ps[8][16][20];

    int bh = blockIdx.y;
    int b = bh / NH, h = bh % NH;
    int q0 = ((int)gridDim.x - 1 - (int)blockIdx.x) * 128;   // heavy blocks first
    int tid = threadIdx.x, w = tid >> 5, lane = tid & 31;
    int g = lane >> 2, qd = lane & 3;
    const float alpha = 0.08838834764831845f;

    const float* qb = q + ((size_t)b * SEQ) * DIM + h * HDIM;
    const float* kb_ = k + ((size_t)b * SEQ) * DIM + h * HDIM;
    const float* vb = v + ((size_t)b * SEQ) * DIM + h * HDIM;

    uint32_t qf[8][4];
    {
        const float* qr0 = qb + (size_t)(q0 + w * 16 + g) * DIM;
        const float* qr1 = qr0 + 8 * DIM;
#pragma unroll
        for (int ks = 0; ks < 8; ks++) {
            int c0 = (ks * 8 + qd) * 2, c1 = (ks * 8 + qd + 4) * 2;
            float2 t00 = *(const float2*)(qr0 + c0);
            float2 t10 = *(const float2*)(qr1 + c0);
            float2 t01 = *(const float2*)(qr0 + c1);
            float2 t11 = *(const float2*)(qr1 + c1);
            qf[ks][0] = pack_bf2(t00.x * alpha, t00.y * alpha);
            qf[ks][1] = pack_bf2(t10.x * alpha, t10.y * alpha);
            qf[ks][2] = pack_bf2(t01.x * alpha, t01.y * alpha);
            qf[ks][3] = pack_bf2(t11.x * alpha, t11.y * alpha);
        }
    }

    float m0 = -1e30f, m1 = -1e30f, l0 = 0.f, l1 = 0.f;
    float out[16][4];
#pragma unroll
    for (int i = 0; i < 16; i++)
#pragma unroll
        for (int r = 0; r < 4; r++) out[i][r] = 0.f;

    int ktiles = q0 / 32 + 4;

    for (int kt = 0; kt < ktiles; kt++) {
        int k0 = kt * 32;
        __syncthreads();
        for (int i = tid; i < 32 * 32; i += 256) {
            int r = i >> 5, c4 = i & 31;
            float4 tk = *(const float4*)(kb_ + (size_t)(k0 + r) * DIM + c4 * 4);
            Ks[r][c4 * 2]     = pack_bf2(tk.x, tk.y);
            Ks[r][c4 * 2 + 1] = pack_bf2(tk.z, tk.w);
            float4 tv = *(const float4*)(vb + (size_t)(k0 + r) * DIM + c4 * 4);
            uint16_t* vt = (uint16_t*)Vt;
            vt[(c4 * 4 + 0) * 40 + r] = bf16bits(tv.x);
            vt[(c4 * 4 + 1) * 40 + r] = bf16bits(tv.y);
            vt[(c4 * 4 + 2) * 40 + r] = bf16bits(tv.z);
            vt[(c4 * 4 + 3) * 40 + r] = bf16bits(tv.w);
        }
        __syncthreads();

        float sc[4][4];
#pragma unroll
        for (int nt = 0; nt < 4; nt++)
#pragma unroll
            for (int r = 0; r < 4; r++) sc[nt][r] = 0.f;
#pragma unroll
        for (int ks = 0; ks < 8; ks++) {
            int kp = ks * 8;
#pragma unroll
            for (int nt = 0; nt < 4; nt++) {
                uint32_t b0 = Ks[nt * 8 + g][kp + qd];
                uint32_t b1 = Ks[nt * 8 + g][kp + qd + 4];
                mma_bf16(sc[nt], qf[ks][0], qf[ks][1], qf[ks][2], qf[ks][3], b0, b1);
            }
        }

        if (k0 + 31 > q0) {
            int rq0 = q0 + w * 16 + g;
            int rq1 = rq0 + 8;
#pragma unroll
            for (int nt = 0; nt < 4; nt++) {
                int kc = k0 + nt * 8 + qd * 2;
                if (kc     > rq0) sc[nt][0] = -1e30f;
                if (kc + 1 > rq0) sc[nt][1] = -1e30f;
                if (kc     > rq1) sc[nt][2] = -1e30f;
                if (kc + 1 > rq1) sc[nt][3] = -1e30f;
            }
        }

        float tm0 = -1e30f, tm1 = -1e30f;
#pragma unroll
        for (int nt = 0; nt < 4; nt++) {
            tm0 = fmaxf(tm0, fmaxf(sc[nt][0], sc[nt][1]));
            tm1 = fmaxf(tm1, fmaxf(sc[nt][2], sc[nt][3]));
        }
        tm0 = fmaxf(tm0, __shfl_xor_sync(0xffffffffu, tm0, 1));
        tm0 = fmaxf(tm0, __shfl_xor_sync(0xffffffffu, tm0, 2));
        tm1 = fmaxf(tm1, __shfl_xor_sync(0xffffffffu, tm1, 1));
        tm1 = fmaxf(tm1, __shfl_xor_sync(0xffffffffu, tm1, 2));

        float mn0 = fmaxf(m0, tm0), mn1 = fmaxf(m1, tm1);
        bool chg = (mn0 != m0) || (mn1 != m1);
        if (__any_sync(0xffffffffu, chg)) {
            float corr0 = __expf(m0 - mn0), corr1 = __expf(m1 - mn1);
            l0 *= corr0; l1 *= corr1;
#pragma unroll
            for (int nt = 0; nt < 16; nt++) {
                out[nt][0] *= corr0; out[nt][1] *= corr0;
                out[nt][2] *= corr1; out[nt][3] *= corr1;
            }
        }
        m0 = mn0; m1 = mn1;

        float s0 = 0.f, s1 = 0.f;
#pragma unroll
        for (int nt = 0; nt < 4; nt++) {
            float p0 = __expf(sc[nt][0] - m0);
            float p1 = __expf(sc[nt][1] - m0);
            float p2 = __expf(sc[nt][2] - m1);
            float p3 = __expf(sc[nt][3] - m1);
            s0 += p0 + p1; s1 += p2 + p3;
            Ps[w][g][nt * 4 + qd]     = pack_bf2(p0, p1);
            Ps[w][g + 8][nt * 4 + qd] = pack_bf2(p2, p3);
        }
        s0 += __shfl_xor_sync(0xffffffffu, s0, 1);
        s0 += __shfl_xor_sync(0xffffffffu, s0, 2);
        s1 += __shfl_xor_sync(0xffffffffu, s1, 1);
        s1 += __shfl_xor_sync(0xffffffffu, s1, 2);
        l0 += s0; l1 += s1;
        __syncwarp();

#pragma unroll
        for (int ks = 0; ks < 2; ks++) {
            int kp = ks * 8;
            uint32_t a0 = Ps[w][g][kp + qd];
            uint32_t a1 = Ps[w][g + 8][kp + qd];
            uint32_t a2 = Ps[w][g][kp + qd + 4];
            uint32_t a3 = Ps[w][g + 8][kp + qd + 4];
#pragma unroll
            for (int nt = 0; nt < 16; nt++) {
                uint32_t b0 = Vt[nt * 8 + g][kp + qd];
                uint32_t b1 = Vt[nt * 8 + g][kp + qd + 4];
                mma_bf16(out[nt], a0, a1, a2, a3, b0, b1);
            }
        }
        __syncwarp();
    }

    float inv0 = 1.f / l0, inv1 = 1.f / l1;
    int r0g = q0 + w * 16 + g;
    __half* ob = attnh + ((size_t)b * SEQ) * DIM + h * HDIM;
#pragma unroll
    for (int nt = 0; nt < 16; nt++) {
        int c = nt * 8 + qd * 2;
        *(uint32_t*)(ob + (size_t)r0g * DIM + c) =
            pack_h2(out[nt][0] * inv0, out[nt][1] * inv0);
        *(uint32_t*)(ob + (size_t)(r0g + 8) * DIM + c) =
            pack_h2(out[nt][2] * inv1, out[nt][3] * inv1);
    }
}

// ---------------- MoE gate -------------------------------------------------------------
__global__ void gate_kernel(const float* __restrict__ x, const float* __restrict__ wg,
                            float* __restrict__ comb) {
    int t = blockIdx.x;
    int tid = threadIdx.x;
    __shared__ float red[NE * 128];
    const float* xr = x + (size_t)t * DIM;
    float acc[NE] = {0.f, 0.f, 0.f, 0.f};
    for (int d = tid; d < DIM; d += 128) {
        float xv = xr[d];
#pragma unroll
        for (int e = 0; e < NE; e++) acc[e] += xv * wg[(size_t)d * NE + e];
    }
#pragma unroll
    for (int e = 0; e < NE; e++) red[e * 128 + tid] = acc[e];
    __syncthreads();
    for (int o = 64; o > 0; o >>= 1) {
        if (tid < o) {
#pragma unroll
            for (int e = 0; e < NE; e++) red[e * 128 + tid] += red[e * 128 + tid + o];
        }
        __syncthreads();
    }
    if (tid == 0) {
        float l[NE];
#pragma unroll
        for (int e = 0; e < NE; e++) l[e] = red[e * 128];
        float mx = fmaxf(fmaxf(l[0], l[1]), fmaxf(l[2], l[3]));
        float ex[NE], s = 0.f;
#pragma unroll
        for (int e = 0; e < NE; e++) { ex[e] = expf(l[e] - mx); s += ex[e]; }
        float p[NE];
#pragma unroll
        for (int e = 0; e < NE; e++) p[e] = ex[e] / s;
        int i0 = 0;
#pragma unroll
        for (int e = 1; e < NE; e++) if (p[e] > p[i0]) i0 = e;
        int i1 = (i0 == 0) ? 1 : 0;
#pragma unroll
        for (int e = 0; e < NE; e++) if (e != i0 && p[e] > p[i1]) i1 = e;
        float e1 = expf(p[i1] - p[i0]);
        float invs = 1.f / (1.f + e1);
        float c[NE] = {0.f, 0.f, 0.f, 0.f};
        c[i0] = invs;
        c[i1] = e1 * invs;
#pragma unroll
        for (int e = 0; e < NE; e++) comb[(size_t)t * NE + e] = c[e];
    }
}

// ---------------- Routing --------------------------------------------------------------
__global__ void zero_cnt_kernel(int* cnt) {
    if (threadIdx.x < NE) cnt[threadIdx.x] = 0;
}
__global__ void route_kernel(const float* __restrict__ comb, int* __restrict__ cnt,
                             int* __restrict__ idx) {
    int t = blockIdx.x * blockDim.x + threadIdx.x;
    if (t >= NTOK) return;
#pragma unroll
    for (int e = 0; e < NE; e++) {
        if (comb[(size_t)t * NE + e] > 0.f) {
            int pos = atomicAdd(&cnt[e], 1);
            idx[e * NTOK + pos] = t;
        }
    }
}

// ---------------- host orchestration ---------------------------------------------------
extern "C" void kernel_launch(void* const* d_in, const int* in_sizes, int n_in,
                              void* d_out, int out_size) {
    (void)in_sizes; (void)n_in; (void)out_size;
    const float* hs   = (const float*)d_in[0];
    const float* wq   = (const float*)d_in[1];
    const float* bq   = (const float*)d_in[2];
    const float* wk   = (const float*)d_in[3];
    const float* bk   = (const float*)d_in[4];
    const float* wv   = (const float*)d_in[5];
    const float* bv   = (const float*)d_in[6];
    const float* wo   = (const float*)d_in[7];
    const float* bo   = (const float*)d_in[8];
    const float* ln1w = (const float*)d_in[9];
    const float* ln1b = (const float*)d_in[10];
    const float* ln2w = (const float*)d_in[11];
    const float* ln2b = (const float*)d_in[12];
    const float* wg   = (const float*)d_in[13];
    const float* we1  = (const float*)d_in[14];
    const float* be1  = (const float*)d_in[15];
    const float* we2  = (const float*)d_in[16];
    const float* be2  = (const float*)d_in[17];
    float* out = (float*)d_out;

    float *p_ln, *p_q, *p_k, *p_v, *p_comb;
    __half *p_lnh, *p_attnh, *p_hmidh, *p_wbf;
    int *p_cnt, *p_idx;
    float2* p_rope;
    cudaGetSymbolAddress((void**)&p_ln, g_ln);
    cudaGetSymbolAddress((void**)&p_lnh, g_lnh);
    cudaGetSymbolAddress((void**)&p_q, g_q);
    cudaGetSymbolAddress((void**)&p_k, g_k);
    cudaGetSymbolAddress((void**)&p_v, g_v);
    cudaGetSymbolAddress((void**)&p_attnh, g_attnh);
    cudaGetSymbolAddress((void**)&p_hmidh, g_hmidh);
    cudaGetSymbolAddress((void**)&p_comb, g_comb);
    cudaGetSymbolAddress((void**)&p_cnt, g_cnt);
    cudaGetSymbolAddress((void**)&p_idx, g_idx);
    cudaGetSymbolAddress((void**)&p_wbf, g_wbf);
    cudaGetSymbolAddress((void**)&p_rope, g_rope);

    cudaFuncSetAttribute(gemm_f16, cudaFuncAttributeMaxDynamicSharedMemorySize, GF_SMEM);

    size_t WSZ = (size_t)DIM * DIM;
    ZIO zn = {nullptr, nullptr, nullptr, nullptr, nullptr, nullptr, nullptr, nullptr};

    // 0. Weight prep + RoPE table
    dim3 gW(DIM / 32, DIM / 32, 12);
    wprep_kernel<<<gW, dim3(32, 8)>>>(wq, wk, wv, wo, we1, we2, p_wbf);
    rope_table_kernel<<<(SEQ * 64) / 256, 256>>>(p_rope);

    // 1. LN1
    ln_kernel<<<NTOK, 256>>>(hs, ln1w, ln1b, p_ln, p_lnh);

    // 2. QKV: one batched launch (z = 0,1,2)
    {
        ZIO zq = zn; zq.bias = bq; zq.C = p_q;
        ZIO zk = zn; zk.bias = bk; zk.C = p_k;
        ZIO zv = zn; zv.bias = bv; zv.C = p_v;
        dim3 grid(DIM / 128, NTOK / 128, 3);
        gemm_f16<<<grid, 128, GF_SMEM>>>(p_lnh, 0, DIM, p_wbf, WSZ, DIM,
                                         zq, zk, zv, zn,
                                         DIM, 0, 0, NTOK, DIM, DIM, 0, 0);
    }

    // 3. RoPE
    int nrope = NTOK * NH * 64;
    rope_kernel<<<(nrope + 255) / 256, 256>>>(p_q, p_k, p_rope);

    // 4. Flash attention
    dim3 gFA(SEQ / 128, BATCH * NH);
    fa_kernel<<<gFA, 256>>>(p_q, p_k, p_v, p_attnh);

    // 5. O-proj + bias + residual -> out (= h)
    {
        ZIO zo = zn; zo.bias = bo; zo.C = out; zo.resid = hs;
        dim3 grid(DIM / 128, NTOK / 128, 1);
        gemm_f16<<<grid, 128, GF_SMEM>>>(p_attnh, 0, DIM, p_wbf + 3 * WSZ, 0, DIM,
                                         zo, zn, zn, zn,
                                         DIM, DIM, 0, NTOK, DIM, DIM, 0, 0);
    }

    // 6. LN2
    ln_kernel<<<NTOK, 256>>>(out, ln2w, ln2b, p_ln, p_lnh);

    // 7. Gate + routing
    gate_kernel<<<NTOK, 128>>>(p_ln, wg, p_comb);
    zero_cnt_kernel<<<1, 32>>>(p_cnt);
    route_kernel<<<NTOK / 256, 256>>>(p_comb, p_cnt, p_idx);

    // 8a. Expert GEMM1 (all 4 experts, one launch)
    {
        ZIO ze[4];
        for (int e = 0; e < NE; e++) {
            ze[e] = zn;
            ze[e].bias = be1 + (size_t)e * IDIM;
            ze[e].Ch = p_hmidh + (size_t)e * NTOK * IDIM;
            ze[e].amap = p_idx + e * NTOK;
            ze[e].mcount = p_cnt + e;
        }
        dim3 grid(IDIM / 128, NTOK / 128, NE);
        gemm_f16<<<grid, 128, GF_SMEM>>>(p_lnh, 0, DIM, p_wbf + 4 * WSZ, WSZ, DIM,
                                         ze[0], ze[1], ze[2], ze[3],
                                         IDIM, 0, 0, NTOK, IDIM, DIM, 1, 0);
    }

    // 8b. Expert GEMM2 (all 4 experts, one launch, atomic accumulate into out)
    {
        ZIO ze[4];
        for (int e = 0; e < NE; e++) {
            ze[e] = zn;
            ze[e].bias = be2 + (size_t)e * DIM;
            ze[e].C = out;
            ze[e].rowscale = p_comb + e;
            ze[e].cmap = p_idx + e * NTOK;
            ze[e].mcount = p_cnt + e;
        }
        dim3 grid(DIM / 128, NTOK / 128, NE);
        gemm_f16<<<grid, 128, GF_SMEM>>>(p_hmidh, (size_t)NTOK * IDIM, IDIM,
                                         p_wbf + 8 * WSZ, WSZ, IDIM,
                                         ze[0], ze[1], ze[2], ze[3],
                                         DIM, 0, NE, NTOK, DIM, IDIM, 0, 2);
    }
}